// round 1
// baseline (speedup 1.0000x reference)
#include <cuda_runtime.h>
#include <math.h>

#define N_NODES 30000
#define E_MAX   480000
#define ET_MAX  (E_MAX + N_NODES)
#define F_IN    1280
#define HEADS   4
#define CH      128
#define HC      512    // HEADS*CH
#define HID     64

// ---------------- scratch (device globals; no dynamic allocation) ----------------
__device__ float    g_h[(size_t)N_NODES * HC];      // GAT features h = x @ W_gat
__device__ float    g_out1[(size_t)N_NODES * HC];   // GAT output (pre-BN)
__device__ float    g_asrc[N_NODES * HEADS];
__device__ float    g_adst[N_NODES * HEADS];
__device__ unsigned g_max[N_NODES * HEADS];         // encoded float max per (dst, head)
__device__ float    g_sum[N_NODES * HEADS];         // softmax denominators
__device__ float    g_logit[(size_t)ET_MAX * HEADS];// logits, then exp values
__device__ float    g_h2[(size_t)N_NODES * HID];    // xr @ W_gcn
__device__ float    g_deg[N_NODES];
__device__ float    g_dinv[N_NODES];
__device__ float    g_colsum[HC];
__device__ float    g_colsum2[HC];
__device__ float    g_scale[HC];
__device__ float    g_shift[HC];

// monotonic float<->uint encoding for atomicMax on floats
__device__ __forceinline__ unsigned encf(float f) {
    unsigned u = __float_as_uint(f);
    return (u & 0x80000000u) ? ~u : (u | 0x80000000u);
}
__device__ __forceinline__ float decf(unsigned u) {
    u = (u & 0x80000000u) ? (u & 0x7FFFFFFFu) : ~u;
    return __uint_as_float(u);
}

// ---------------- init: biases into accumulators, zero reducers ----------------
__global__ void k_init(const float* __restrict__ b_gat,
                       const float* __restrict__ b_gcn,
                       float* __restrict__ out) {
    int i = blockIdx.x * blockDim.x + threadIdx.x;
    if (i < N_NODES * HC)    g_out1[i] = b_gat[i & (HC - 1)];
    if (i < N_NODES * HID)   out[i]    = b_gcn[i & (HID - 1)];
    if (i < N_NODES * HEADS) { g_max[i] = 0u; g_sum[i] = 0.0f; }
    if (i < N_NODES)         g_deg[i] = 0.0f;
    if (i < HC)              { g_colsum[i] = 0.0f; g_colsum2[i] = 0.0f; }
}

// ---------------- GEMM1: g_h = x[M,K] @ W_gat[K,N], M=30000 K=1280 N=512 ----------------
__global__ void k_gemm1(const float* __restrict__ A, const float* __restrict__ B) {
    __shared__ float As[8][128];
    __shared__ float Bs[8][128];
    const int K = F_IN, Nn = HC;
    int tid  = threadIdx.x;                    // 256 threads
    int row0 = blockIdx.y * 128;
    int col0 = blockIdx.x * 128;
    int arow = tid >> 1, acol = (tid & 1) * 4; // A tile 128x8
    int brow = tid >> 5, bcol = (tid & 31) * 4;// B tile 8x128
    int ty = tid >> 4, tx = tid & 15;          // 16x16 threads, 8x8 each

    float acc[8][8];
#pragma unroll
    for (int i = 0; i < 8; i++)
#pragma unroll
        for (int j = 0; j < 8; j++) acc[i][j] = 0.0f;

    for (int k0 = 0; k0 < K; k0 += 8) {
        float4 av = make_float4(0.f, 0.f, 0.f, 0.f);
        int ar = row0 + arow;
        if (ar < N_NODES)
            av = *(const float4*)(A + (size_t)ar * K + k0 + acol);
        As[acol + 0][arow] = av.x;
        As[acol + 1][arow] = av.y;
        As[acol + 2][arow] = av.z;
        As[acol + 3][arow] = av.w;
        float4 bv = *(const float4*)(B + (size_t)(k0 + brow) * Nn + col0 + bcol);
        *(float4*)&Bs[brow][bcol] = bv;
        __syncthreads();
#pragma unroll
        for (int kk = 0; kk < 8; kk++) {
            float a8[8], b8[8];
#pragma unroll
            for (int i = 0; i < 8; i++) a8[i] = As[kk][ty * 8 + i];
#pragma unroll
            for (int j = 0; j < 8; j++) b8[j] = Bs[kk][tx * 8 + j];
#pragma unroll
            for (int i = 0; i < 8; i++)
#pragma unroll
                for (int j = 0; j < 8; j++) acc[i][j] = fmaf(a8[i], b8[j], acc[i][j]);
        }
        __syncthreads();
    }
#pragma unroll
    for (int i = 0; i < 8; i++) {
        int r = row0 + ty * 8 + i;
        if (r >= N_NODES) continue;
#pragma unroll
        for (int j = 0; j < 8; j += 4) {
            float4 v = make_float4(acc[i][j], acc[i][j + 1], acc[i][j + 2], acc[i][j + 3]);
            *(float4*)&g_h[(size_t)r * HC + col0 + tx * 8 + j] = v;
        }
    }
}

// ---------------- attention dots: one warp per (node, head) ----------------
__global__ void k_att(const float* __restrict__ att_src, const float* __restrict__ att_dst) {
    int gw   = (blockIdx.x * blockDim.x + threadIdx.x) >> 5;
    int lane = threadIdx.x & 31;
    if (gw >= N_NODES * HEADS) return;
    int n = gw >> 2, hd = gw & 3;
    float4 hv = *(const float4*)&g_h[(size_t)n * HC + hd * CH + lane * 4];
    float4 sv = *(const float4*)&att_src[hd * CH + lane * 4];
    float4 dv = *(const float4*)&att_dst[hd * CH + lane * 4];
    float vs = hv.x * sv.x + hv.y * sv.y + hv.z * sv.z + hv.w * sv.w;
    float vd = hv.x * dv.x + hv.y * dv.y + hv.z * dv.z + hv.w * dv.w;
#pragma unroll
    for (int o = 16; o > 0; o >>= 1) {
        vs += __shfl_down_sync(0xFFFFFFFFu, vs, o);
        vd += __shfl_down_sync(0xFFFFFFFFu, vd, o);
    }
    if (lane == 0) { g_asrc[gw] = vs; g_adst[gw] = vd; }
}

// ---------------- edge pass 1: logits (leaky relu) + segment max + degree ----------------
__global__ void k_edge_logits(const int* __restrict__ ei, const float* __restrict__ ew, int E) {
    int e = blockIdx.x * blockDim.x + threadIdx.x;
    int ET = E + N_NODES;
    if (e >= ET) return;
    int s, d; float w;
    if (e < E) { s = ei[e]; d = ei[E + e]; w = ew[e]; }
    else       { s = d = e - E; w = 1.0f; }
    float4 as = *(const float4*)&g_asrc[s * 4];
    float4 ad = *(const float4*)&g_adst[d * 4];
    float l0 = as.x + ad.x, l1 = as.y + ad.y, l2 = as.z + ad.z, l3 = as.w + ad.w;
    l0 = l0 > 0.f ? l0 : 0.2f * l0;
    l1 = l1 > 0.f ? l1 : 0.2f * l1;
    l2 = l2 > 0.f ? l2 : 0.2f * l2;
    l3 = l3 > 0.f ? l3 : 0.2f * l3;
    *(float4*)&g_logit[(size_t)e * 4] = make_float4(l0, l1, l2, l3);
    atomicMax(&g_max[d * 4 + 0], encf(l0));
    atomicMax(&g_max[d * 4 + 1], encf(l1));
    atomicMax(&g_max[d * 4 + 2], encf(l2));
    atomicMax(&g_max[d * 4 + 3], encf(l3));
    atomicAdd(&g_deg[d], w);
}

// ---------------- edge pass 2: exp + segment sum ----------------
__global__ void k_edge_exp(const int* __restrict__ ei, int E) {
    int e = blockIdx.x * blockDim.x + threadIdx.x;
    int ET = E + N_NODES;
    if (e >= ET) return;
    int d = (e < E) ? ei[E + e] : (e - E);
    float4 l = *(const float4*)&g_logit[(size_t)e * 4];
    float e0 = __expf(l.x - decf(g_max[d * 4 + 0]));
    float e1 = __expf(l.y - decf(g_max[d * 4 + 1]));
    float e2 = __expf(l.z - decf(g_max[d * 4 + 2]));
    float e3 = __expf(l.w - decf(g_max[d * 4 + 3]));
    *(float4*)&g_logit[(size_t)e * 4] = make_float4(e0, e1, e2, e3);
    atomicAdd(&g_sum[d * 4 + 0], e0);
    atomicAdd(&g_sum[d * 4 + 1], e1);
    atomicAdd(&g_sum[d * 4 + 2], e2);
    atomicAdd(&g_sum[d * 4 + 3], e3);
}

// ---------------- message aggregation: warp per edge, 16 floats per lane ----------------
__global__ void k_aggregate(const int* __restrict__ ei, int E) {
    int gw   = (blockIdx.x * blockDim.x + threadIdx.x) >> 5;
    int lane = threadIdx.x & 31;
    int ET = E + N_NODES;
    if (gw >= ET) return;
    int s, d;
    if (gw < E) { s = ei[gw]; d = ei[E + gw]; }
    else        { s = d = gw - E; }
    int hd = lane >> 3;  // 128 channels per head, 16 per lane -> head = lane/8
    float alpha = g_logit[(size_t)gw * 4 + hd] / (g_sum[d * 4 + hd] + 1e-16f);
    const float* hp = &g_h[(size_t)s * HC + lane * 16];
    float*       op = &g_out1[(size_t)d * HC + lane * 16];
#pragma unroll
    for (int j = 0; j < 16; j += 4) {
        float4 v = *(const float4*)(hp + j);
        atomicAdd(op + j + 0, v.x * alpha);
        atomicAdd(op + j + 1, v.y * alpha);
        atomicAdd(op + j + 2, v.z * alpha);
        atomicAdd(op + j + 3, v.w * alpha);
    }
}

// ---------------- BN column stats (coalesced: thread owns a column) ----------------
__global__ void k_bnstats() {
    int col = threadIdx.x;    // 512 threads
    float s = 0.f, s2 = 0.f;
    for (int r = blockIdx.x; r < N_NODES; r += gridDim.x) {
        float v = g_out1[(size_t)r * HC + col];
        s += v; s2 += v * v;
    }
    atomicAdd(&g_colsum[col], s);
    atomicAdd(&g_colsum2[col], s2);
}

__global__ void k_bnfinal(const float* __restrict__ gamma, const float* __restrict__ beta) {
    int c = blockIdx.x * blockDim.x + threadIdx.x;
    if (c >= HC) return;
    float mean = g_colsum[c] * (1.0f / N_NODES);
    float var  = g_colsum2[c] * (1.0f / N_NODES) - mean * mean;
    float sc = gamma[c] * rsqrtf(var + 1e-5f);
    g_scale[c] = sc;
    g_shift[c] = beta[c] - mean * sc;
}

__global__ void k_dinv() {
    int i = blockIdx.x * blockDim.x + threadIdx.x;
    if (i >= N_NODES) return;
    float dv = g_deg[i];
    g_dinv[i] = dv > 0.f ? rsqrtf(dv) : 0.0f;
}

// ---------------- GEMM2: g_h2 = relu(bn(out1)) @ W_gcn, M=30000 K=512 N=64 ----------------
__global__ void k_gemm2(const float* __restrict__ W) {
    __shared__ float As[16][64];
    __shared__ float Bs[16][64];
    int tid  = threadIdx.x;            // 256
    int row0 = blockIdx.x * 64;
    int arow = tid >> 2, acol = (tid & 3) * 4;   // A tile 64x16
    int brow = tid >> 4, bcol = (tid & 15) * 4;  // B tile 16x64
    int ty = tid >> 4, tx = tid & 15;            // 16x16, 4x4 each

    float acc[4][4];
#pragma unroll
    for (int i = 0; i < 4; i++)
#pragma unroll
        for (int j = 0; j < 4; j++) acc[i][j] = 0.0f;

    for (int k0 = 0; k0 < HC; k0 += 16) {
        float4 av = make_float4(0.f, 0.f, 0.f, 0.f);
        int ar = row0 + arow;
        if (ar < N_NODES)
            av = *(const float4*)&g_out1[(size_t)ar * HC + k0 + acol];
        int kc = k0 + acol;
        av.x = fmaxf(fmaf(av.x, g_scale[kc + 0], g_shift[kc + 0]), 0.0f);
        av.y = fmaxf(fmaf(av.y, g_scale[kc + 1], g_shift[kc + 1]), 0.0f);
        av.z = fmaxf(fmaf(av.z, g_scale[kc + 2], g_shift[kc + 2]), 0.0f);
        av.w = fmaxf(fmaf(av.w, g_scale[kc + 3], g_shift[kc + 3]), 0.0f);
        As[acol + 0][arow] = av.x;
        As[acol + 1][arow] = av.y;
        As[acol + 2][arow] = av.z;
        As[acol + 3][arow] = av.w;
        float4 bv = *(const float4*)&W[(size_t)(k0 + brow) * HID + bcol];
        *(float4*)&Bs[brow][bcol] = bv;
        __syncthreads();
#pragma unroll
        for (int kk = 0; kk < 16; kk++) {
            float a4[4], b4[4];
#pragma unroll
            for (int i = 0; i < 4; i++) a4[i] = As[kk][ty * 4 + i];
#pragma unroll
            for (int j = 0; j < 4; j++) b4[j] = Bs[kk][tx * 4 + j];
#pragma unroll
            for (int i = 0; i < 4; i++)
#pragma unroll
                for (int j = 0; j < 4; j++) acc[i][j] = fmaf(a4[i], b4[j], acc[i][j]);
        }
        __syncthreads();
    }
#pragma unroll
    for (int i = 0; i < 4; i++) {
        int r = row0 + ty * 4 + i;
        if (r >= N_NODES) continue;
        float4 v = make_float4(acc[i][0], acc[i][1], acc[i][2], acc[i][3]);
        *(float4*)&g_h2[(size_t)r * HID + tx * 4] = v;
    }
}

// ---------------- GCN scatter: 16 threads per edge, 4 floats each ----------------
__global__ void k_gcn(const int* __restrict__ ei, const float* __restrict__ ew,
                      float* __restrict__ out, int E) {
    int idx  = blockIdx.x * blockDim.x + threadIdx.x;
    int e    = idx >> 4;
    int lane = idx & 15;
    int ET = E + N_NODES;
    if (e >= ET) return;
    int s, d; float w;
    if (e < E) { s = ei[e]; d = ei[E + e]; w = ew[e]; }
    else       { s = d = e - E; w = 1.0f; }
    float norm = g_dinv[s] * w * g_dinv[d];
    float4 v = *(const float4*)&g_h2[(size_t)s * HID + lane * 4];
    float* op = &out[(size_t)d * HID + lane * 4];
    atomicAdd(op + 0, v.x * norm);
    atomicAdd(op + 1, v.y * norm);
    atomicAdd(op + 2, v.z * norm);
    atomicAdd(op + 3, v.w * norm);
}

// ---------------- launch ----------------
extern "C" void kernel_launch(void* const* d_in, const int* in_sizes, int n_in,
                              void* d_out, int out_size) {
    const float* x       = (const float*)d_in[0];
    const int*   ei      = (const int*)  d_in[1];
    const float* ew      = (const float*)d_in[2];
    const float* W_gat   = (const float*)d_in[3];
    const float* att_src = (const float*)d_in[4];
    const float* att_dst = (const float*)d_in[5];
    const float* b_gat   = (const float*)d_in[6];
    const float* gamma   = (const float*)d_in[7];
    const float* beta    = (const float*)d_in[8];
    const float* W_gcn   = (const float*)d_in[9];
    const float* b_gcn   = (const float*)d_in[10];
    float* out = (float*)d_out;

    int E  = in_sizes[1] / 2;
    int ET = E + N_NODES;

    k_init<<<(N_NODES * HC + 255) / 256, 256>>>(b_gat, b_gcn, out);

    dim3 g1(HC / 128, (N_NODES + 127) / 128);
    k_gemm1<<<g1, 256>>>(x, W_gat);

    k_att<<<(N_NODES * HEADS * 32 + 255) / 256, 256>>>(att_src, att_dst);

    k_edge_logits<<<(ET + 255) / 256, 256>>>(ei, ew, E);
    k_edge_exp<<<(ET + 255) / 256, 256>>>(ei, E);
    k_aggregate<<<((size_t)ET * 32 + 255) / 256, 256>>>(ei, E);

    k_bnstats<<<240, 512>>>();
    k_bnfinal<<<2, 256>>>(gamma, beta);
    k_dinv<<<(N_NODES + 255) / 256, 256>>>();

    k_gemm2<<<(N_NODES + 63) / 64, 256>>>(W_gcn);
    k_gcn<<<((size_t)ET * 16 + 255) / 256, 256>>>(ei, ew, out, E);
}

// round 2
// speedup vs baseline: 3.2801x; 3.2801x over previous
#include <cuda_runtime.h>
#include <cuda_bf16.h>
#include <math.h>

#define N_NODES 30000
#define E_MAX   480000
#define ET_MAX  (E_MAX + N_NODES)
#define F_IN    1280
#define HEADS   4
#define CH      128
#define HC      512    // HEADS*CH
#define HID     64

// ---------------- scratch (device globals) ----------------
__device__ float g_h[(size_t)N_NODES * HC];      // GAT features h = x @ W_gat
__device__ float g_out1[(size_t)N_NODES * HC];   // GAT output (pre-BN)
__device__ float g_asrc[N_NODES * HEADS];
__device__ float g_adst[N_NODES * HEADS];
__device__ float g_alpha[(size_t)ET_MAX * HEADS];// per-edge attention (CSR order)
__device__ float g_h2[(size_t)N_NODES * HID];    // relu(bn(out1)) @ W_gcn
__device__ float g_dinv[N_NODES];
__device__ float g_colsum[HC];
__device__ float g_colsum2[HC];
__device__ float g_scale[HC];
__device__ float g_shift[HC];
// CSR
__device__ int   g_cnt[N_NODES];
__device__ int   g_off[N_NODES + 1];
__device__ int   g_esrc[ET_MAX];   // src node per CSR slot
__device__ float g_ewc[ET_MAX];    // edge weight per CSR slot

// ---------------- init ----------------
__global__ void k_init() {
    int i = blockIdx.x * blockDim.x + threadIdx.x;
    if (i < N_NODES) g_cnt[i] = 0;
    if (i < HC) { g_colsum[i] = 0.0f; g_colsum2[i] = 0.0f; }
}

// ================= GEMM1: g_h = x @ W_gat via bf16-split mma =================
// M=30000, K=1280, N=512. Block tile 128x128, BK=32, 8 warps (4x2), warp 32x64.
#define BM 128
#define BN 128
#define BK 32
#define SA 40   // padded smem row stride (bf16 elems)

__device__ __forceinline__ void mma16816(float* c, const unsigned* a, unsigned b0, unsigned b1) {
    asm volatile(
        "mma.sync.aligned.m16n8k16.row.col.f32.bf16.bf16.f32 "
        "{%0,%1,%2,%3}, {%4,%5,%6,%7}, {%8,%9}, {%0,%1,%2,%3};\n"
        : "+f"(c[0]), "+f"(c[1]), "+f"(c[2]), "+f"(c[3])
        : "r"(a[0]), "r"(a[1]), "r"(a[2]), "r"(a[3]), "r"(b0), "r"(b1));
}

__device__ __forceinline__ unsigned pack2(float x, float y, bool lo) {
    __nv_bfloat16 xh = __float2bfloat16(x);
    __nv_bfloat16 yh = __float2bfloat16(y);
    if (lo) {
        xh = __float2bfloat16(x - __bfloat162float(xh));
        yh = __float2bfloat16(y - __bfloat162float(yh));
    }
    unsigned u = ((unsigned)__bfloat16_as_ushort(yh) << 16) | (unsigned)__bfloat16_as_ushort(xh);
    return u;
}

__global__ void __launch_bounds__(256)
k_gemm1(const float* __restrict__ A, const float* __restrict__ B) {
    __shared__ __align__(16) __nv_bfloat16 Ah[BM * SA];
    __shared__ __align__(16) __nv_bfloat16 Al[BM * SA];
    __shared__ __align__(16) __nv_bfloat16 Bh[BN * SA];
    __shared__ __align__(16) __nv_bfloat16 Bl[BN * SA];

    int tid  = threadIdx.x;
    int warp = tid >> 5, lane = tid & 31;
    int row0 = blockIdx.y * BM, col0 = blockIdx.x * BN;
    int wm = (warp >> 1) * 32, wn = (warp & 1) * 64;
    int g = lane >> 2, tig = lane & 3;

    float acc[2][8][4];
#pragma unroll
    for (int t = 0; t < 2; t++)
#pragma unroll
        for (int n = 0; n < 8; n++)
#pragma unroll
            for (int j = 0; j < 4; j++) acc[t][n][j] = 0.0f;

    // A load map: thread loads 4 rows (q*32 + tid/8), cols (tid&7)*4..+3
    int a_rb = tid >> 3, a_c = (tid & 7) * 4;
    // B load map: thread loads 4 k-rows ((tid>>5)*4 + j), cols (tid&31)*4..+3
    int b_kb = (tid >> 5) * 4, b_n = (tid & 31) * 4;

    for (int k0 = 0; k0 < F_IN; k0 += BK) {
        // ---- load + split A tile (128x32) ----
#pragma unroll
        for (int q = 0; q < 4; q++) {
            int r = a_rb + q * 32;
            int gr = row0 + r;
            float4 v = make_float4(0.f, 0.f, 0.f, 0.f);
            if (gr < N_NODES) v = *(const float4*)(A + (size_t)gr * F_IN + k0 + a_c);
            unsigned* ph = (unsigned*)&Ah[r * SA + a_c];
            unsigned* pl = (unsigned*)&Al[r * SA + a_c];
            ph[0] = pack2(v.x, v.y, false); ph[1] = pack2(v.z, v.w, false);
            pl[0] = pack2(v.x, v.y, true);  pl[1] = pack2(v.z, v.w, true);
        }
        // ---- load + split B tile (32k x 128n), store transposed [n][k] ----
#pragma unroll
        for (int j = 0; j < 4; j++) {
            int kb = b_kb + j;
            float4 v = *(const float4*)(B + (size_t)(k0 + kb) * HC + col0 + b_n);
            // store 4 n-rows, single bf16 each (can't pack across n)
            Bh[(b_n + 0) * SA + kb] = __float2bfloat16(v.x);
            Bh[(b_n + 1) * SA + kb] = __float2bfloat16(v.y);
            Bh[(b_n + 2) * SA + kb] = __float2bfloat16(v.z);
            Bh[(b_n + 3) * SA + kb] = __float2bfloat16(v.w);
            Bl[(b_n + 0) * SA + kb] = __float2bfloat16(v.x - __bfloat162float(__float2bfloat16(v.x)));
            Bl[(b_n + 1) * SA + kb] = __float2bfloat16(v.y - __bfloat162float(__float2bfloat16(v.y)));
            Bl[(b_n + 2) * SA + kb] = __float2bfloat16(v.z - __bfloat162float(__float2bfloat16(v.z)));
            Bl[(b_n + 3) * SA + kb] = __float2bfloat16(v.w - __bfloat162float(__float2bfloat16(v.w)));
        }
        __syncthreads();

        // ---- 3 passes: Ah*Bh, Ah*Bl, Al*Bh ----
#pragma unroll
        for (int pass = 0; pass < 3; pass++) {
            const __nv_bfloat16* Asrc = (pass == 2) ? Al : Ah;
            const __nv_bfloat16* Bsrc = (pass == 1) ? Bl : Bh;
#pragma unroll
            for (int kk = 0; kk < BK; kk += 16) {
                unsigned afr[2][4];
#pragma unroll
                for (int t = 0; t < 2; t++) {
                    const __nv_bfloat16* base = Asrc + (wm + t * 16 + g) * SA + kk + tig * 2;
                    afr[t][0] = *(const unsigned*)(base);
                    afr[t][1] = *(const unsigned*)(base + 8 * SA);
                    afr[t][2] = *(const unsigned*)(base + 8);
                    afr[t][3] = *(const unsigned*)(base + 8 * SA + 8);
                }
#pragma unroll
                for (int n = 0; n < 8; n++) {
                    const __nv_bfloat16* bb = Bsrc + (wn + n * 8 + g) * SA + kk + tig * 2;
                    unsigned b0 = *(const unsigned*)(bb);
                    unsigned b1 = *(const unsigned*)(bb + 8);
                    mma16816(acc[0][n], afr[0], b0, b1);
                    mma16816(acc[1][n], afr[1], b0, b1);
                }
            }
        }
        __syncthreads();
    }

    // ---- epilogue ----
#pragma unroll
    for (int t = 0; t < 2; t++) {
        int r0 = row0 + wm + t * 16 + g;
#pragma unroll
        for (int n = 0; n < 8; n++) {
            int cc = col0 + wn + n * 8 + tig * 2;
            if (r0 < N_NODES)
                *(float2*)&g_h[(size_t)r0 * HC + cc] = make_float2(acc[t][n][0], acc[t][n][1]);
            if (r0 + 8 < N_NODES)
                *(float2*)&g_h[(size_t)(r0 + 8) * HC + cc] = make_float2(acc[t][n][2], acc[t][n][3]);
        }
    }
}

// ---------------- attention dots: one warp per (node, head) ----------------
__global__ void k_att(const float* __restrict__ att_src, const float* __restrict__ att_dst) {
    int gw   = (blockIdx.x * blockDim.x + threadIdx.x) >> 5;
    int lane = threadIdx.x & 31;
    if (gw >= N_NODES * HEADS) return;
    int n = gw >> 2, hd = gw & 3;
    float4 hv = *(const float4*)&g_h[(size_t)n * HC + hd * CH + lane * 4];
    float4 sv = *(const float4*)&att_src[hd * CH + lane * 4];
    float4 dv = *(const float4*)&att_dst[hd * CH + lane * 4];
    float vs = hv.x * sv.x + hv.y * sv.y + hv.z * sv.z + hv.w * sv.w;
    float vd = hv.x * dv.x + hv.y * dv.y + hv.z * dv.z + hv.w * dv.w;
#pragma unroll
    for (int o = 16; o > 0; o >>= 1) {
        vs += __shfl_down_sync(0xFFFFFFFFu, vs, o);
        vd += __shfl_down_sync(0xFFFFFFFFu, vd, o);
    }
    if (lane == 0) { g_asrc[gw] = vs; g_adst[gw] = vd; }
}

// ---------------- CSR build ----------------
__global__ void k_count(const int* __restrict__ ei, int E) {
    int e = blockIdx.x * blockDim.x + threadIdx.x;
    int ET = E + N_NODES;
    if (e >= ET) return;
    int d = (e < E) ? ei[E + e] : (e - E);
    atomicAdd(&g_cnt[d], 1);
}

__global__ void k_scan() {   // single block, 1024 threads
    __shared__ int sh[1024];
    int t = threadIdx.x;
    const int CHUNK = (N_NODES + 1023) / 1024;
    int lo = t * CHUNK, hi = min(lo + CHUNK, N_NODES);
    int s = 0;
    for (int i = lo; i < hi; i++) s += g_cnt[i];
    sh[t] = s;
    __syncthreads();
    for (int o = 1; o < 1024; o <<= 1) {
        int v = (t >= o) ? sh[t - o] : 0;
        __syncthreads();
        sh[t] += v;
        __syncthreads();
    }
    int run = sh[t] - s;   // exclusive prefix
    for (int i = lo; i < hi; i++) {
        int c = g_cnt[i];
        g_off[i] = run;
        run += c;
        g_cnt[i] = 0;      // reset as cursor for fill
    }
    if (t == 1023) g_off[N_NODES] = run;
}

__global__ void k_fill(const int* __restrict__ ei, const float* __restrict__ ew, int E) {
    int e = blockIdx.x * blockDim.x + threadIdx.x;
    int ET = E + N_NODES;
    if (e >= ET) return;
    int s, d; float w;
    if (e < E) { s = ei[e]; d = ei[E + e]; w = ew[e]; }
    else       { s = d = e - E; w = 1.0f; }
    int slot = g_off[d] + atomicAdd(&g_cnt[d], 1);
    g_esrc[slot] = s;
    g_ewc[slot]  = w;
}

// ---------------- fused segment softmax + weighted degree: warp per dst ----------------
__global__ void k_softmax() {
    int d    = (blockIdx.x * blockDim.x + threadIdx.x) >> 5;
    int lane = threadIdx.x & 31;
    if (d >= N_NODES) return;
    int beg = g_off[d], end = g_off[d + 1];
    int cnt = end - beg;
    float4 ad = *(const float4*)&g_adst[d * 4];

    float mx0 = -1e30f, mx1 = -1e30f, mx2 = -1e30f, mx3 = -1e30f;
    float degw = 0.0f;

    if (cnt <= 32) {
        int i = beg + lane;
        bool act = lane < cnt;
        float l0 = -1e30f, l1 = -1e30f, l2 = -1e30f, l3 = -1e30f;
        if (act) {
            int s = g_esrc[i];
            float4 as = *(const float4*)&g_asrc[s * 4];
            l0 = as.x + ad.x; l1 = as.y + ad.y; l2 = as.z + ad.z; l3 = as.w + ad.w;
            l0 = l0 > 0.f ? l0 : 0.2f * l0;
            l1 = l1 > 0.f ? l1 : 0.2f * l1;
            l2 = l2 > 0.f ? l2 : 0.2f * l2;
            l3 = l3 > 0.f ? l3 : 0.2f * l3;
            degw = g_ewc[i];
        }
        mx0 = l0; mx1 = l1; mx2 = l2; mx3 = l3;
#pragma unroll
        for (int o = 16; o > 0; o >>= 1) {
            mx0 = fmaxf(mx0, __shfl_xor_sync(0xFFFFFFFFu, mx0, o));
            mx1 = fmaxf(mx1, __shfl_xor_sync(0xFFFFFFFFu, mx1, o));
            mx2 = fmaxf(mx2, __shfl_xor_sync(0xFFFFFFFFu, mx2, o));
            mx3 = fmaxf(mx3, __shfl_xor_sync(0xFFFFFFFFu, mx3, o));
            degw += __shfl_xor_sync(0xFFFFFFFFu, degw, o);
        }
        float e0 = act ? __expf(l0 - mx0) : 0.f;
        float e1 = act ? __expf(l1 - mx1) : 0.f;
        float e2 = act ? __expf(l2 - mx2) : 0.f;
        float e3 = act ? __expf(l3 - mx3) : 0.f;
        float s0 = e0, s1 = e1, s2 = e2, s3 = e3;
#pragma unroll
        for (int o = 16; o > 0; o >>= 1) {
            s0 += __shfl_xor_sync(0xFFFFFFFFu, s0, o);
            s1 += __shfl_xor_sync(0xFFFFFFFFu, s1, o);
            s2 += __shfl_xor_sync(0xFFFFFFFFu, s2, o);
            s3 += __shfl_xor_sync(0xFFFFFFFFu, s3, o);
        }
        if (act) {
            float4 al = make_float4(e0 / (s0 + 1e-16f), e1 / (s1 + 1e-16f),
                                    e2 / (s2 + 1e-16f), e3 / (s3 + 1e-16f));
            *(float4*)&g_alpha[(size_t)i * 4] = al;
        }
    } else {
        // general path: 3 passes through g_alpha
        for (int i = beg + lane; i < end; i += 32) {
            int s = g_esrc[i];
            float4 as = *(const float4*)&g_asrc[s * 4];
            float l0 = as.x + ad.x, l1 = as.y + ad.y, l2 = as.z + ad.z, l3 = as.w + ad.w;
            l0 = l0 > 0.f ? l0 : 0.2f * l0;
            l1 = l1 > 0.f ? l1 : 0.2f * l1;
            l2 = l2 > 0.f ? l2 : 0.2f * l2;
            l3 = l3 > 0.f ? l3 : 0.2f * l3;
            *(float4*)&g_alpha[(size_t)i * 4] = make_float4(l0, l1, l2, l3);
            mx0 = fmaxf(mx0, l0); mx1 = fmaxf(mx1, l1);
            mx2 = fmaxf(mx2, l2); mx3 = fmaxf(mx3, l3);
            degw += g_ewc[i];
        }
#pragma unroll
        for (int o = 16; o > 0; o >>= 1) {
            mx0 = fmaxf(mx0, __shfl_xor_sync(0xFFFFFFFFu, mx0, o));
            mx1 = fmaxf(mx1, __shfl_xor_sync(0xFFFFFFFFu, mx1, o));
            mx2 = fmaxf(mx2, __shfl_xor_sync(0xFFFFFFFFu, mx2, o));
            mx3 = fmaxf(mx3, __shfl_xor_sync(0xFFFFFFFFu, mx3, o));
            degw += __shfl_xor_sync(0xFFFFFFFFu, degw, o);
        }
        float s0 = 0.f, s1 = 0.f, s2 = 0.f, s3 = 0.f;
        for (int i = beg + lane; i < end; i += 32) {
            float4 l = *(const float4*)&g_alpha[(size_t)i * 4];
            float e0 = __expf(l.x - mx0), e1 = __expf(l.y - mx1);
            float e2 = __expf(l.z - mx2), e3 = __expf(l.w - mx3);
            *(float4*)&g_alpha[(size_t)i * 4] = make_float4(e0, e1, e2, e3);
            s0 += e0; s1 += e1; s2 += e2; s3 += e3;
        }
#pragma unroll
        for (int o = 16; o > 0; o >>= 1) {
            s0 += __shfl_xor_sync(0xFFFFFFFFu, s0, o);
            s1 += __shfl_xor_sync(0xFFFFFFFFu, s1, o);
            s2 += __shfl_xor_sync(0xFFFFFFFFu, s2, o);
            s3 += __shfl_xor_sync(0xFFFFFFFFu, s3, o);
        }
        float r0 = 1.f / (s0 + 1e-16f), r1 = 1.f / (s1 + 1e-16f);
        float r2 = 1.f / (s2 + 1e-16f), r3 = 1.f / (s3 + 1e-16f);
        for (int i = beg + lane; i < end; i += 32) {
            float4 l = *(const float4*)&g_alpha[(size_t)i * 4];
            *(float4*)&g_alpha[(size_t)i * 4] = make_float4(l.x * r0, l.y * r1, l.z * r2, l.w * r3);
        }
    }
    if (lane == 0) g_dinv[d] = degw > 0.f ? rsqrtf(degw) : 0.0f;
}

// ---------------- GAT aggregation: block (128 thr) per dst, register acc ----------------
__global__ void __launch_bounds__(128)
k_aggregate(const float* __restrict__ b_gat) {
    int d = blockIdx.x;
    int tid = threadIdx.x;
    int head = tid >> 5;
    int c = tid * 4;
    float4 acc = *(const float4*)&b_gat[c];
    int beg = g_off[d], end = g_off[d + 1];
    for (int i = beg; i < end; i++) {
        int s = g_esrc[i];                         // broadcast
        float a = g_alpha[(size_t)i * 4 + head];   // broadcast per head-group
        float4 v = *(const float4*)&g_h[(size_t)s * HC + c];
        acc.x = fmaf(v.x, a, acc.x);
        acc.y = fmaf(v.y, a, acc.y);
        acc.z = fmaf(v.z, a, acc.z);
        acc.w = fmaf(v.w, a, acc.w);
    }
    *(float4*)&g_out1[(size_t)d * HC + c] = acc;
}

// ---------------- BN column stats ----------------
__global__ void k_bnstats() {
    int col = threadIdx.x;    // 512 threads
    float s = 0.f, s2 = 0.f;
    for (int r = blockIdx.x; r < N_NODES; r += gridDim.x) {
        float v = g_out1[(size_t)r * HC + col];
        s += v; s2 += v * v;
    }
    atomicAdd(&g_colsum[col], s);
    atomicAdd(&g_colsum2[col], s2);
}

__global__ void k_bnfinal(const float* __restrict__ gamma, const float* __restrict__ beta) {
    int c = blockIdx.x * blockDim.x + threadIdx.x;
    if (c >= HC) return;
    float mean = g_colsum[c] * (1.0f / N_NODES);
    float var  = g_colsum2[c] * (1.0f / N_NODES) - mean * mean;
    float sc = gamma[c] * rsqrtf(var + 1e-5f);
    g_scale[c] = sc;
    g_shift[c] = beta[c] - mean * sc;
}

// ---------------- GEMM2: g_h2 = relu(bn(out1)) @ W_gcn ----------------
__global__ void k_gemm2(const float* __restrict__ W) {
    __shared__ float As[16][64];
    __shared__ float Bs[16][64];
    int tid  = threadIdx.x;            // 256
    int row0 = blockIdx.x * 64;
    int arow = tid >> 2, acol = (tid & 3) * 4;
    int brow = tid >> 4, bcol = (tid & 15) * 4;
    int ty = tid >> 4, tx = tid & 15;

    float acc[4][4];
#pragma unroll
    for (int i = 0; i < 4; i++)
#pragma unroll
        for (int j = 0; j < 4; j++) acc[i][j] = 0.0f;

    for (int k0 = 0; k0 < HC; k0 += 16) {
        float4 av = make_float4(0.f, 0.f, 0.f, 0.f);
        int ar = row0 + arow;
        if (ar < N_NODES)
            av = *(const float4*)&g_out1[(size_t)ar * HC + k0 + acol];
        int kc = k0 + acol;
        av.x = fmaxf(fmaf(av.x, g_scale[kc + 0], g_shift[kc + 0]), 0.0f);
        av.y = fmaxf(fmaf(av.y, g_scale[kc + 1], g_shift[kc + 1]), 0.0f);
        av.z = fmaxf(fmaf(av.z, g_scale[kc + 2], g_shift[kc + 2]), 0.0f);
        av.w = fmaxf(fmaf(av.w, g_scale[kc + 3], g_shift[kc + 3]), 0.0f);
        As[acol + 0][arow] = av.x;
        As[acol + 1][arow] = av.y;
        As[acol + 2][arow] = av.z;
        As[acol + 3][arow] = av.w;
        float4 bv = *(const float4*)&W[(size_t)(k0 + brow) * HID + bcol];
        *(float4*)&Bs[brow][bcol] = bv;
        __syncthreads();
#pragma unroll
        for (int kk = 0; kk < 16; kk++) {
            float a4[4], b4[4];
#pragma unroll
            for (int i = 0; i < 4; i++) a4[i] = As[kk][ty * 4 + i];
#pragma unroll
            for (int j = 0; j < 4; j++) b4[j] = Bs[kk][tx * 4 + j];
#pragma unroll
            for (int i = 0; i < 4; i++)
#pragma unroll
                for (int j = 0; j < 4; j++) acc[i][j] = fmaf(a4[i], b4[j], acc[i][j]);
        }
        __syncthreads();
    }
#pragma unroll
    for (int i = 0; i < 4; i++) {
        int r = row0 + ty * 4 + i;
        if (r >= N_NODES) continue;
        float4 v = make_float4(acc[i][0], acc[i][1], acc[i][2], acc[i][3]);
        *(float4*)&g_h2[(size_t)r * HID + tx * 4] = v;
    }
}

// ---------------- GCN gather: warp per dst, 2 floats per lane ----------------
__global__ void k_gcn(const float* __restrict__ b_gcn, float* __restrict__ out) {
    int d    = (blockIdx.x * blockDim.x + threadIdx.x) >> 5;
    int lane = threadIdx.x & 31;
    if (d >= N_NODES) return;
    float dinv_d = g_dinv[d];
    float2 acc = *(const float2*)&b_gcn[lane * 2];
    int beg = g_off[d], end = g_off[d + 1];
    for (int i = beg; i < end; i++) {
        int s = g_esrc[i];
        float norm = g_dinv[s] * g_ewc[i] * dinv_d;
        float2 v = *(const float2*)&g_h2[(size_t)s * HID + lane * 2];
        acc.x = fmaf(v.x, norm, acc.x);
        acc.y = fmaf(v.y, norm, acc.y);
    }
    *(float2*)&out[(size_t)d * HID + lane * 2] = acc;
}

// ---------------- launch ----------------
extern "C" void kernel_launch(void* const* d_in, const int* in_sizes, int n_in,
                              void* d_out, int out_size) {
    const float* x       = (const float*)d_in[0];
    const int*   ei      = (const int*)  d_in[1];
    const float* ew      = (const float*)d_in[2];
    const float* W_gat   = (const float*)d_in[3];
    const float* att_src = (const float*)d_in[4];
    const float* att_dst = (const float*)d_in[5];
    const float* b_gat   = (const float*)d_in[6];
    const float* gamma   = (const float*)d_in[7];
    const float* beta    = (const float*)d_in[8];
    const float* W_gcn   = (const float*)d_in[9];
    const float* b_gcn   = (const float*)d_in[10];
    float* out = (float*)d_out;

    int E  = in_sizes[1] / 2;
    int ET = E + N_NODES;

    k_init<<<(N_NODES + 255) / 256, 256>>>();

    dim3 g1(HC / BN, (N_NODES + BM - 1) / BM);
    k_gemm1<<<g1, 256>>>(x, W_gat);

    k_count<<<(ET + 255) / 256, 256>>>(ei, E);
    k_scan<<<1, 1024>>>();
    k_fill<<<(ET + 255) / 256, 256>>>(ei, ew, E);

    k_att<<<(N_NODES * HEADS * 32 + 255) / 256, 256>>>(att_src, att_dst);
    k_softmax<<<(N_NODES * 32 + 255) / 256, 256>>>();
    k_aggregate<<<N_NODES, 128>>>(b_gat);

    k_bnstats<<<240, 512>>>();
    k_bnfinal<<<2, 256>>>(gamma, beta);

    k_gemm2<<<(N_NODES + 63) / 64, 256>>>(W_gcn);
    k_gcn<<<(N_NODES * 32 + 255) / 256, 256>>>(b_gcn, out);
}

// round 3
// speedup vs baseline: 3.2913x; 1.0034x over previous
#include <cuda_runtime.h>
#include <cuda_bf16.h>
#include <math.h>

#define N_NODES 30000
#define E_MAX   480000
#define ET_MAX  (E_MAX + N_NODES)
#define F_IN    1280
#define HEADS   4
#define CH      128
#define HC      512
#define HID     64

// ---------------- scratch ----------------
__device__ float g_h[(size_t)N_NODES * HC];
__device__ float g_out1[(size_t)N_NODES * HC];
__device__ float g_asrc[N_NODES * HEADS];
__device__ float g_adst[N_NODES * HEADS];
__device__ float g_alpha[(size_t)ET_MAX * HEADS];
__device__ float g_h2[(size_t)N_NODES * HID];
__device__ float g_dinv[N_NODES];
__device__ float g_colsum[HC];
__device__ float g_colsum2[HC];
__device__ float g_scale[HC];
__device__ float g_shift[HC];
// CSR
__device__ int   g_cnt[N_NODES];
__device__ int   g_off[N_NODES + 1];
__device__ int   g_esrc[ET_MAX];
__device__ float g_ewc[ET_MAX];
// pre-split bf16 operands for GEMM1
__device__ __nv_bfloat16 g_ah[(size_t)N_NODES * F_IN];
__device__ __nv_bfloat16 g_al[(size_t)N_NODES * F_IN];
__device__ __nv_bfloat16 g_bh[(size_t)HC * F_IN];   // B^T: [n][k]
__device__ __nv_bfloat16 g_bl[(size_t)HC * F_IN];
// scan partials
#define SCAN_BLOCKS 120
#define SCAN_CHUNK  ((N_NODES + SCAN_BLOCKS - 1) / SCAN_BLOCKS)   // 250
__device__ int g_bsum[SCAN_BLOCKS];

// ---------------- init ----------------
__global__ void k_init() {
    int i = blockIdx.x * blockDim.x + threadIdx.x;
    if (i < N_NODES) g_cnt[i] = 0;
    if (i < HC) { g_colsum[i] = 0.0f; g_colsum2[i] = 0.0f; }
}

// ---------------- split kernels ----------------
__global__ void k_split_a(const float* __restrict__ X) {
    size_t i = (size_t)blockIdx.x * blockDim.x + threadIdx.x;
    if (i * 4 >= (size_t)N_NODES * F_IN) return;
    float4 v = ((const float4*)X)[i];
    __nv_bfloat16 h0 = __float2bfloat16(v.x), h1 = __float2bfloat16(v.y);
    __nv_bfloat16 h2 = __float2bfloat16(v.z), h3 = __float2bfloat16(v.w);
    __nv_bfloat16 l0 = __float2bfloat16(v.x - __bfloat162float(h0));
    __nv_bfloat16 l1 = __float2bfloat16(v.y - __bfloat162float(h1));
    __nv_bfloat16 l2 = __float2bfloat16(v.z - __bfloat162float(h2));
    __nv_bfloat16 l3 = __float2bfloat16(v.w - __bfloat162float(h3));
    ((__nv_bfloat162*)g_ah)[i * 2 + 0] = __nv_bfloat162(h0, h1);
    ((__nv_bfloat162*)g_ah)[i * 2 + 1] = __nv_bfloat162(h2, h3);
    ((__nv_bfloat162*)g_al)[i * 2 + 0] = __nv_bfloat162(l0, l1);
    ((__nv_bfloat162*)g_al)[i * 2 + 1] = __nv_bfloat162(l2, l3);
}

__global__ void k_split_bt(const float* __restrict__ W) {
    int idx = blockIdx.x * blockDim.x + threadIdx.x;   // over 1280*512
    if (idx >= F_IN * HC) return;
    int k = idx >> 9, n = idx & (HC - 1);
    float v = W[idx];
    __nv_bfloat16 h = __float2bfloat16(v);
    __nv_bfloat16 l = __float2bfloat16(v - __bfloat162float(h));
    g_bh[(size_t)n * F_IN + k] = h;
    g_bl[(size_t)n * F_IN + k] = l;
}

// ================= GEMM1: g_h = x @ W_gat (bf16 split, cp.async pipelined) =================
#define BM 128
#define BN 256
#define BK 32
#define SA 40                        // smem row stride in bf16 (80B, conflict-free)
#define A_ST   (BM * SA)             // 5120 bf16
#define B_ST   (BN * SA)             // 10240 bf16
#define STAGE_ELEMS (2 * A_ST + 2 * B_ST)    // Ah, Al, Bh, Bl
#define GEMM1_SMEM (2 * STAGE_ELEMS * 2)     // bytes: 2 stages * elems * 2B = 122880

__device__ __forceinline__ void mma16816(float* c, const unsigned* a, unsigned b0, unsigned b1) {
    asm volatile(
        "mma.sync.aligned.m16n8k16.row.col.f32.bf16.bf16.f32 "
        "{%0,%1,%2,%3}, {%4,%5,%6,%7}, {%8,%9}, {%0,%1,%2,%3};\n"
        : "+f"(c[0]), "+f"(c[1]), "+f"(c[2]), "+f"(c[3])
        : "r"(a[0]), "r"(a[1]), "r"(a[2]), "r"(a[3]), "r"(b0), "r"(b1));
}

__device__ __forceinline__ void cpa16(void* dst, const void* src, int sz) {
    unsigned d = (unsigned)__cvta_generic_to_shared(dst);
    asm volatile("cp.async.ca.shared.global [%0], [%1], 16, %2;\n"
                 :: "r"(d), "l"(src), "r"(sz));
}

__global__ void __launch_bounds__(512, 1)
k_gemm1() {
    extern __shared__ __nv_bfloat16 sm[];

    int tid  = threadIdx.x;
    int warp = tid >> 5, lane = tid & 31;
    int row0 = blockIdx.y * BM, col0 = blockIdx.x * BN;
    int wm = (warp >> 2) * 32, wn = (warp & 3) * 64;
    int g = lane >> 2, tig = lane & 3;

    float acc[2][8][4];
#pragma unroll
    for (int t = 0; t < 2; t++)
#pragma unroll
        for (int n = 0; n < 8; n++)
#pragma unroll
            for (int j = 0; j < 4; j++) acc[t][n][j] = 0.0f;

    // load maps
    int arow = tid >> 2, achk = tid & 3;              // A: 128 rows x 4 chunks(16B)
    int gr   = row0 + arow;
    int asz  = (gr < N_NODES) ? 16 : 0;
    size_t asrc_off = (size_t)min(gr, N_NODES - 1) * F_IN + achk * 8;
    int brow = tid >> 2, bchk = tid & 3;              // B: 256 rows (two halves) x 4 chunks
    size_t bsrc0 = (size_t)(col0 + brow) * F_IN + bchk * 8;
    size_t bsrc1 = (size_t)(col0 + brow + 128) * F_IN + bchk * 8;

    const int NIT = F_IN / BK;   // 40

    // stage pointers
    __nv_bfloat16* st[2];
    st[0] = sm;
    st[1] = sm + STAGE_ELEMS;

    // prologue: issue tile 0
    {
        __nv_bfloat16* s = st[0];
        cpa16(s + arow * SA + achk * 8,              g_ah + asrc_off, asz);
        cpa16(s + A_ST + arow * SA + achk * 8,       g_al + asrc_off, asz);
        cpa16(s + 2*A_ST + brow * SA + bchk * 8,           g_bh + bsrc0, 16);
        cpa16(s + 2*A_ST + (brow+128) * SA + bchk * 8,     g_bh + bsrc1, 16);
        cpa16(s + 2*A_ST + B_ST + brow * SA + bchk * 8,       g_bl + bsrc0, 16);
        cpa16(s + 2*A_ST + B_ST + (brow+128) * SA + bchk * 8, g_bl + bsrc1, 16);
        asm volatile("cp.async.commit_group;\n");
    }

    for (int it = 0; it < NIT; it++) {
        // issue next tile
        if (it + 1 < NIT) {
            int k0 = (it + 1) * BK;
            __nv_bfloat16* s = st[(it + 1) & 1];
            cpa16(s + arow * SA + achk * 8,              g_ah + asrc_off + k0, asz);
            cpa16(s + A_ST + arow * SA + achk * 8,       g_al + asrc_off + k0, asz);
            cpa16(s + 2*A_ST + brow * SA + bchk * 8,           g_bh + bsrc0 + k0, 16);
            cpa16(s + 2*A_ST + (brow+128) * SA + bchk * 8,     g_bh + bsrc1 + k0, 16);
            cpa16(s + 2*A_ST + B_ST + brow * SA + bchk * 8,       g_bl + bsrc0 + k0, 16);
            cpa16(s + 2*A_ST + B_ST + (brow+128) * SA + bchk * 8, g_bl + bsrc1 + k0, 16);
        }
        asm volatile("cp.async.commit_group;\n");
        asm volatile("cp.async.wait_group 1;\n");
        __syncthreads();

        const __nv_bfloat16* pAh = st[it & 1];
        const __nv_bfloat16* pAl = pAh + A_ST;
        const __nv_bfloat16* pBh = pAh + 2 * A_ST;
        const __nv_bfloat16* pBl = pBh + B_ST;

#pragma unroll
        for (int kk = 0; kk < BK; kk += 16) {
            unsigned ah[2][4], al[2][4];
#pragma unroll
            for (int t = 0; t < 2; t++) {
                const __nv_bfloat16* ba = pAh + (wm + t * 16 + g) * SA + kk + tig * 2;
                ah[t][0] = *(const unsigned*)(ba);
                ah[t][1] = *(const unsigned*)(ba + 8 * SA);
                ah[t][2] = *(const unsigned*)(ba + 8);
                ah[t][3] = *(const unsigned*)(ba + 8 * SA + 8);
                const __nv_bfloat16* bl2 = pAl + (wm + t * 16 + g) * SA + kk + tig * 2;
                al[t][0] = *(const unsigned*)(bl2);
                al[t][1] = *(const unsigned*)(bl2 + 8 * SA);
                al[t][2] = *(const unsigned*)(bl2 + 8);
                al[t][3] = *(const unsigned*)(bl2 + 8 * SA + 8);
            }
#pragma unroll
            for (int n = 0; n < 8; n++) {
                const __nv_bfloat16* bb = pBh + (wn + n * 8 + g) * SA + kk + tig * 2;
                unsigned bh0 = *(const unsigned*)(bb);
                unsigned bh1 = *(const unsigned*)(bb + 8);
                const __nv_bfloat16* bc = pBl + (wn + n * 8 + g) * SA + kk + tig * 2;
                unsigned bl0 = *(const unsigned*)(bc);
                unsigned bl1 = *(const unsigned*)(bc + 8);
                mma16816(acc[0][n], ah[0], bh0, bh1);
                mma16816(acc[1][n], ah[1], bh0, bh1);
                mma16816(acc[0][n], al[0], bh0, bh1);
                mma16816(acc[1][n], al[1], bh0, bh1);
                mma16816(acc[0][n], ah[0], bl0, bl1);
                mma16816(acc[1][n], ah[1], bl0, bl1);
            }
        }
        __syncthreads();
    }

    // epilogue
#pragma unroll
    for (int t = 0; t < 2; t++) {
        int r0 = row0 + wm + t * 16 + g;
#pragma unroll
        for (int n = 0; n < 8; n++) {
            int cc = col0 + wn + n * 8 + tig * 2;
            if (r0 < N_NODES)
                *(float2*)&g_h[(size_t)r0 * HC + cc] = make_float2(acc[t][n][0], acc[t][n][1]);
            if (r0 + 8 < N_NODES)
                *(float2*)&g_h[(size_t)(r0 + 8) * HC + cc] = make_float2(acc[t][n][2], acc[t][n][3]);
        }
    }
}

// ---------------- attention dots ----------------
__global__ void k_att(const float* __restrict__ att_src, const float* __restrict__ att_dst) {
    int gw   = (blockIdx.x * blockDim.x + threadIdx.x) >> 5;
    int lane = threadIdx.x & 31;
    if (gw >= N_NODES * HEADS) return;
    int n = gw >> 2, hd = gw & 3;
    float4 hv = *(const float4*)&g_h[(size_t)n * HC + hd * CH + lane * 4];
    float4 sv = *(const float4*)&att_src[hd * CH + lane * 4];
    float4 dv = *(const float4*)&att_dst[hd * CH + lane * 4];
    float vs = hv.x * sv.x + hv.y * sv.y + hv.z * sv.z + hv.w * sv.w;
    float vd = hv.x * dv.x + hv.y * dv.y + hv.z * dv.z + hv.w * dv.w;
#pragma unroll
    for (int o = 16; o > 0; o >>= 1) {
        vs += __shfl_down_sync(0xFFFFFFFFu, vs, o);
        vd += __shfl_down_sync(0xFFFFFFFFu, vd, o);
    }
    if (lane == 0) { g_asrc[gw] = vs; g_adst[gw] = vd; }
}

// ---------------- CSR build ----------------
__global__ void k_count(const int* __restrict__ ei, int E) {
    int e = blockIdx.x * blockDim.x + threadIdx.x;
    int ET = E + N_NODES;
    if (e >= ET) return;
    int d = (e < E) ? ei[E + e] : (e - E);
    atomicAdd(&g_cnt[d], 1);
}

__global__ void k_scan1() {     // per-block partial sums
    __shared__ int red[8];
    int b = blockIdx.x, t = threadIdx.x;     // 256 threads
    int lo = b * SCAN_CHUNK, hi = min(lo + SCAN_CHUNK, N_NODES);
    int s = 0;
    for (int i = lo + t; i < hi; i += 256) s += g_cnt[i];
#pragma unroll
    for (int o = 16; o > 0; o >>= 1) s += __shfl_xor_sync(0xFFFFFFFFu, s, o);
    if ((t & 31) == 0) red[t >> 5] = s;
    __syncthreads();
    if (t == 0) {
        int tot = 0;
#pragma unroll
        for (int i = 0; i < 8; i++) tot += red[i];
        g_bsum[b] = tot;
    }
}

__global__ void k_scan2() {     // exclusive scan of 120 partials, 1 block 128 thr
    __shared__ int sh[128];
    int t = threadIdx.x;
    int v = (t < SCAN_BLOCKS) ? g_bsum[t] : 0;
    sh[t] = v;
    __syncthreads();
#pragma unroll
    for (int o = 1; o < 128; o <<= 1) {
        int x = (t >= o) ? sh[t - o] : 0;
        __syncthreads();
        sh[t] += x;
        __syncthreads();
    }
    if (t < SCAN_BLOCKS) g_bsum[t] = sh[t] - v;   // exclusive
    if (t == 127) g_off[N_NODES] = sh[127];       // total
}

__global__ void k_scan3() {     // local scans + base
    __shared__ int sh[256];
    int b = blockIdx.x, t = threadIdx.x;   // 256 threads, chunk=250
    int lo = b * SCAN_CHUNK;
    int i = lo + t;
    int v = (t < SCAN_CHUNK && i < N_NODES) ? g_cnt[i] : 0;
    sh[t] = v;
    __syncthreads();
#pragma unroll
    for (int o = 1; o < 256; o <<= 1) {
        int x = (t >= o) ? sh[t - o] : 0;
        __syncthreads();
        sh[t] += x;
        __syncthreads();
    }
    if (t < SCAN_CHUNK && i < N_NODES) {
        g_off[i] = g_bsum[b] + sh[t] - v;
        g_cnt[i] = 0;
    }
}

__global__ void k_fill(const int* __restrict__ ei, const float* __restrict__ ew, int E) {
    int e = blockIdx.x * blockDim.x + threadIdx.x;
    int ET = E + N_NODES;
    if (e >= ET) return;
    int s, d; float w;
    if (e < E) { s = ei[e]; d = ei[E + e]; w = ew[e]; }
    else       { s = d = e - E; w = 1.0f; }
    int slot = g_off[d] + atomicAdd(&g_cnt[d], 1);
    g_esrc[slot] = s;
    g_ewc[slot]  = w;
}

// ---------------- fused segment softmax + weighted degree ----------------
__global__ void k_softmax() {
    int d    = (blockIdx.x * blockDim.x + threadIdx.x) >> 5;
    int lane = threadIdx.x & 31;
    if (d >= N_NODES) return;
    int beg = g_off[d], end = g_off[d + 1];
    int cnt = end - beg;
    float4 ad = *(const float4*)&g_adst[d * 4];

    float mx0 = -1e30f, mx1 = -1e30f, mx2 = -1e30f, mx3 = -1e30f;
    float degw = 0.0f;

    if (cnt <= 32) {
        int i = beg + lane;
        bool act = lane < cnt;
        float l0 = -1e30f, l1 = -1e30f, l2 = -1e30f, l3 = -1e30f;
        if (act) {
            int s = g_esrc[i];
            float4 as = *(const float4*)&g_asrc[s * 4];
            l0 = as.x + ad.x; l1 = as.y + ad.y; l2 = as.z + ad.z; l3 = as.w + ad.w;
            l0 = l0 > 0.f ? l0 : 0.2f * l0;
            l1 = l1 > 0.f ? l1 : 0.2f * l1;
            l2 = l2 > 0.f ? l2 : 0.2f * l2;
            l3 = l3 > 0.f ? l3 : 0.2f * l3;
            degw = g_ewc[i];
        }
        mx0 = l0; mx1 = l1; mx2 = l2; mx3 = l3;
#pragma unroll
        for (int o = 16; o > 0; o >>= 1) {
            mx0 = fmaxf(mx0, __shfl_xor_sync(0xFFFFFFFFu, mx0, o));
            mx1 = fmaxf(mx1, __shfl_xor_sync(0xFFFFFFFFu, mx1, o));
            mx2 = fmaxf(mx2, __shfl_xor_sync(0xFFFFFFFFu, mx2, o));
            mx3 = fmaxf(mx3, __shfl_xor_sync(0xFFFFFFFFu, mx3, o));
            degw += __shfl_xor_sync(0xFFFFFFFFu, degw, o);
        }
        float e0 = act ? __expf(l0 - mx0) : 0.f;
        float e1 = act ? __expf(l1 - mx1) : 0.f;
        float e2 = act ? __expf(l2 - mx2) : 0.f;
        float e3 = act ? __expf(l3 - mx3) : 0.f;
        float s0 = e0, s1 = e1, s2 = e2, s3 = e3;
#pragma unroll
        for (int o = 16; o > 0; o >>= 1) {
            s0 += __shfl_xor_sync(0xFFFFFFFFu, s0, o);
            s1 += __shfl_xor_sync(0xFFFFFFFFu, s1, o);
            s2 += __shfl_xor_sync(0xFFFFFFFFu, s2, o);
            s3 += __shfl_xor_sync(0xFFFFFFFFu, s3, o);
        }
        if (act) {
            float4 al = make_float4(e0 / (s0 + 1e-16f), e1 / (s1 + 1e-16f),
                                    e2 / (s2 + 1e-16f), e3 / (s3 + 1e-16f));
            *(float4*)&g_alpha[(size_t)i * 4] = al;
        }
    } else {
        for (int i = beg + lane; i < end; i += 32) {
            int s = g_esrc[i];
            float4 as = *(const float4*)&g_asrc[s * 4];
            float l0 = as.x + ad.x, l1 = as.y + ad.y, l2 = as.z + ad.z, l3 = as.w + ad.w;
            l0 = l0 > 0.f ? l0 : 0.2f * l0;
            l1 = l1 > 0.f ? l1 : 0.2f * l1;
            l2 = l2 > 0.f ? l2 : 0.2f * l2;
            l3 = l3 > 0.f ? l3 : 0.2f * l3;
            *(float4*)&g_alpha[(size_t)i * 4] = make_float4(l0, l1, l2, l3);
            mx0 = fmaxf(mx0, l0); mx1 = fmaxf(mx1, l1);
            mx2 = fmaxf(mx2, l2); mx3 = fmaxf(mx3, l3);
            degw += g_ewc[i];
        }
#pragma unroll
        for (int o = 16; o > 0; o >>= 1) {
            mx0 = fmaxf(mx0, __shfl_xor_sync(0xFFFFFFFFu, mx0, o));
            mx1 = fmaxf(mx1, __shfl_xor_sync(0xFFFFFFFFu, mx1, o));
            mx2 = fmaxf(mx2, __shfl_xor_sync(0xFFFFFFFFu, mx2, o));
            mx3 = fmaxf(mx3, __shfl_xor_sync(0xFFFFFFFFu, mx3, o));
            degw += __shfl_xor_sync(0xFFFFFFFFu, degw, o);
        }
        float s0 = 0.f, s1 = 0.f, s2 = 0.f, s3 = 0.f;
        for (int i = beg + lane; i < end; i += 32) {
            float4 l = *(const float4*)&g_alpha[(size_t)i * 4];
            float e0 = __expf(l.x - mx0), e1 = __expf(l.y - mx1);
            float e2 = __expf(l.z - mx2), e3 = __expf(l.w - mx3);
            *(float4*)&g_alpha[(size_t)i * 4] = make_float4(e0, e1, e2, e3);
            s0 += e0; s1 += e1; s2 += e2; s3 += e3;
        }
#pragma unroll
        for (int o = 16; o > 0; o >>= 1) {
            s0 += __shfl_xor_sync(0xFFFFFFFFu, s0, o);
            s1 += __shfl_xor_sync(0xFFFFFFFFu, s1, o);
            s2 += __shfl_xor_sync(0xFFFFFFFFu, s2, o);
            s3 += __shfl_xor_sync(0xFFFFFFFFu, s3, o);
        }
        float r0 = 1.f / (s0 + 1e-16f), r1 = 1.f / (s1 + 1e-16f);
        float r2 = 1.f / (s2 + 1e-16f), r3 = 1.f / (s3 + 1e-16f);
        for (int i = beg + lane; i < end; i += 32) {
            float4 l = *(const float4*)&g_alpha[(size_t)i * 4];
            *(float4*)&g_alpha[(size_t)i * 4] = make_float4(l.x * r0, l.y * r1, l.z * r2, l.w * r3);
        }
    }
    if (lane == 0) g_dinv[d] = degw > 0.f ? rsqrtf(degw) : 0.0f;
}

// ---------------- GAT aggregation: block per dst, 2x unrolled ----------------
__global__ void __launch_bounds__(128)
k_aggregate(const float* __restrict__ b_gat) {
    int d = blockIdx.x;
    int tid = threadIdx.x;
    int head = tid >> 5;
    int c = tid * 4;
    float4 acc = *(const float4*)&b_gat[c];
    int beg = g_off[d], end = g_off[d + 1];
    int i = beg;
    for (; i + 1 < end; i += 2) {
        int s0 = g_esrc[i], s1 = g_esrc[i + 1];
        float a0 = g_alpha[(size_t)i * 4 + head];
        float a1 = g_alpha[(size_t)(i + 1) * 4 + head];
        float4 v0 = *(const float4*)&g_h[(size_t)s0 * HC + c];
        float4 v1 = *(const float4*)&g_h[(size_t)s1 * HC + c];
        acc.x = fmaf(v0.x, a0, acc.x); acc.y = fmaf(v0.y, a0, acc.y);
        acc.z = fmaf(v0.z, a0, acc.z); acc.w = fmaf(v0.w, a0, acc.w);
        acc.x = fmaf(v1.x, a1, acc.x); acc.y = fmaf(v1.y, a1, acc.y);
        acc.z = fmaf(v1.z, a1, acc.z); acc.w = fmaf(v1.w, a1, acc.w);
    }
    if (i < end) {
        int s0 = g_esrc[i];
        float a0 = g_alpha[(size_t)i * 4 + head];
        float4 v0 = *(const float4*)&g_h[(size_t)s0 * HC + c];
        acc.x = fmaf(v0.x, a0, acc.x); acc.y = fmaf(v0.y, a0, acc.y);
        acc.z = fmaf(v0.z, a0, acc.z); acc.w = fmaf(v0.w, a0, acc.w);
    }
    *(float4*)&g_out1[(size_t)d * HC + c] = acc;
}

// ---------------- BN stats ----------------
__global__ void k_bnstats() {
    int col = threadIdx.x;
    float s = 0.f, s2 = 0.f;
    for (int r = blockIdx.x; r < N_NODES; r += gridDim.x) {
        float v = g_out1[(size_t)r * HC + col];
        s += v; s2 += v * v;
    }
    atomicAdd(&g_colsum[col], s);
    atomicAdd(&g_colsum2[col], s2);
}

__global__ void k_bnfinal(const float* __restrict__ gamma, const float* __restrict__ beta) {
    int c = blockIdx.x * blockDim.x + threadIdx.x;
    if (c >= HC) return;
    float mean = g_colsum[c] * (1.0f / N_NODES);
    float var  = g_colsum2[c] * (1.0f / N_NODES) - mean * mean;
    float sc = gamma[c] * rsqrtf(var + 1e-5f);
    g_scale[c] = sc;
    g_shift[c] = beta[c] - mean * sc;
}

// ---------------- GEMM2 ----------------
__global__ void k_gemm2(const float* __restrict__ W) {
    __shared__ float As[16][64];
    __shared__ float Bs[16][64];
    int tid  = threadIdx.x;
    int row0 = blockIdx.x * 64;
    int arow = tid >> 2, acol = (tid & 3) * 4;
    int brow = tid >> 4, bcol = (tid & 15) * 4;
    int ty = tid >> 4, tx = tid & 15;

    float acc[4][4];
#pragma unroll
    for (int i = 0; i < 4; i++)
#pragma unroll
        for (int j = 0; j < 4; j++) acc[i][j] = 0.0f;

    for (int k0 = 0; k0 < HC; k0 += 16) {
        float4 av = make_float4(0.f, 0.f, 0.f, 0.f);
        int ar = row0 + arow;
        if (ar < N_NODES)
            av = *(const float4*)&g_out1[(size_t)ar * HC + k0 + acol];
        int kc = k0 + acol;
        av.x = fmaxf(fmaf(av.x, g_scale[kc + 0], g_shift[kc + 0]), 0.0f);
        av.y = fmaxf(fmaf(av.y, g_scale[kc + 1], g_shift[kc + 1]), 0.0f);
        av.z = fmaxf(fmaf(av.z, g_scale[kc + 2], g_shift[kc + 2]), 0.0f);
        av.w = fmaxf(fmaf(av.w, g_scale[kc + 3], g_shift[kc + 3]), 0.0f);
        As[acol + 0][arow] = av.x;
        As[acol + 1][arow] = av.y;
        As[acol + 2][arow] = av.z;
        As[acol + 3][arow] = av.w;
        float4 bv = *(const float4*)&W[(size_t)(k0 + brow) * HID + bcol];
        *(float4*)&Bs[brow][bcol] = bv;
        __syncthreads();
#pragma unroll
        for (int kk = 0; kk < 16; kk++) {
            float a4[4], b4[4];
#pragma unroll
            for (int i = 0; i < 4; i++) a4[i] = As[kk][ty * 4 + i];
#pragma unroll
            for (int j = 0; j < 4; j++) b4[j] = Bs[kk][tx * 4 + j];
#pragma unroll
            for (int i = 0; i < 4; i++)
#pragma unroll
                for (int j = 0; j < 4; j++) acc[i][j] = fmaf(a4[i], b4[j], acc[i][j]);
        }
        __syncthreads();
    }
#pragma unroll
    for (int i = 0; i < 4; i++) {
        int r = row0 + ty * 4 + i;
        if (r >= N_NODES) continue;
        float4 v = make_float4(acc[i][0], acc[i][1], acc[i][2], acc[i][3]);
        *(float4*)&g_h2[(size_t)r * HID + tx * 4] = v;
    }
}

// ---------------- GCN gather: warp per dst, 2x unrolled ----------------
__global__ void k_gcn(const float* __restrict__ b_gcn, float* __restrict__ out) {
    int d    = (blockIdx.x * blockDim.x + threadIdx.x) >> 5;
    int lane = threadIdx.x & 31;
    if (d >= N_NODES) return;
    float dinv_d = g_dinv[d];
    float2 acc = *(const float2*)&b_gcn[lane * 2];
    int beg = g_off[d], end = g_off[d + 1];
    int i = beg;
    for (; i + 1 < end; i += 2) {
        int s0 = g_esrc[i], s1 = g_esrc[i + 1];
        float n0 = g_dinv[s0] * g_ewc[i] * dinv_d;
        float n1 = g_dinv[s1] * g_ewc[i + 1] * dinv_d;
        float2 v0 = *(const float2*)&g_h2[(size_t)s0 * HID + lane * 2];
        float2 v1 = *(const float2*)&g_h2[(size_t)s1 * HID + lane * 2];
        acc.x = fmaf(v0.x, n0, acc.x); acc.y = fmaf(v0.y, n0, acc.y);
        acc.x = fmaf(v1.x, n1, acc.x); acc.y = fmaf(v1.y, n1, acc.y);
    }
    if (i < end) {
        int s0 = g_esrc[i];
        float n0 = g_dinv[s0] * g_ewc[i] * dinv_d;
        float2 v0 = *(const float2*)&g_h2[(size_t)s0 * HID + lane * 2];
        acc.x = fmaf(v0.x, n0, acc.x); acc.y = fmaf(v0.y, n0, acc.y);
    }
    *(float2*)&out[(size_t)d * HID + lane * 2] = acc;
}

// ---------------- launch ----------------
extern "C" void kernel_launch(void* const* d_in, const int* in_sizes, int n_in,
                              void* d_out, int out_size) {
    const float* x       = (const float*)d_in[0];
    const int*   ei      = (const int*)  d_in[1];
    const float* ew      = (const float*)d_in[2];
    const float* W_gat   = (const float*)d_in[3];
    const float* att_src = (const float*)d_in[4];
    const float* att_dst = (const float*)d_in[5];
    const float* b_gat   = (const float*)d_in[6];
    const float* gamma   = (const float*)d_in[7];
    const float* beta    = (const float*)d_in[8];
    const float* W_gcn   = (const float*)d_in[9];
    const float* b_gcn   = (const float*)d_in[10];
    float* out = (float*)d_out;

    int E  = in_sizes[1] / 2;
    int ET = E + N_NODES;

    static bool attr_set = false;
    if (!attr_set) {
        cudaFuncSetAttribute(k_gemm1, cudaFuncAttributeMaxDynamicSharedMemorySize, GEMM1_SMEM);
        attr_set = true;
    }

    k_init<<<(N_NODES + 255) / 256, 256>>>();
    k_split_a<<<((N_NODES * (F_IN / 4)) + 255) / 256, 256>>>(x);
    k_split_bt<<<(F_IN * HC + 255) / 256, 256>>>(W_gat);

    dim3 g1(HC / BN, (N_NODES + BM - 1) / BM);
    k_gemm1<<<g1, 512, GEMM1_SMEM>>>();

    k_count<<<(ET + 255) / 256, 256>>>(ei, E);
    k_scan1<<<SCAN_BLOCKS, 256>>>();
    k_scan2<<<1, 128>>>();
    k_scan3<<<SCAN_BLOCKS, 256>>>();
    k_fill<<<(ET + 255) / 256, 256>>>(ei, ew, E);

    k_att<<<(N_NODES * HEADS * 32 + 255) / 256, 256>>>(att_src, att_dst);
    k_softmax<<<(N_NODES * 32 + 255) / 256, 256>>>();
    k_aggregate<<<N_NODES, 128>>>(b_gat);

    k_bnstats<<<240, 512>>>();
    k_bnfinal<<<2, 256>>>(gamma, beta);

    k_gemm2<<<(N_NODES + 63) / 64, 256>>>(W_gcn);
    k_gcn<<<(N_NODES * 32 + 255) / 256, 256>>>(b_gcn, out);
}

// round 4
// speedup vs baseline: 3.3033x; 1.0036x over previous
#include <cuda_runtime.h>
#include <cuda_bf16.h>
#include <math.h>

#define N_NODES 30000
#define E_MAX   480000
#define ET_MAX  (E_MAX + N_NODES)
#define F_IN    1280
#define HEADS   4
#define CH      128
#define HC      512
#define HID     64

// ---------------- scratch ----------------
__device__ float g_h[(size_t)N_NODES * HC];
__device__ float g_out1[(size_t)N_NODES * HC];
__device__ float g_asrc[N_NODES * HEADS];
__device__ float g_adst[N_NODES * HEADS];
__device__ float g_alpha[(size_t)ET_MAX * HEADS];
__device__ float g_h2[(size_t)N_NODES * HID];
__device__ float g_dinv[N_NODES];
__device__ float g_colsum[HC];
__device__ float g_colsum2[HC];
__device__ float g_scale[HC];
__device__ float g_shift[HC];
// CSR
__device__ int   g_cnt[N_NODES];
__device__ int   g_off[N_NODES + 1];
__device__ int   g_esrc[ET_MAX];
__device__ float g_ewc[ET_MAX];
// pre-split bf16 operands for GEMM1
__device__ __nv_bfloat16 g_ah[(size_t)N_NODES * F_IN];
__device__ __nv_bfloat16 g_al[(size_t)N_NODES * F_IN];
__device__ __nv_bfloat16 g_bh[(size_t)HC * F_IN];   // B^T: [n][k]
__device__ __nv_bfloat16 g_bl[(size_t)HC * F_IN];
// scan partials
#define SCAN_BLOCKS 120
#define SCAN_CHUNK  ((N_NODES + SCAN_BLOCKS - 1) / SCAN_BLOCKS)   // 250
__device__ int g_bsum[SCAN_BLOCKS];

// ---------------- init ----------------
__global__ void k_init() {
    int i = blockIdx.x * blockDim.x + threadIdx.x;
    if (i < N_NODES) g_cnt[i] = 0;
    if (i < HC) { g_colsum[i] = 0.0f; g_colsum2[i] = 0.0f; }
}

// ---------------- split kernels ----------------
__global__ void k_split_a(const float* __restrict__ X) {
    size_t i = (size_t)blockIdx.x * blockDim.x + threadIdx.x;
    if (i * 4 >= (size_t)N_NODES * F_IN) return;
    float4 v = ((const float4*)X)[i];
    __nv_bfloat16 h0 = __float2bfloat16(v.x), h1 = __float2bfloat16(v.y);
    __nv_bfloat16 h2 = __float2bfloat16(v.z), h3 = __float2bfloat16(v.w);
    __nv_bfloat16 l0 = __float2bfloat16(v.x - __bfloat162float(h0));
    __nv_bfloat16 l1 = __float2bfloat16(v.y - __bfloat162float(h1));
    __nv_bfloat16 l2 = __float2bfloat16(v.z - __bfloat162float(h2));
    __nv_bfloat16 l3 = __float2bfloat16(v.w - __bfloat162float(h3));
    ((__nv_bfloat162*)g_ah)[i * 2 + 0] = __nv_bfloat162(h0, h1);
    ((__nv_bfloat162*)g_ah)[i * 2 + 1] = __nv_bfloat162(h2, h3);
    ((__nv_bfloat162*)g_al)[i * 2 + 0] = __nv_bfloat162(l0, l1);
    ((__nv_bfloat162*)g_al)[i * 2 + 1] = __nv_bfloat162(l2, l3);
}

__global__ void k_split_bt(const float* __restrict__ W) {
    int idx = blockIdx.x * blockDim.x + threadIdx.x;   // over 1280*512
    if (idx >= F_IN * HC) return;
    int k = idx >> 9, n = idx & (HC - 1);
    float v = W[idx];
    __nv_bfloat16 h = __float2bfloat16(v);
    __nv_bfloat16 l = __float2bfloat16(v - __bfloat162float(h));
    g_bh[(size_t)n * F_IN + k] = h;
    g_bl[(size_t)n * F_IN + k] = l;
}

// ================= GEMM1: g_h = x @ W_gat (bf16 split, ldmatrix, 3-stage) =================
#define BM 128
#define BN 256
#define BK 32
#define SA 40
#define A_ST   (BM * SA)
#define B_ST   (BN * SA)
#define STAGE_ELEMS (2 * A_ST + 2 * B_ST)        // Ah, Al, Bh, Bl = 30720 bf16
#define NSTAGE 3
#define GEMM1_SMEM (NSTAGE * STAGE_ELEMS * 2)    // 184320 bytes

__device__ __forceinline__ void mma16816(float* c, const unsigned* a, unsigned b0, unsigned b1) {
    asm volatile(
        "mma.sync.aligned.m16n8k16.row.col.f32.bf16.bf16.f32 "
        "{%0,%1,%2,%3}, {%4,%5,%6,%7}, {%8,%9}, {%0,%1,%2,%3};\n"
        : "+f"(c[0]), "+f"(c[1]), "+f"(c[2]), "+f"(c[3])
        : "r"(a[0]), "r"(a[1]), "r"(a[2]), "r"(a[3]), "r"(b0), "r"(b1));
}

__device__ __forceinline__ void ldsm4(unsigned* r, const __nv_bfloat16* p) {
    unsigned a = (unsigned)__cvta_generic_to_shared(p);
    asm volatile("ldmatrix.sync.aligned.m8n8.x4.shared.b16 {%0,%1,%2,%3}, [%4];\n"
                 : "=r"(r[0]), "=r"(r[1]), "=r"(r[2]), "=r"(r[3]) : "r"(a));
}

__device__ __forceinline__ void cpa16(void* dst, const void* src, int sz) {
    unsigned d = (unsigned)__cvta_generic_to_shared(dst);
    asm volatile("cp.async.ca.shared.global [%0], [%1], 16, %2;\n"
                 :: "r"(d), "l"(src), "r"(sz));
}

__global__ void __launch_bounds__(512, 1)
k_gemm1() {
    extern __shared__ __nv_bfloat16 sm[];

    int tid  = threadIdx.x;
    int warp = tid >> 5, lane = tid & 31;
    int row0 = blockIdx.y * BM, col0 = blockIdx.x * BN;
    int wm = (warp >> 2) * 32, wn = (warp & 3) * 64;

    float acc[2][8][4];
#pragma unroll
    for (int t = 0; t < 2; t++)
#pragma unroll
        for (int n = 0; n < 8; n++)
#pragma unroll
            for (int j = 0; j < 4; j++) acc[t][n][j] = 0.0f;

    // global load maps
    int arow = tid >> 2, achk = tid & 3;
    int gr   = row0 + arow;
    int asz  = (gr < N_NODES) ? 16 : 0;
    size_t asrc_off = (size_t)min(gr, N_NODES - 1) * F_IN + achk * 8;
    int brow = tid >> 2, bchk = tid & 3;
    size_t bsrc0 = (size_t)(col0 + brow) * F_IN + bchk * 8;
    size_t bsrc1 = (size_t)(col0 + brow + 128) * F_IN + bchk * 8;

    // ldmatrix per-lane address components
    int aRow = lane & 15;                 // row within 16-row A frag
    int aK   = (lane >> 4) << 3;          // 0 or 8
    int bRow = ((lane >> 4) << 3) + (lane & 7);  // row within 16-row (2x n8) B frag
    int bK   = ((lane >> 3) & 1) << 3;    // 0,8,0,8 per 8-lane group

    const int NIT = F_IN / BK;   // 40

    __nv_bfloat16* st[NSTAGE];
#pragma unroll
    for (int s = 0; s < NSTAGE; s++) st[s] = sm + s * STAGE_ELEMS;

    // prologue: issue tiles 0 and 1
#pragma unroll
    for (int p = 0; p < 2; p++) {
        __nv_bfloat16* s = st[p];
        int k0 = p * BK;
        cpa16(s + arow * SA + achk * 8,              g_ah + asrc_off + k0, asz);
        cpa16(s + A_ST + arow * SA + achk * 8,       g_al + asrc_off + k0, asz);
        cpa16(s + 2*A_ST + brow * SA + bchk * 8,           g_bh + bsrc0 + k0, 16);
        cpa16(s + 2*A_ST + (brow+128) * SA + bchk * 8,     g_bh + bsrc1 + k0, 16);
        cpa16(s + 2*A_ST + B_ST + brow * SA + bchk * 8,       g_bl + bsrc0 + k0, 16);
        cpa16(s + 2*A_ST + B_ST + (brow+128) * SA + bchk * 8, g_bl + bsrc1 + k0, 16);
        asm volatile("cp.async.commit_group;\n");
    }

    for (int it = 0; it < NIT; it++) {
        if (it + 2 < NIT) {
            int k0 = (it + 2) * BK;
            __nv_bfloat16* s = st[(it + 2) % NSTAGE];
            cpa16(s + arow * SA + achk * 8,              g_ah + asrc_off + k0, asz);
            cpa16(s + A_ST + arow * SA + achk * 8,       g_al + asrc_off + k0, asz);
            cpa16(s + 2*A_ST + brow * SA + bchk * 8,           g_bh + bsrc0 + k0, 16);
            cpa16(s + 2*A_ST + (brow+128) * SA + bchk * 8,     g_bh + bsrc1 + k0, 16);
            cpa16(s + 2*A_ST + B_ST + brow * SA + bchk * 8,       g_bl + bsrc0 + k0, 16);
            cpa16(s + 2*A_ST + B_ST + (brow+128) * SA + bchk * 8, g_bl + bsrc1 + k0, 16);
        }
        asm volatile("cp.async.commit_group;\n");
        asm volatile("cp.async.wait_group 2;\n");
        __syncthreads();

        const __nv_bfloat16* pAh = st[it % NSTAGE];
        const __nv_bfloat16* pAl = pAh + A_ST;
        const __nv_bfloat16* pBh = pAh + 2 * A_ST;
        const __nv_bfloat16* pBl = pBh + B_ST;

#pragma unroll
        for (int kk = 0; kk < BK; kk += 16) {
            unsigned ah[2][4], al[2][4];
            ldsm4(ah[0], pAh + (wm +  0 + aRow) * SA + kk + aK);
            ldsm4(ah[1], pAh + (wm + 16 + aRow) * SA + kk + aK);
            ldsm4(al[0], pAl + (wm +  0 + aRow) * SA + kk + aK);
            ldsm4(al[1], pAl + (wm + 16 + aRow) * SA + kk + aK);
#pragma unroll
            for (int p = 0; p < 4; p++) {
                unsigned bh[4], bl[4];
                ldsm4(bh, pBh + (wn + p * 16 + bRow) * SA + kk + bK);
                ldsm4(bl, pBl + (wn + p * 16 + bRow) * SA + kk + bK);
                int n0 = 2 * p, n1 = 2 * p + 1;
                mma16816(acc[0][n0], ah[0], bh[0], bh[1]);
                mma16816(acc[1][n0], ah[1], bh[0], bh[1]);
                mma16816(acc[0][n0], al[0], bh[0], bh[1]);
                mma16816(acc[1][n0], al[1], bh[0], bh[1]);
                mma16816(acc[0][n0], ah[0], bl[0], bl[1]);
                mma16816(acc[1][n0], ah[1], bl[0], bl[1]);
                mma16816(acc[0][n1], ah[0], bh[2], bh[3]);
                mma16816(acc[1][n1], ah[1], bh[2], bh[3]);
                mma16816(acc[0][n1], al[0], bh[2], bh[3]);
                mma16816(acc[1][n1], al[1], bh[2], bh[3]);
                mma16816(acc[0][n1], ah[0], bl[2], bl[3]);
                mma16816(acc[1][n1], ah[1], bl[2], bl[3]);
            }
        }
        __syncthreads();
    }

    // epilogue
    int g = lane >> 2, tig = lane & 3;
#pragma unroll
    for (int t = 0; t < 2; t++) {
        int r0 = row0 + wm + t * 16 + g;
#pragma unroll
        for (int n = 0; n < 8; n++) {
            int cc = col0 + wn + n * 8 + tig * 2;
            if (r0 < N_NODES)
                *(float2*)&g_h[(size_t)r0 * HC + cc] = make_float2(acc[t][n][0], acc[t][n][1]);
            if (r0 + 8 < N_NODES)
                *(float2*)&g_h[(size_t)(r0 + 8) * HC + cc] = make_float2(acc[t][n][2], acc[t][n][3]);
        }
    }
}

// ---------------- attention dots ----------------
__global__ void k_att(const float* __restrict__ att_src, const float* __restrict__ att_dst) {
    int gw   = (blockIdx.x * blockDim.x + threadIdx.x) >> 5;
    int lane = threadIdx.x & 31;
    if (gw >= N_NODES * HEADS) return;
    int n = gw >> 2, hd = gw & 3;
    float4 hv = *(const float4*)&g_h[(size_t)n * HC + hd * CH + lane * 4];
    float4 sv = *(const float4*)&att_src[hd * CH + lane * 4];
    float4 dv = *(const float4*)&att_dst[hd * CH + lane * 4];
    float vs = hv.x * sv.x + hv.y * sv.y + hv.z * sv.z + hv.w * sv.w;
    float vd = hv.x * dv.x + hv.y * dv.y + hv.z * dv.z + hv.w * dv.w;
#pragma unroll
    for (int o = 16; o > 0; o >>= 1) {
        vs += __shfl_down_sync(0xFFFFFFFFu, vs, o);
        vd += __shfl_down_sync(0xFFFFFFFFu, vd, o);
    }
    if (lane == 0) { g_asrc[gw] = vs; g_adst[gw] = vd; }
}

// ---------------- CSR build ----------------
__global__ void k_count(const int* __restrict__ ei, int E) {
    int e = blockIdx.x * blockDim.x + threadIdx.x;
    int ET = E + N_NODES;
    if (e >= ET) return;
    int d = (e < E) ? ei[E + e] : (e - E);
    atomicAdd(&g_cnt[d], 1);
}

__global__ void k_scan1() {
    __shared__ int red[8];
    int b = blockIdx.x, t = threadIdx.x;
    int lo = b * SCAN_CHUNK, hi = min(lo + SCAN_CHUNK, N_NODES);
    int s = 0;
    for (int i = lo + t; i < hi; i += 256) s += g_cnt[i];
#pragma unroll
    for (int o = 16; o > 0; o >>= 1) s += __shfl_xor_sync(0xFFFFFFFFu, s, o);
    if ((t & 31) == 0) red[t >> 5] = s;
    __syncthreads();
    if (t == 0) {
        int tot = 0;
#pragma unroll
        for (int i = 0; i < 8; i++) tot += red[i];
        g_bsum[b] = tot;
    }
}

__global__ void k_scan2() {
    __shared__ int sh[128];
    int t = threadIdx.x;
    int v = (t < SCAN_BLOCKS) ? g_bsum[t] : 0;
    sh[t] = v;
    __syncthreads();
#pragma unroll
    for (int o = 1; o < 128; o <<= 1) {
        int x = (t >= o) ? sh[t - o] : 0;
        __syncthreads();
        sh[t] += x;
        __syncthreads();
    }
    if (t < SCAN_BLOCKS) g_bsum[t] = sh[t] - v;
    if (t == 127) g_off[N_NODES] = sh[127];
}

__global__ void k_scan3() {
    __shared__ int sh[256];
    int b = blockIdx.x, t = threadIdx.x;
    int lo = b * SCAN_CHUNK;
    int i = lo + t;
    int v = (t < SCAN_CHUNK && i < N_NODES) ? g_cnt[i] : 0;
    sh[t] = v;
    __syncthreads();
#pragma unroll
    for (int o = 1; o < 256; o <<= 1) {
        int x = (t >= o) ? sh[t - o] : 0;
        __syncthreads();
        sh[t] += x;
        __syncthreads();
    }
    if (t < SCAN_CHUNK && i < N_NODES) {
        g_off[i] = g_bsum[b] + sh[t] - v;
        g_cnt[i] = 0;
    }
}

__global__ void k_fill(const int* __restrict__ ei, const float* __restrict__ ew, int E) {
    int e = blockIdx.x * blockDim.x + threadIdx.x;
    int ET = E + N_NODES;
    if (e >= ET) return;
    int s, d; float w;
    if (e < E) { s = ei[e]; d = ei[E + e]; w = ew[e]; }
    else       { s = d = e - E; w = 1.0f; }
    int slot = g_off[d] + atomicAdd(&g_cnt[d], 1);
    g_esrc[slot] = s;
    g_ewc[slot]  = w;
}

// ---------------- fused segment softmax + weighted degree ----------------
__global__ void k_softmax() {
    int d    = (blockIdx.x * blockDim.x + threadIdx.x) >> 5;
    int lane = threadIdx.x & 31;
    if (d >= N_NODES) return;
    int beg = g_off[d], end = g_off[d + 1];
    int cnt = end - beg;
    float4 ad = *(const float4*)&g_adst[d * 4];

    float mx0 = -1e30f, mx1 = -1e30f, mx2 = -1e30f, mx3 = -1e30f;
    float degw = 0.0f;

    if (cnt <= 32) {
        int i = beg + lane;
        bool act = lane < cnt;
        float l0 = -1e30f, l1 = -1e30f, l2 = -1e30f, l3 = -1e30f;
        if (act) {
            int s = g_esrc[i];
            float4 as = *(const float4*)&g_asrc[s * 4];
            l0 = as.x + ad.x; l1 = as.y + ad.y; l2 = as.z + ad.z; l3 = as.w + ad.w;
            l0 = l0 > 0.f ? l0 : 0.2f * l0;
            l1 = l1 > 0.f ? l1 : 0.2f * l1;
            l2 = l2 > 0.f ? l2 : 0.2f * l2;
            l3 = l3 > 0.f ? l3 : 0.2f * l3;
            degw = g_ewc[i];
        }
        mx0 = l0; mx1 = l1; mx2 = l2; mx3 = l3;
#pragma unroll
        for (int o = 16; o > 0; o >>= 1) {
            mx0 = fmaxf(mx0, __shfl_xor_sync(0xFFFFFFFFu, mx0, o));
            mx1 = fmaxf(mx1, __shfl_xor_sync(0xFFFFFFFFu, mx1, o));
            mx2 = fmaxf(mx2, __shfl_xor_sync(0xFFFFFFFFu, mx2, o));
            mx3 = fmaxf(mx3, __shfl_xor_sync(0xFFFFFFFFu, mx3, o));
            degw += __shfl_xor_sync(0xFFFFFFFFu, degw, o);
        }
        float e0 = act ? __expf(l0 - mx0) : 0.f;
        float e1 = act ? __expf(l1 - mx1) : 0.f;
        float e2 = act ? __expf(l2 - mx2) : 0.f;
        float e3 = act ? __expf(l3 - mx3) : 0.f;
        float s0 = e0, s1 = e1, s2 = e2, s3 = e3;
#pragma unroll
        for (int o = 16; o > 0; o >>= 1) {
            s0 += __shfl_xor_sync(0xFFFFFFFFu, s0, o);
            s1 += __shfl_xor_sync(0xFFFFFFFFu, s1, o);
            s2 += __shfl_xor_sync(0xFFFFFFFFu, s2, o);
            s3 += __shfl_xor_sync(0xFFFFFFFFu, s3, o);
        }
        if (act) {
            float4 al = make_float4(e0 / (s0 + 1e-16f), e1 / (s1 + 1e-16f),
                                    e2 / (s2 + 1e-16f), e3 / (s3 + 1e-16f));
            *(float4*)&g_alpha[(size_t)i * 4] = al;
        }
    } else {
        for (int i = beg + lane; i < end; i += 32) {
            int s = g_esrc[i];
            float4 as = *(const float4*)&g_asrc[s * 4];
            float l0 = as.x + ad.x, l1 = as.y + ad.y, l2 = as.z + ad.z, l3 = as.w + ad.w;
            l0 = l0 > 0.f ? l0 : 0.2f * l0;
            l1 = l1 > 0.f ? l1 : 0.2f * l1;
            l2 = l2 > 0.f ? l2 : 0.2f * l2;
            l3 = l3 > 0.f ? l3 : 0.2f * l3;
            *(float4*)&g_alpha[(size_t)i * 4] = make_float4(l0, l1, l2, l3);
            mx0 = fmaxf(mx0, l0); mx1 = fmaxf(mx1, l1);
            mx2 = fmaxf(mx2, l2); mx3 = fmaxf(mx3, l3);
            degw += g_ewc[i];
        }
#pragma unroll
        for (int o = 16; o > 0; o >>= 1) {
            mx0 = fmaxf(mx0, __shfl_xor_sync(0xFFFFFFFFu, mx0, o));
            mx1 = fmaxf(mx1, __shfl_xor_sync(0xFFFFFFFFu, mx1, o));
            mx2 = fmaxf(mx2, __shfl_xor_sync(0xFFFFFFFFu, mx2, o));
            mx3 = fmaxf(mx3, __shfl_xor_sync(0xFFFFFFFFu, mx3, o));
            degw += __shfl_xor_sync(0xFFFFFFFFu, degw, o);
        }
        float s0 = 0.f, s1 = 0.f, s2 = 0.f, s3 = 0.f;
        for (int i = beg + lane; i < end; i += 32) {
            float4 l = *(const float4*)&g_alpha[(size_t)i * 4];
            float e0 = __expf(l.x - mx0), e1 = __expf(l.y - mx1);
            float e2 = __expf(l.z - mx2), e3 = __expf(l.w - mx3);
            *(float4*)&g_alpha[(size_t)i * 4] = make_float4(e0, e1, e2, e3);
            s0 += e0; s1 += e1; s2 += e2; s3 += e3;
        }
#pragma unroll
        for (int o = 16; o > 0; o >>= 1) {
            s0 += __shfl_xor_sync(0xFFFFFFFFu, s0, o);
            s1 += __shfl_xor_sync(0xFFFFFFFFu, s1, o);
            s2 += __shfl_xor_sync(0xFFFFFFFFu, s2, o);
            s3 += __shfl_xor_sync(0xFFFFFFFFu, s3, o);
        }
        float r0 = 1.f / (s0 + 1e-16f), r1 = 1.f / (s1 + 1e-16f);
        float r2 = 1.f / (s2 + 1e-16f), r3 = 1.f / (s3 + 1e-16f);
        for (int i = beg + lane; i < end; i += 32) {
            float4 l = *(const float4*)&g_alpha[(size_t)i * 4];
            *(float4*)&g_alpha[(size_t)i * 4] = make_float4(l.x * r0, l.y * r1, l.z * r2, l.w * r3);
        }
    }
    if (lane == 0) g_dinv[d] = degw > 0.f ? rsqrtf(degw) : 0.0f;
}

// ---------------- GAT aggregation ----------------
__global__ void __launch_bounds__(128)
k_aggregate(const float* __restrict__ b_gat) {
    int d = blockIdx.x;
    int tid = threadIdx.x;
    int head = tid >> 5;
    int c = tid * 4;
    float4 acc = *(const float4*)&b_gat[c];
    int beg = g_off[d], end = g_off[d + 1];
    int i = beg;
    for (; i + 1 < end; i += 2) {
        int s0 = g_esrc[i], s1 = g_esrc[i + 1];
        float a0 = g_alpha[(size_t)i * 4 + head];
        float a1 = g_alpha[(size_t)(i + 1) * 4 + head];
        float4 v0 = *(const float4*)&g_h[(size_t)s0 * HC + c];
        float4 v1 = *(const float4*)&g_h[(size_t)s1 * HC + c];
        acc.x = fmaf(v0.x, a0, acc.x); acc.y = fmaf(v0.y, a0, acc.y);
        acc.z = fmaf(v0.z, a0, acc.z); acc.w = fmaf(v0.w, a0, acc.w);
        acc.x = fmaf(v1.x, a1, acc.x); acc.y = fmaf(v1.y, a1, acc.y);
        acc.z = fmaf(v1.z, a1, acc.z); acc.w = fmaf(v1.w, a1, acc.w);
    }
    if (i < end) {
        int s0 = g_esrc[i];
        float a0 = g_alpha[(size_t)i * 4 + head];
        float4 v0 = *(const float4*)&g_h[(size_t)s0 * HC + c];
        acc.x = fmaf(v0.x, a0, acc.x); acc.y = fmaf(v0.y, a0, acc.y);
        acc.z = fmaf(v0.z, a0, acc.z); acc.w = fmaf(v0.w, a0, acc.w);
    }
    *(float4*)&g_out1[(size_t)d * HC + c] = acc;
}

// ---------------- BN stats ----------------
__global__ void k_bnstats() {
    int col = threadIdx.x;
    float s = 0.f, s2 = 0.f;
    for (int r = blockIdx.x; r < N_NODES; r += gridDim.x) {
        float v = g_out1[(size_t)r * HC + col];
        s += v; s2 += v * v;
    }
    atomicAdd(&g_colsum[col], s);
    atomicAdd(&g_colsum2[col], s2);
}

__global__ void k_bnfinal(const float* __restrict__ gamma, const float* __restrict__ beta) {
    int c = blockIdx.x * blockDim.x + threadIdx.x;
    if (c >= HC) return;
    float mean = g_colsum[c] * (1.0f / N_NODES);
    float var  = g_colsum2[c] * (1.0f / N_NODES) - mean * mean;
    float sc = gamma[c] * rsqrtf(var + 1e-5f);
    g_scale[c] = sc;
    g_shift[c] = beta[c] - mean * sc;
}

// ---------------- GEMM2 ----------------
__global__ void k_gemm2(const float* __restrict__ W) {
    __shared__ float As[16][64];
    __shared__ float Bs[16][64];
    int tid  = threadIdx.x;
    int row0 = blockIdx.x * 64;
    int arow = tid >> 2, acol = (tid & 3) * 4;
    int brow = tid >> 4, bcol = (tid & 15) * 4;
    int ty = tid >> 4, tx = tid & 15;

    float acc[4][4];
#pragma unroll
    for (int i = 0; i < 4; i++)
#pragma unroll
        for (int j = 0; j < 4; j++) acc[i][j] = 0.0f;

    for (int k0 = 0; k0 < HC; k0 += 16) {
        float4 av = make_float4(0.f, 0.f, 0.f, 0.f);
        int ar = row0 + arow;
        if (ar < N_NODES)
            av = *(const float4*)&g_out1[(size_t)ar * HC + k0 + acol];
        int kc = k0 + acol;
        av.x = fmaxf(fmaf(av.x, g_scale[kc + 0], g_shift[kc + 0]), 0.0f);
        av.y = fmaxf(fmaf(av.y, g_scale[kc + 1], g_shift[kc + 1]), 0.0f);
        av.z = fmaxf(fmaf(av.z, g_scale[kc + 2], g_shift[kc + 2]), 0.0f);
        av.w = fmaxf(fmaf(av.w, g_scale[kc + 3], g_shift[kc + 3]), 0.0f);
        As[acol + 0][arow] = av.x;
        As[acol + 1][arow] = av.y;
        As[acol + 2][arow] = av.z;
        As[acol + 3][arow] = av.w;
        float4 bv = *(const float4*)&W[(size_t)(k0 + brow) * HID + bcol];
        *(float4*)&Bs[brow][bcol] = bv;
        __syncthreads();
#pragma unroll
        for (int kk = 0; kk < 16; kk++) {
            float a4[4], b4[4];
#pragma unroll
            for (int i = 0; i < 4; i++) a4[i] = As[kk][ty * 4 + i];
#pragma unroll
            for (int j = 0; j < 4; j++) b4[j] = Bs[kk][tx * 4 + j];
#pragma unroll
            for (int i = 0; i < 4; i++)
#pragma unroll
                for (int j = 0; j < 4; j++) acc[i][j] = fmaf(a4[i], b4[j], acc[i][j]);
        }
        __syncthreads();
    }
#pragma unroll
    for (int i = 0; i < 4; i++) {
        int r = row0 + ty * 4 + i;
        if (r >= N_NODES) continue;
        float4 v = make_float4(acc[i][0], acc[i][1], acc[i][2], acc[i][3]);
        *(float4*)&g_h2[(size_t)r * HID + tx * 4] = v;
    }
}

// ---------------- GCN gather ----------------
__global__ void k_gcn(const float* __restrict__ b_gcn, float* __restrict__ out) {
    int d    = (blockIdx.x * blockDim.x + threadIdx.x) >> 5;
    int lane = threadIdx.x & 31;
    if (d >= N_NODES) return;
    float dinv_d = g_dinv[d];
    float2 acc = *(const float2*)&b_gcn[lane * 2];
    int beg = g_off[d], end = g_off[d + 1];
    int i = beg;
    for (; i + 1 < end; i += 2) {
        int s0 = g_esrc[i], s1 = g_esrc[i + 1];
        float n0 = g_dinv[s0] * g_ewc[i] * dinv_d;
        float n1 = g_dinv[s1] * g_ewc[i + 1] * dinv_d;
        float2 v0 = *(const float2*)&g_h2[(size_t)s0 * HID + lane * 2];
        float2 v1 = *(const float2*)&g_h2[(size_t)s1 * HID + lane * 2];
        acc.x = fmaf(v0.x, n0, acc.x); acc.y = fmaf(v0.y, n0, acc.y);
        acc.x = fmaf(v1.x, n1, acc.x); acc.y = fmaf(v1.y, n1, acc.y);
    }
    if (i < end) {
        int s0 = g_esrc[i];
        float n0 = g_dinv[s0] * g_ewc[i] * dinv_d;
        float2 v0 = *(const float2*)&g_h2[(size_t)s0 * HID + lane * 2];
        acc.x = fmaf(v0.x, n0, acc.x); acc.y = fmaf(v0.y, n0, acc.y);
    }
    *(float2*)&out[(size_t)d * HID + lane * 2] = acc;
}

// ---------------- launch ----------------
extern "C" void kernel_launch(void* const* d_in, const int* in_sizes, int n_in,
                              void* d_out, int out_size) {
    const float* x       = (const float*)d_in[0];
    const int*   ei      = (const int*)  d_in[1];
    const float* ew      = (const float*)d_in[2];
    const float* W_gat   = (const float*)d_in[3];
    const float* att_src = (const float*)d_in[4];
    const float* att_dst = (const float*)d_in[5];
    const float* b_gat   = (const float*)d_in[6];
    const float* gamma   = (const float*)d_in[7];
    const float* beta    = (const float*)d_in[8];
    const float* W_gcn   = (const float*)d_in[9];
    const float* b_gcn   = (const float*)d_in[10];
    float* out = (float*)d_out;

    int E  = in_sizes[1] / 2;
    int ET = E + N_NODES;

    static bool attr_set = false;
    if (!attr_set) {
        cudaFuncSetAttribute(k_gemm1, cudaFuncAttributeMaxDynamicSharedMemorySize, GEMM1_SMEM);
        attr_set = true;
    }

    k_init<<<(N_NODES + 255) / 256, 256>>>();
    k_split_a<<<((N_NODES * (F_IN / 4)) + 255) / 256, 256>>>(x);
    k_split_bt<<<(F_IN * HC + 255) / 256, 256>>>(W_gat);

    dim3 g1(HC / BN, (N_NODES + BM - 1) / BM);
    k_gemm1<<<g1, 512, GEMM1_SMEM>>>();

    k_count<<<(ET + 255) / 256, 256>>>(ei, E);
    k_scan1<<<SCAN_BLOCKS, 256>>>();
    k_scan2<<<1, 128>>>();
    k_scan3<<<SCAN_BLOCKS, 256>>>();
    k_fill<<<(ET + 255) / 256, 256>>>(ei, ew, E);

    k_att<<<(N_NODES * HEADS * 32 + 255) / 256, 256>>>(att_src, att_dst);
    k_softmax<<<(N_NODES * 32 + 255) / 256, 256>>>();
    k_aggregate<<<N_NODES, 128>>>(b_gat);

    k_bnstats<<<240, 512>>>();
    k_bnfinal<<<2, 256>>>(gamma, beta);

    k_gemm2<<<(N_NODES + 63) / 64, 256>>>(W_gcn);
    k_gcn<<<(N_NODES * 32 + 255) / 256, 256>>>(b_gcn, out);
}

// round 7
// speedup vs baseline: 3.7112x; 1.1235x over previous
#include <cuda_runtime.h>
#include <cuda_bf16.h>
#include <cstdint>
#include <math.h>

#define N_NODES 30000
#define E_MAX   480000
#define ET_MAX  (E_MAX + N_NODES)
#define F_IN    1280
#define HEADS   4
#define CH      128
#define HC      512
#define HID     64

// ---------------- scratch ----------------
__device__ float g_h[(size_t)N_NODES * HC];
__device__ float g_out1[(size_t)N_NODES * HC];
__device__ float g_asrc[N_NODES * HEADS];
__device__ float g_adst[N_NODES * HEADS];
__device__ float g_alpha[(size_t)ET_MAX * HEADS];
__device__ float g_h2[(size_t)N_NODES * HID];
__device__ float g_dinv[N_NODES];
__device__ float g_colsum[HC];
__device__ float g_colsum2[HC];
__device__ float g_scale[HC];
__device__ float g_shift[HC];
// CSR
__device__ int   g_cnt[N_NODES];
__device__ int   g_off[N_NODES + 1];
__device__ int   g_esrc[ET_MAX];
__device__ float g_ewc[ET_MAX];
// pre-split bf16 operands for GEMM1
__device__ __nv_bfloat16 g_ah[(size_t)N_NODES * F_IN];
__device__ __nv_bfloat16 g_al[(size_t)N_NODES * F_IN];
__device__ __nv_bfloat16 g_bh[(size_t)HC * F_IN];   // B^T: [n][k]
__device__ __nv_bfloat16 g_bl[(size_t)HC * F_IN];
// scan partials
#define SCAN_BLOCKS 120
#define SCAN_CHUNK  ((N_NODES + SCAN_BLOCKS - 1) / SCAN_BLOCKS)
__device__ int g_bsum[SCAN_BLOCKS];

// ---------------- init ----------------
__global__ void k_init() {
    int i = blockIdx.x * blockDim.x + threadIdx.x;
    if (i < N_NODES) g_cnt[i] = 0;
    if (i < HC) { g_colsum[i] = 0.0f; g_colsum2[i] = 0.0f; }
}

// ---------------- split kernels ----------------
__global__ void k_split_a(const float* __restrict__ X) {
    size_t i = (size_t)blockIdx.x * blockDim.x + threadIdx.x;
    if (i * 4 >= (size_t)N_NODES * F_IN) return;
    float4 v = ((const float4*)X)[i];
    __nv_bfloat16 h0 = __float2bfloat16(v.x), h1 = __float2bfloat16(v.y);
    __nv_bfloat16 h2 = __float2bfloat16(v.z), h3 = __float2bfloat16(v.w);
    __nv_bfloat16 l0 = __float2bfloat16(v.x - __bfloat162float(h0));
    __nv_bfloat16 l1 = __float2bfloat16(v.y - __bfloat162float(h1));
    __nv_bfloat16 l2 = __float2bfloat16(v.z - __bfloat162float(h2));
    __nv_bfloat16 l3 = __float2bfloat16(v.w - __bfloat162float(h3));
    ((__nv_bfloat162*)g_ah)[i * 2 + 0] = __nv_bfloat162(h0, h1);
    ((__nv_bfloat162*)g_ah)[i * 2 + 1] = __nv_bfloat162(h2, h3);
    ((__nv_bfloat162*)g_al)[i * 2 + 0] = __nv_bfloat162(l0, l1);
    ((__nv_bfloat162*)g_al)[i * 2 + 1] = __nv_bfloat162(l2, l3);
}

__global__ void k_split_bt(const float* __restrict__ W) {
    int idx = blockIdx.x * blockDim.x + threadIdx.x;
    if (idx >= F_IN * HC) return;
    int k = idx >> 9, n = idx & (HC - 1);
    float v = W[idx];
    __nv_bfloat16 h = __float2bfloat16(v);
    __nv_bfloat16 l = __float2bfloat16(v - __bfloat162float(h));
    g_bh[(size_t)n * F_IN + k] = h;
    g_bl[(size_t)n * F_IN + k] = l;
}

// ========== GEMM1: bf16-split mma.sync, 128x128 tiles, 2 CTAs/SM ==========
#define BM 128
#define BN 128
#define BK 32
#define SA 40
#define A_ST   (BM * SA)                 // 5120 bf16
#define B_ST   (BN * SA)                 // 5120 bf16
#define STAGE_ELEMS (2 * A_ST + 2 * B_ST)   // 20480 bf16 (Ah,Al,Bh,Bl)
#define NSTAGE 2
#define GEMM1_SMEM (NSTAGE * STAGE_ELEMS * 2)   // 81920 bytes

__device__ __forceinline__ void mma16816(float* c, const unsigned* a, unsigned b0, unsigned b1) {
    asm volatile(
        "mma.sync.aligned.m16n8k16.row.col.f32.bf16.bf16.f32 "
        "{%0,%1,%2,%3}, {%4,%5,%6,%7}, {%8,%9}, {%0,%1,%2,%3};\n"
        : "+f"(c[0]), "+f"(c[1]), "+f"(c[2]), "+f"(c[3])
        : "r"(a[0]), "r"(a[1]), "r"(a[2]), "r"(a[3]), "r"(b0), "r"(b1));
}

__device__ __forceinline__ void ldsm4(unsigned* r, const __nv_bfloat16* p) {
    unsigned a = (unsigned)__cvta_generic_to_shared(p);
    asm volatile("ldmatrix.sync.aligned.m8n8.x4.shared.b16 {%0,%1,%2,%3}, [%4];\n"
                 : "=r"(r[0]), "=r"(r[1]), "=r"(r[2]), "=r"(r[3]) : "r"(a));
}

__device__ __forceinline__ void cpa16(void* dst, const void* src, int sz) {
    unsigned d = (unsigned)__cvta_generic_to_shared(dst);
    asm volatile("cp.async.ca.shared.global [%0], [%1], 16, %2;\n"
                 :: "r"(d), "l"(src), "r"(sz));
}

__global__ void __launch_bounds__(256, 2)
k_gemm1() {
    extern __shared__ __nv_bfloat16 sm[];

    int tid  = threadIdx.x;
    int warp = tid >> 5, lane = tid & 31;
    int row0 = blockIdx.y * BM, col0 = blockIdx.x * BN;
    int wm = (warp >> 1) * 32, wn = (warp & 1) * 64;

    float acc[2][8][4];
#pragma unroll
    for (int t = 0; t < 2; t++)
#pragma unroll
        for (int n = 0; n < 8; n++)
#pragma unroll
            for (int j = 0; j < 4; j++) acc[t][n][j] = 0.0f;

    // global load maps: 128 rows x 4 chunks of 16B; each thread 2 rows (r, r+64)
    int lrow = tid >> 2, lchk = tid & 3;
    int gr0 = row0 + lrow, gr1 = row0 + lrow + 64;
    int asz0 = (gr0 < N_NODES) ? 16 : 0;
    int asz1 = (gr1 < N_NODES) ? 16 : 0;
    size_t asrc0 = (size_t)min(gr0, N_NODES - 1) * F_IN + lchk * 8;
    size_t asrc1 = (size_t)min(gr1, N_NODES - 1) * F_IN + lchk * 8;
    size_t bsrc0 = (size_t)(col0 + lrow) * F_IN + lchk * 8;
    size_t bsrc1 = (size_t)(col0 + lrow + 64) * F_IN + lchk * 8;
    int sA0 = lrow * SA + lchk * 8, sA1 = (lrow + 64) * SA + lchk * 8;

    const int NIT = F_IN / BK;   // 40

    __nv_bfloat16* st[NSTAGE];
    st[0] = sm;
    st[1] = sm + STAGE_ELEMS;

    // ldmatrix per-lane address components (same as round-4 verified layout)
    int aRow = lane & 15;
    int aK   = (lane >> 4) << 3;
    int bRow = ((lane >> 4) << 3) + (lane & 7);
    int bK   = ((lane >> 3) & 1) << 3;

    // prologue: issue tile 0
    {
        __nv_bfloat16* s = st[0];
        cpa16(s + sA0,               g_ah + asrc0, asz0);
        cpa16(s + sA1,               g_ah + asrc1, asz1);
        cpa16(s + A_ST + sA0,        g_al + asrc0, asz0);
        cpa16(s + A_ST + sA1,        g_al + asrc1, asz1);
        cpa16(s + 2*A_ST + sA0,        g_bh + bsrc0, 16);
        cpa16(s + 2*A_ST + sA1,        g_bh + bsrc1, 16);
        cpa16(s + 2*A_ST + B_ST + sA0, g_bl + bsrc0, 16);
        cpa16(s + 2*A_ST + B_ST + sA1, g_bl + bsrc1, 16);
        asm volatile("cp.async.commit_group;\n");
    }

    for (int it = 0; it < NIT; it++) {
        if (it + 1 < NIT) {
            int k0 = (it + 1) * BK;
            __nv_bfloat16* s = st[(it + 1) & 1];
            cpa16(s + sA0,               g_ah + asrc0 + k0, asz0);
            cpa16(s + sA1,               g_ah + asrc1 + k0, asz1);
            cpa16(s + A_ST + sA0,        g_al + asrc0 + k0, asz0);
            cpa16(s + A_ST + sA1,        g_al + asrc1 + k0, asz1);
            cpa16(s + 2*A_ST + sA0,        g_bh + bsrc0 + k0, 16);
            cpa16(s + 2*A_ST + sA1,        g_bh + bsrc1 + k0, 16);
            cpa16(s + 2*A_ST + B_ST + sA0, g_bl + bsrc0 + k0, 16);
            cpa16(s + 2*A_ST + B_ST + sA1, g_bl + bsrc1 + k0, 16);
        }
        asm volatile("cp.async.commit_group;\n");
        asm volatile("cp.async.wait_group 1;\n");
        __syncthreads();

        const __nv_bfloat16* pAh = st[it & 1];
        const __nv_bfloat16* pAl = pAh + A_ST;
        const __nv_bfloat16* pBh = pAh + 2 * A_ST;
        const __nv_bfloat16* pBl = pBh + B_ST;

#pragma unroll
        for (int kk = 0; kk < BK; kk += 16) {
            unsigned ah[2][4], al[2][4];
            ldsm4(ah[0], pAh + (wm +  0 + aRow) * SA + kk + aK);
            ldsm4(ah[1], pAh + (wm + 16 + aRow) * SA + kk + aK);
            ldsm4(al[0], pAl + (wm +  0 + aRow) * SA + kk + aK);
            ldsm4(al[1], pAl + (wm + 16 + aRow) * SA + kk + aK);
#pragma unroll
            for (int p = 0; p < 4; p++) {
                unsigned bh[4], bl[4];
                ldsm4(bh, pBh + (wn + p * 16 + bRow) * SA + kk + bK);
                ldsm4(bl, pBl + (wn + p * 16 + bRow) * SA + kk + bK);
                int n0 = 2 * p, n1 = 2 * p + 1;
                mma16816(acc[0][n0], ah[0], bh[0], bh[1]);
                mma16816(acc[1][n0], ah[1], bh[0], bh[1]);
                mma16816(acc[0][n0], al[0], bh[0], bh[1]);
                mma16816(acc[1][n0], al[1], bh[0], bh[1]);
                mma16816(acc[0][n0], ah[0], bl[0], bl[1]);
                mma16816(acc[1][n0], ah[1], bl[0], bl[1]);
                mma16816(acc[0][n1], ah[0], bh[2], bh[3]);
                mma16816(acc[1][n1], ah[1], bh[2], bh[3]);
                mma16816(acc[0][n1], al[0], bh[2], bh[3]);
                mma16816(acc[1][n1], al[1], bh[2], bh[3]);
                mma16816(acc[0][n1], ah[0], bl[2], bl[3]);
                mma16816(acc[1][n1], ah[1], bl[2], bl[3]);
            }
        }
        __syncthreads();
    }

    // epilogue
    int g = lane >> 2, tig = lane & 3;
#pragma unroll
    for (int t = 0; t < 2; t++) {
        int r0 = row0 + wm + t * 16 + g;
#pragma unroll
        for (int n = 0; n < 8; n++) {
            int cc = col0 + wn + n * 8 + tig * 2;
            if (r0 < N_NODES)
                *(float2*)&g_h[(size_t)r0 * HC + cc] = make_float2(acc[t][n][0], acc[t][n][1]);
            if (r0 + 8 < N_NODES)
                *(float2*)&g_h[(size_t)(r0 + 8) * HC + cc] = make_float2(acc[t][n][2], acc[t][n][3]);
        }
    }
}

// ---------------- attention dots ----------------
__global__ void k_att(const float* __restrict__ att_src, const float* __restrict__ att_dst) {
    int gw   = (blockIdx.x * blockDim.x + threadIdx.x) >> 5;
    int lane = threadIdx.x & 31;
    if (gw >= N_NODES * HEADS) return;
    int n = gw >> 2, hd = gw & 3;
    float4 hv = *(const float4*)&g_h[(size_t)n * HC + hd * CH + lane * 4];
    float4 sv = *(const float4*)&att_src[hd * CH + lane * 4];
    float4 dv = *(const float4*)&att_dst[hd * CH + lane * 4];
    float vs = hv.x * sv.x + hv.y * sv.y + hv.z * sv.z + hv.w * sv.w;
    float vd = hv.x * dv.x + hv.y * dv.y + hv.z * dv.z + hv.w * dv.w;
#pragma unroll
    for (int o = 16; o > 0; o >>= 1) {
        vs += __shfl_down_sync(0xFFFFFFFFu, vs, o);
        vd += __shfl_down_sync(0xFFFFFFFFu, vd, o);
    }
    if (lane == 0) { g_asrc[gw] = vs; g_adst[gw] = vd; }
}

// ---------------- CSR build ----------------
__global__ void k_count(const int* __restrict__ ei, int E) {
    int e = blockIdx.x * blockDim.x + threadIdx.x;
    int ET = E + N_NODES;
    if (e >= ET) return;
    int d = (e < E) ? ei[E + e] : (e - E);
    atomicAdd(&g_cnt[d], 1);
}

__global__ void k_scan1() {
    __shared__ int red[8];
    int b = blockIdx.x, t = threadIdx.x;
    int lo = b * SCAN_CHUNK, hi = min(lo + SCAN_CHUNK, N_NODES);
    int s = 0;
    for (int i = lo + t; i < hi; i += 256) s += g_cnt[i];
#pragma unroll
    for (int o = 16; o > 0; o >>= 1) s += __shfl_xor_sync(0xFFFFFFFFu, s, o);
    if ((t & 31) == 0) red[t >> 5] = s;
    __syncthreads();
    if (t == 0) {
        int tot = 0;
#pragma unroll
        for (int i = 0; i < 8; i++) tot += red[i];
        g_bsum[b] = tot;
    }
}

__global__ void k_scan2() {
    __shared__ int sh[128];
    int t = threadIdx.x;
    int v = (t < SCAN_BLOCKS) ? g_bsum[t] : 0;
    sh[t] = v;
    __syncthreads();
#pragma unroll
    for (int o = 1; o < 128; o <<= 1) {
        int x = (t >= o) ? sh[t - o] : 0;
        __syncthreads();
        sh[t] += x;
        __syncthreads();
    }
    if (t < SCAN_BLOCKS) g_bsum[t] = sh[t] - v;
    if (t == 127) g_off[N_NODES] = sh[127];
}

__global__ void k_scan3() {
    __shared__ int sh[256];
    int b = blockIdx.x, t = threadIdx.x;
    int lo = b * SCAN_CHUNK;
    int i = lo + t;
    int v = (t < SCAN_CHUNK && i < N_NODES) ? g_cnt[i] : 0;
    sh[t] = v;
    __syncthreads();
#pragma unroll
    for (int o = 1; o < 256; o <<= 1) {
        int x = (t >= o) ? sh[t - o] : 0;
        __syncthreads();
        sh[t] += x;
        __syncthreads();
    }
    if (t < SCAN_CHUNK && i < N_NODES) {
        g_off[i] = g_bsum[b] + sh[t] - v;
        g_cnt[i] = 0;
    }
}

__global__ void k_fill(const int* __restrict__ ei, const float* __restrict__ ew, int E) {
    int e = blockIdx.x * blockDim.x + threadIdx.x;
    int ET = E + N_NODES;
    if (e >= ET) return;
    int s, d; float w;
    if (e < E) { s = ei[e]; d = ei[E + e]; w = ew[e]; }
    else       { s = d = e - E; w = 1.0f; }
    int slot = g_off[d] + atomicAdd(&g_cnt[d], 1);
    g_esrc[slot] = s;
    g_ewc[slot]  = w;
}

// ---------------- fused segment softmax + weighted degree ----------------
__global__ void k_softmax() {
    int d    = (blockIdx.x * blockDim.x + threadIdx.x) >> 5;
    int lane = threadIdx.x & 31;
    if (d >= N_NODES) return;
    int beg = g_off[d], end = g_off[d + 1];
    int cnt = end - beg;
    float4 ad = *(const float4*)&g_adst[d * 4];

    float mx0 = -1e30f, mx1 = -1e30f, mx2 = -1e30f, mx3 = -1e30f;
    float degw = 0.0f;

    if (cnt <= 32) {
        int i = beg + lane;
        bool act = lane < cnt;
        float l0 = -1e30f, l1 = -1e30f, l2 = -1e30f, l3 = -1e30f;
        if (act) {
            int s = g_esrc[i];
            float4 as = *(const float4*)&g_asrc[s * 4];
            l0 = as.x + ad.x; l1 = as.y + ad.y; l2 = as.z + ad.z; l3 = as.w + ad.w;
            l0 = l0 > 0.f ? l0 : 0.2f * l0;
            l1 = l1 > 0.f ? l1 : 0.2f * l1;
            l2 = l2 > 0.f ? l2 : 0.2f * l2;
            l3 = l3 > 0.f ? l3 : 0.2f * l3;
            degw = g_ewc[i];
        }
        mx0 = l0; mx1 = l1; mx2 = l2; mx3 = l3;
#pragma unroll
        for (int o = 16; o > 0; o >>= 1) {
            mx0 = fmaxf(mx0, __shfl_xor_sync(0xFFFFFFFFu, mx0, o));
            mx1 = fmaxf(mx1, __shfl_xor_sync(0xFFFFFFFFu, mx1, o));
            mx2 = fmaxf(mx2, __shfl_xor_sync(0xFFFFFFFFu, mx2, o));
            mx3 = fmaxf(mx3, __shfl_xor_sync(0xFFFFFFFFu, mx3, o));
            degw += __shfl_xor_sync(0xFFFFFFFFu, degw, o);
        }
        float e0 = act ? __expf(l0 - mx0) : 0.f;
        float e1 = act ? __expf(l1 - mx1) : 0.f;
        float e2 = act ? __expf(l2 - mx2) : 0.f;
        float e3 = act ? __expf(l3 - mx3) : 0.f;
        float s0 = e0, s1 = e1, s2 = e2, s3 = e3;
#pragma unroll
        for (int o = 16; o > 0; o >>= 1) {
            s0 += __shfl_xor_sync(0xFFFFFFFFu, s0, o);
            s1 += __shfl_xor_sync(0xFFFFFFFFu, s1, o);
            s2 += __shfl_xor_sync(0xFFFFFFFFu, s2, o);
            s3 += __shfl_xor_sync(0xFFFFFFFFu, s3, o);
        }
        if (act) {
            float4 al = make_float4(e0 / (s0 + 1e-16f), e1 / (s1 + 1e-16f),
                                    e2 / (s2 + 1e-16f), e3 / (s3 + 1e-16f));
            *(float4*)&g_alpha[(size_t)i * 4] = al;
        }
    } else {
        for (int i = beg + lane; i < end; i += 32) {
            int s = g_esrc[i];
            float4 as = *(const float4*)&g_asrc[s * 4];
            float l0 = as.x + ad.x, l1 = as.y + ad.y, l2 = as.z + ad.z, l3 = as.w + ad.w;
            l0 = l0 > 0.f ? l0 : 0.2f * l0;
            l1 = l1 > 0.f ? l1 : 0.2f * l1;
            l2 = l2 > 0.f ? l2 : 0.2f * l2;
            l3 = l3 > 0.f ? l3 : 0.2f * l3;
            *(float4*)&g_alpha[(size_t)i * 4] = make_float4(l0, l1, l2, l3);
            mx0 = fmaxf(mx0, l0); mx1 = fmaxf(mx1, l1);
            mx2 = fmaxf(mx2, l2); mx3 = fmaxf(mx3, l3);
            degw += g_ewc[i];
        }
#pragma unroll
        for (int o = 16; o > 0; o >>= 1) {
            mx0 = fmaxf(mx0, __shfl_xor_sync(0xFFFFFFFFu, mx0, o));
            mx1 = fmaxf(mx1, __shfl_xor_sync(0xFFFFFFFFu, mx1, o));
            mx2 = fmaxf(mx2, __shfl_xor_sync(0xFFFFFFFFu, mx2, o));
            mx3 = fmaxf(mx3, __shfl_xor_sync(0xFFFFFFFFu, mx3, o));
            degw += __shfl_xor_sync(0xFFFFFFFFu, degw, o);
        }
        float s0 = 0.f, s1 = 0.f, s2 = 0.f, s3 = 0.f;
        for (int i = beg + lane; i < end; i += 32) {
            float4 l = *(const float4*)&g_alpha[(size_t)i * 4];
            float e0 = __expf(l.x - mx0), e1 = __expf(l.y - mx1);
            float e2 = __expf(l.z - mx2), e3 = __expf(l.w - mx3);
            *(float4*)&g_alpha[(size_t)i * 4] = make_float4(e0, e1, e2, e3);
            s0 += e0; s1 += e1; s2 += e2; s3 += e3;
        }
#pragma unroll
        for (int o = 16; o > 0; o >>= 1) {
            s0 += __shfl_xor_sync(0xFFFFFFFFu, s0, o);
            s1 += __shfl_xor_sync(0xFFFFFFFFu, s1, o);
            s2 += __shfl_xor_sync(0xFFFFFFFFu, s2, o);
            s3 += __shfl_xor_sync(0xFFFFFFFFu, s3, o);
        }
        float r0 = 1.f / (s0 + 1e-16f), r1 = 1.f / (s1 + 1e-16f);
        float r2 = 1.f / (s2 + 1e-16f), r3 = 1.f / (s3 + 1e-16f);
        for (int i = beg + lane; i < end; i += 32) {
            float4 l = *(const float4*)&g_alpha[(size_t)i * 4];
            *(float4*)&g_alpha[(size_t)i * 4] = make_float4(l.x * r0, l.y * r1, l.z * r2, l.w * r3);
        }
    }
    if (lane == 0) g_dinv[d] = degw > 0.f ? rsqrtf(degw) : 0.0f;
}

// ---------------- GAT aggregation ----------------
__global__ void __launch_bounds__(128)
k_aggregate(const float* __restrict__ b_gat) {
    int d = blockIdx.x;
    int tid = threadIdx.x;
    int head = tid >> 5;
    int c = tid * 4;
    float4 acc = *(const float4*)&b_gat[c];
    int beg = g_off[d], end = g_off[d + 1];
    int i = beg;
    for (; i + 1 < end; i += 2) {
        int s0 = g_esrc[i], s1 = g_esrc[i + 1];
        float a0 = g_alpha[(size_t)i * 4 + head];
        float a1 = g_alpha[(size_t)(i + 1) * 4 + head];
        float4 v0 = *(const float4*)&g_h[(size_t)s0 * HC + c];
        float4 v1 = *(const float4*)&g_h[(size_t)s1 * HC + c];
        acc.x = fmaf(v0.x, a0, acc.x); acc.y = fmaf(v0.y, a0, acc.y);
        acc.z = fmaf(v0.z, a0, acc.z); acc.w = fmaf(v0.w, a0, acc.w);
        acc.x = fmaf(v1.x, a1, acc.x); acc.y = fmaf(v1.y, a1, acc.y);
        acc.z = fmaf(v1.z, a1, acc.z); acc.w = fmaf(v1.w, a1, acc.w);
    }
    if (i < end) {
        int s0 = g_esrc[i];
        float a0 = g_alpha[(size_t)i * 4 + head];
        float4 v0 = *(const float4*)&g_h[(size_t)s0 * HC + c];
        acc.x = fmaf(v0.x, a0, acc.x); acc.y = fmaf(v0.y, a0, acc.y);
        acc.z = fmaf(v0.z, a0, acc.z); acc.w = fmaf(v0.w, a0, acc.w);
    }
    *(float4*)&g_out1[(size_t)d * HC + c] = acc;
}

// ---------------- BN stats ----------------
__global__ void k_bnstats() {
    int col = threadIdx.x;
    float s = 0.f, s2 = 0.f;
    for (int r = blockIdx.x; r < N_NODES; r += gridDim.x) {
        float v = g_out1[(size_t)r * HC + col];
        s += v; s2 += v * v;
    }
    atomicAdd(&g_colsum[col], s);
    atomicAdd(&g_colsum2[col], s2);
}

__global__ void k_bnfinal(const float* __restrict__ gamma, const float* __restrict__ beta) {
    int c = blockIdx.x * blockDim.x + threadIdx.x;
    if (c >= HC) return;
    float mean = g_colsum[c] * (1.0f / N_NODES);
    float var  = g_colsum2[c] * (1.0f / N_NODES) - mean * mean;
    float sc = gamma[c] * rsqrtf(var + 1e-5f);
    g_scale[c] = sc;
    g_shift[c] = beta[c] - mean * sc;
}

// ---------------- GEMM2 ----------------
__global__ void k_gemm2(const float* __restrict__ W) {
    __shared__ float As[16][64];
    __shared__ float Bs[16][64];
    int tid  = threadIdx.x;
    int row0 = blockIdx.x * 64;
    int arow = tid >> 2, acol = (tid & 3) * 4;
    int brow = tid >> 4, bcol = (tid & 15) * 4;
    int ty = tid >> 4, tx = tid & 15;

    float acc[4][4];
#pragma unroll
    for (int i = 0; i < 4; i++)
#pragma unroll
        for (int j = 0; j < 4; j++) acc[i][j] = 0.0f;

    for (int k0 = 0; k0 < HC; k0 += 16) {
        float4 av = make_float4(0.f, 0.f, 0.f, 0.f);
        int ar = row0 + arow;
        if (ar < N_NODES)
            av = *(const float4*)&g_out1[(size_t)ar * HC + k0 + acol];
        int kc = k0 + acol;
        av.x = fmaxf(fmaf(av.x, g_scale[kc + 0], g_shift[kc + 0]), 0.0f);
        av.y = fmaxf(fmaf(av.y, g_scale[kc + 1], g_shift[kc + 1]), 0.0f);
        av.z = fmaxf(fmaf(av.z, g_scale[kc + 2], g_shift[kc + 2]), 0.0f);
        av.w = fmaxf(fmaf(av.w, g_scale[kc + 3], g_shift[kc + 3]), 0.0f);
        As[acol + 0][arow] = av.x;
        As[acol + 1][arow] = av.y;
        As[acol + 2][arow] = av.z;
        As[acol + 3][arow] = av.w;
        float4 bv = *(const float4*)&W[(size_t)(k0 + brow) * HID + bcol];
        *(float4*)&Bs[brow][bcol] = bv;
        __syncthreads();
#pragma unroll
        for (int kk = 0; kk < 16; kk++) {
            float a4[4], b4[4];
#pragma unroll
            for (int i = 0; i < 4; i++) a4[i] = As[kk][ty * 4 + i];
#pragma unroll
            for (int j = 0; j < 4; j++) b4[j] = Bs[kk][tx * 4 + j];
#pragma unroll
            for (int i = 0; i < 4; i++)
#pragma unroll
                for (int j = 0; j < 4; j++) acc[i][j] = fmaf(a4[i], b4[j], acc[i][j]);
        }
        __syncthreads();
    }
#pragma unroll
    for (int i = 0; i < 4; i++) {
        int r = row0 + ty * 4 + i;
        if (r >= N_NODES) continue;
        float4 v = make_float4(acc[i][0], acc[i][1], acc[i][2], acc[i][3]);
        *(float4*)&g_h2[(size_t)r * HID + tx * 4] = v;
    }
}

// ---------------- GCN gather ----------------
__global__ void k_gcn(const float* __restrict__ b_gcn, float* __restrict__ out) {
    int d    = (blockIdx.x * blockDim.x + threadIdx.x) >> 5;
    int lane = threadIdx.x & 31;
    if (d >= N_NODES) return;
    float dinv_d = g_dinv[d];
    float2 acc = *(const float2*)&b_gcn[lane * 2];
    int beg = g_off[d], end = g_off[d + 1];
    int i = beg;
    for (; i + 1 < end; i += 2) {
        int s0 = g_esrc[i], s1 = g_esrc[i + 1];
        float n0 = g_dinv[s0] * g_ewc[i] * dinv_d;
        float n1 = g_dinv[s1] * g_ewc[i + 1] * dinv_d;
        float2 v0 = *(const float2*)&g_h2[(size_t)s0 * HID + lane * 2];
        float2 v1 = *(const float2*)&g_h2[(size_t)s1 * HID + lane * 2];
        acc.x = fmaf(v0.x, n0, acc.x); acc.y = fmaf(v0.y, n0, acc.y);
        acc.x = fmaf(v1.x, n1, acc.x); acc.y = fmaf(v1.y, n1, acc.y);
    }
    if (i < end) {
        int s0 = g_esrc[i];
        float n0 = g_dinv[s0] * g_ewc[i] * dinv_d;
        float2 v0 = *(const float2*)&g_h2[(size_t)s0 * HID + lane * 2];
        acc.x = fmaf(v0.x, n0, acc.x); acc.y = fmaf(v0.y, n0, acc.y);
    }
    *(float2*)&out[(size_t)d * HID + lane * 2] = acc;
}

// ---------------- launch ----------------
extern "C" void kernel_launch(void* const* d_in, const int* in_sizes, int n_in,
                              void* d_out, int out_size) {
    const float* x       = (const float*)d_in[0];
    const int*   ei      = (const int*)  d_in[1];
    const float* ew      = (const float*)d_in[2];
    const float* W_gat   = (const float*)d_in[3];
    const float* att_src = (const float*)d_in[4];
    const float* att_dst = (const float*)d_in[5];
    const float* b_gat   = (const float*)d_in[6];
    const float* gamma   = (const float*)d_in[7];
    const float* beta    = (const float*)d_in[8];
    const float* W_gcn   = (const float*)d_in[9];
    const float* b_gcn   = (const float*)d_in[10];
    float* out = (float*)d_out;

    int E  = in_sizes[1] / 2;
    int ET = E + N_NODES;

    static bool attr_set = false;
    if (!attr_set) {
        cudaFuncSetAttribute(k_gemm1, cudaFuncAttributeMaxDynamicSharedMemorySize, GEMM1_SMEM);
        attr_set = true;
    }

    k_init<<<(N_NODES + 255) / 256, 256>>>();
    k_split_a<<<((N_NODES * (F_IN / 4)) + 255) / 256, 256>>>(x);
    k_split_bt<<<(F_IN * HC + 255) / 256, 256>>>(W_gat);

    dim3 g1(HC / BN, (N_NODES + BM - 1) / BM);   // (4, 235)
    k_gemm1<<<g1, 256, GEMM1_SMEM>>>();

    k_count<<<(ET + 255) / 256, 256>>>(ei, E);
    k_scan1<<<SCAN_BLOCKS, 256>>>();
    k_scan2<<<1, 128>>>();
    k_scan3<<<SCAN_BLOCKS, 256>>>();
    k_fill<<<(ET + 255) / 256, 256>>>(ei, ew, E);

    k_att<<<(N_NODES * HEADS * 32 + 255) / 256, 256>>>(att_src, att_dst);
    k_softmax<<<(N_NODES * 32 + 255) / 256, 256>>>();
    k_aggregate<<<N_NODES, 128>>>(b_gat);

    k_bnstats<<<240, 512>>>();
    k_bnfinal<<<2, 256>>>(gamma, beta);

    k_gemm2<<<(N_NODES + 63) / 64, 256>>>(W_gcn);
    k_gcn<<<(N_NODES * 32 + 255) / 256, 256>>>(b_gcn, out);
}

// round 8
// speedup vs baseline: 5.2771x; 1.4219x over previous
#include <cuda_runtime.h>
#include <cuda_fp16.h>
#include <cstdint>
#include <math.h>

#define N_NODES 30000
#define E_MAX   480000
#define ET_MAX  (E_MAX + N_NODES)
#define F_IN    1280
#define HEADS   4
#define CH      128
#define HC      512
#define HID     64

// ---------------- scratch ----------------
__device__ float g_h[(size_t)N_NODES * HC];
__device__ float g_out1[(size_t)N_NODES * HC];
__device__ float g_asrc[N_NODES * HEADS];
__device__ float g_adst[N_NODES * HEADS];
__device__ float g_alpha[(size_t)ET_MAX * HEADS];
__device__ float g_h2[(size_t)N_NODES * HID];
__device__ float g_dinv[N_NODES];
__device__ float g_colsum[HC];
__device__ float g_colsum2[HC];
__device__ float g_scale[HC];
__device__ float g_shift[HC];
// CSR
__device__ int   g_cnt[N_NODES];
__device__ int   g_off[N_NODES + 1];
__device__ int   g_esrc[ET_MAX];
__device__ float g_ewc[ET_MAX];
// fp16 operands for GEMM1
__device__ __half g_af[(size_t)N_NODES * F_IN];
__device__ __half g_bf[(size_t)HC * F_IN];   // B^T: [n][k]
// scan partials
#define SCAN_BLOCKS 120
#define SCAN_CHUNK  ((N_NODES + SCAN_BLOCKS - 1) / SCAN_BLOCKS)
__device__ int g_bsum[SCAN_BLOCKS];

// ---------------- init ----------------
__global__ void k_init() {
    int i = blockIdx.x * blockDim.x + threadIdx.x;
    if (i < N_NODES) g_cnt[i] = 0;
    if (i < HC) { g_colsum[i] = 0.0f; g_colsum2[i] = 0.0f; }
}

// ---------------- convert kernels ----------------
__global__ void k_conv_a(const float* __restrict__ X) {
    size_t i = (size_t)blockIdx.x * blockDim.x + threadIdx.x;
    if (i * 4 >= (size_t)N_NODES * F_IN) return;
    float4 v = ((const float4*)X)[i];
    __half2* o = (__half2*)g_af;
    o[i * 2 + 0] = __floats2half2_rn(v.x, v.y);
    o[i * 2 + 1] = __floats2half2_rn(v.z, v.w);
}

__global__ void k_conv_bt(const float* __restrict__ W) {
    int idx = blockIdx.x * blockDim.x + threadIdx.x;
    if (idx >= F_IN * HC) return;
    int k = idx >> 9, n = idx & (HC - 1);
    g_bf[(size_t)n * F_IN + k] = __float2half(W[idx]);
}

// ========== GEMM1: plain fp16 mma.sync, 128x128 tiles, BK=64, 2 CTAs/SM ==========
#define BM 128
#define BN 128
#define BK 64
#define SA 72                          // padded row stride (fp16 elems)
#define A_ST   (BM * SA)               // 9216
#define B_ST   (BN * SA)               // 9216
#define STAGE_ELEMS (A_ST + B_ST)      // 18432 fp16
#define NSTAGE 2
#define GEMM1_SMEM (NSTAGE * STAGE_ELEMS * 2)   // 73728 bytes

__device__ __forceinline__ void mma16816(float* c, const unsigned* a, unsigned b0, unsigned b1) {
    asm volatile(
        "mma.sync.aligned.m16n8k16.row.col.f32.f16.f16.f32 "
        "{%0,%1,%2,%3}, {%4,%5,%6,%7}, {%8,%9}, {%0,%1,%2,%3};\n"
        : "+f"(c[0]), "+f"(c[1]), "+f"(c[2]), "+f"(c[3])
        : "r"(a[0]), "r"(a[1]), "r"(a[2]), "r"(a[3]), "r"(b0), "r"(b1));
}

__device__ __forceinline__ void ldsm4(unsigned* r, const __half* p) {
    unsigned a = (unsigned)__cvta_generic_to_shared(p);
    asm volatile("ldmatrix.sync.aligned.m8n8.x4.shared.b16 {%0,%1,%2,%3}, [%4];\n"
                 : "=r"(r[0]), "=r"(r[1]), "=r"(r[2]), "=r"(r[3]) : "r"(a));
}

__device__ __forceinline__ void cpa16(void* dst, const void* src, int sz) {
    unsigned d = (unsigned)__cvta_generic_to_shared(dst);
    asm volatile("cp.async.ca.shared.global [%0], [%1], 16, %2;\n"
                 :: "r"(d), "l"(src), "r"(sz));
}

__global__ void __launch_bounds__(256, 2)
k_gemm1() {
    extern __shared__ __half sm[];

    int tid  = threadIdx.x;
    int warp = tid >> 5, lane = tid & 31;
    int row0 = blockIdx.y * BM, col0 = blockIdx.x * BN;
    int wm = (warp >> 1) * 32, wn = (warp & 1) * 64;

    float acc[2][8][4];
#pragma unroll
    for (int t = 0; t < 2; t++)
#pragma unroll
        for (int n = 0; n < 8; n++)
#pragma unroll
            for (int j = 0; j < 4; j++) acc[t][n][j] = 0.0f;

    // load maps: tile is 128 rows x 64 fp16 = 8 chunks(16B)/row.
    // 2 threads per row, 4 chunks each.
    int lrow = tid >> 1, lch0 = (tid & 1) * 4;
    int gra = row0 + lrow;
    int asz = (gra < N_NODES) ? 16 : 0;
    size_t asrc = (size_t)min(gra, N_NODES - 1) * F_IN + lch0 * 8;
    size_t bsrc = (size_t)(col0 + lrow) * F_IN + lch0 * 8;
    int sOff = lrow * SA + lch0 * 8;

    const int NIT = F_IN / BK;   // 20

    __half* st[NSTAGE];
    st[0] = sm;
    st[1] = sm + STAGE_ELEMS;

    // ldmatrix per-lane address components
    int aRow = lane & 15;
    int aK   = (lane >> 4) << 3;
    int bRow = ((lane >> 4) << 3) + (lane & 7);
    int bK   = ((lane >> 3) & 1) << 3;

    // prologue
    {
        __half* s = st[0];
#pragma unroll
        for (int c = 0; c < 4; c++) {
            cpa16(s + sOff + c * 8,        g_af + asrc + c * 8, asz);
            cpa16(s + A_ST + sOff + c * 8, g_bf + bsrc + c * 8, 16);
        }
        asm volatile("cp.async.commit_group;\n");
    }

    for (int it = 0; it < NIT; it++) {
        if (it + 1 < NIT) {
            int k0 = (it + 1) * BK;
            __half* s = st[(it + 1) & 1];
#pragma unroll
            for (int c = 0; c < 4; c++) {
                cpa16(s + sOff + c * 8,        g_af + asrc + k0 + c * 8, asz);
                cpa16(s + A_ST + sOff + c * 8, g_bf + bsrc + k0 + c * 8, 16);
            }
        }
        asm volatile("cp.async.commit_group;\n");
        asm volatile("cp.async.wait_group 1;\n");
        __syncthreads();

        const __half* pA = st[it & 1];
        const __half* pB = pA + A_ST;

#pragma unroll
        for (int kk = 0; kk < BK; kk += 16) {
            unsigned af[2][4];
            ldsm4(af[0], pA + (wm +  0 + aRow) * SA + kk + aK);
            ldsm4(af[1], pA + (wm + 16 + aRow) * SA + kk + aK);
#pragma unroll
            for (int p = 0; p < 4; p++) {
                unsigned bf[4];
                ldsm4(bf, pB + (wn + p * 16 + bRow) * SA + kk + bK);
                int n0 = 2 * p, n1 = 2 * p + 1;
                mma16816(acc[0][n0], af[0], bf[0], bf[1]);
                mma16816(acc[1][n0], af[1], bf[0], bf[1]);
                mma16816(acc[0][n1], af[0], bf[2], bf[3]);
                mma16816(acc[1][n1], af[1], bf[2], bf[3]);
            }
        }
        __syncthreads();
    }

    // epilogue
    int g = lane >> 2, tig = lane & 3;
#pragma unroll
    for (int t = 0; t < 2; t++) {
        int r0 = row0 + wm + t * 16 + g;
#pragma unroll
        for (int n = 0; n < 8; n++) {
            int cc = col0 + wn + n * 8 + tig * 2;
            if (r0 < N_NODES)
                *(float2*)&g_h[(size_t)r0 * HC + cc] = make_float2(acc[t][n][0], acc[t][n][1]);
            if (r0 + 8 < N_NODES)
                *(float2*)&g_h[(size_t)(r0 + 8) * HC + cc] = make_float2(acc[t][n][2], acc[t][n][3]);
        }
    }
}

// ---------------- attention dots ----------------
__global__ void k_att(const float* __restrict__ att_src, const float* __restrict__ att_dst) {
    int gw   = (blockIdx.x * blockDim.x + threadIdx.x) >> 5;
    int lane = threadIdx.x & 31;
    if (gw >= N_NODES * HEADS) return;
    int n = gw >> 2, hd = gw & 3;
    float4 hv = *(const float4*)&g_h[(size_t)n * HC + hd * CH + lane * 4];
    float4 sv = *(const float4*)&att_src[hd * CH + lane * 4];
    float4 dv = *(const float4*)&att_dst[hd * CH + lane * 4];
    float vs = hv.x * sv.x + hv.y * sv.y + hv.z * sv.z + hv.w * sv.w;
    float vd = hv.x * dv.x + hv.y * dv.y + hv.z * dv.z + hv.w * dv.w;
#pragma unroll
    for (int o = 16; o > 0; o >>= 1) {
        vs += __shfl_down_sync(0xFFFFFFFFu, vs, o);
        vd += __shfl_down_sync(0xFFFFFFFFu, vd, o);
    }
    if (lane == 0) { g_asrc[gw] = vs; g_adst[gw] = vd; }
}

// ---------------- CSR build ----------------
__global__ void k_count(const int* __restrict__ ei, int E) {
    int e = blockIdx.x * blockDim.x + threadIdx.x;
    int ET = E + N_NODES;
    if (e >= ET) return;
    int d = (e < E) ? ei[E + e] : (e - E);
    atomicAdd(&g_cnt[d], 1);
}

__global__ void k_scan1() {
    __shared__ int red[8];
    int b = blockIdx.x, t = threadIdx.x;
    int lo = b * SCAN_CHUNK, hi = min(lo + SCAN_CHUNK, N_NODES);
    int s = 0;
    for (int i = lo + t; i < hi; i += 256) s += g_cnt[i];
#pragma unroll
    for (int o = 16; o > 0; o >>= 1) s += __shfl_xor_sync(0xFFFFFFFFu, s, o);
    if ((t & 31) == 0) red[t >> 5] = s;
    __syncthreads();
    if (t == 0) {
        int tot = 0;
#pragma unroll
        for (int i = 0; i < 8; i++) tot += red[i];
        g_bsum[b] = tot;
    }
}

__global__ void k_scan2() {
    __shared__ int sh[128];
    int t = threadIdx.x;
    int v = (t < SCAN_BLOCKS) ? g_bsum[t] : 0;
    sh[t] = v;
    __syncthreads();
#pragma unroll
    for (int o = 1; o < 128; o <<= 1) {
        int x = (t >= o) ? sh[t - o] : 0;
        __syncthreads();
        sh[t] += x;
        __syncthreads();
    }
    if (t < SCAN_BLOCKS) g_bsum[t] = sh[t] - v;
    if (t == 127) g_off[N_NODES] = sh[127];
}

__global__ void k_scan3() {
    __shared__ int sh[256];
    int b = blockIdx.x, t = threadIdx.x;
    int lo = b * SCAN_CHUNK;
    int i = lo + t;
    int v = (t < SCAN_CHUNK && i < N_NODES) ? g_cnt[i] : 0;
    sh[t] = v;
    __syncthreads();
#pragma unroll
    for (int o = 1; o < 256; o <<= 1) {
        int x = (t >= o) ? sh[t - o] : 0;
        __syncthreads();
        sh[t] += x;
        __syncthreads();
    }
    if (t < SCAN_CHUNK && i < N_NODES) {
        g_off[i] = g_bsum[b] + sh[t] - v;
        g_cnt[i] = 0;
    }
}

__global__ void k_fill(const int* __restrict__ ei, const float* __restrict__ ew, int E) {
    int e = blockIdx.x * blockDim.x + threadIdx.x;
    int ET = E + N_NODES;
    if (e >= ET) return;
    int s, d; float w;
    if (e < E) { s = ei[e]; d = ei[E + e]; w = ew[e]; }
    else       { s = d = e - E; w = 1.0f; }
    int slot = g_off[d] + atomicAdd(&g_cnt[d], 1);
    g_esrc[slot] = s;
    g_ewc[slot]  = w;
}

// ---------------- fused segment softmax + weighted degree ----------------
__global__ void k_softmax() {
    int d    = (blockIdx.x * blockDim.x + threadIdx.x) >> 5;
    int lane = threadIdx.x & 31;
    if (d >= N_NODES) return;
    int beg = g_off[d], end = g_off[d + 1];
    int cnt = end - beg;
    float4 ad = *(const float4*)&g_adst[d * 4];

    float mx0 = -1e30f, mx1 = -1e30f, mx2 = -1e30f, mx3 = -1e30f;
    float degw = 0.0f;

    if (cnt <= 32) {
        int i = beg + lane;
        bool act = lane < cnt;
        float l0 = -1e30f, l1 = -1e30f, l2 = -1e30f, l3 = -1e30f;
        if (act) {
            int s = g_esrc[i];
            float4 as = *(const float4*)&g_asrc[s * 4];
            l0 = as.x + ad.x; l1 = as.y + ad.y; l2 = as.z + ad.z; l3 = as.w + ad.w;
            l0 = l0 > 0.f ? l0 : 0.2f * l0;
            l1 = l1 > 0.f ? l1 : 0.2f * l1;
            l2 = l2 > 0.f ? l2 : 0.2f * l2;
            l3 = l3 > 0.f ? l3 : 0.2f * l3;
            degw = g_ewc[i];
        }
        mx0 = l0; mx1 = l1; mx2 = l2; mx3 = l3;
#pragma unroll
        for (int o = 16; o > 0; o >>= 1) {
            mx0 = fmaxf(mx0, __shfl_xor_sync(0xFFFFFFFFu, mx0, o));
            mx1 = fmaxf(mx1, __shfl_xor_sync(0xFFFFFFFFu, mx1, o));
            mx2 = fmaxf(mx2, __shfl_xor_sync(0xFFFFFFFFu, mx2, o));
            mx3 = fmaxf(mx3, __shfl_xor_sync(0xFFFFFFFFu, mx3, o));
            degw += __shfl_xor_sync(0xFFFFFFFFu, degw, o);
        }
        float e0 = act ? __expf(l0 - mx0) : 0.f;
        float e1 = act ? __expf(l1 - mx1) : 0.f;
        float e2 = act ? __expf(l2 - mx2) : 0.f;
        float e3 = act ? __expf(l3 - mx3) : 0.f;
        float s0 = e0, s1 = e1, s2 = e2, s3 = e3;
#pragma unroll
        for (int o = 16; o > 0; o >>= 1) {
            s0 += __shfl_xor_sync(0xFFFFFFFFu, s0, o);
            s1 += __shfl_xor_sync(0xFFFFFFFFu, s1, o);
            s2 += __shfl_xor_sync(0xFFFFFFFFu, s2, o);
            s3 += __shfl_xor_sync(0xFFFFFFFFu, s3, o);
        }
        if (act) {
            float4 al = make_float4(e0 / (s0 + 1e-16f), e1 / (s1 + 1e-16f),
                                    e2 / (s2 + 1e-16f), e3 / (s3 + 1e-16f));
            *(float4*)&g_alpha[(size_t)i * 4] = al;
        }
    } else {
        for (int i = beg + lane; i < end; i += 32) {
            int s = g_esrc[i];
            float4 as = *(const float4*)&g_asrc[s * 4];
            float l0 = as.x + ad.x, l1 = as.y + ad.y, l2 = as.z + ad.z, l3 = as.w + ad.w;
            l0 = l0 > 0.f ? l0 : 0.2f * l0;
            l1 = l1 > 0.f ? l1 : 0.2f * l1;
            l2 = l2 > 0.f ? l2 : 0.2f * l2;
            l3 = l3 > 0.f ? l3 : 0.2f * l3;
            *(float4*)&g_alpha[(size_t)i * 4] = make_float4(l0, l1, l2, l3);
            mx0 = fmaxf(mx0, l0); mx1 = fmaxf(mx1, l1);
            mx2 = fmaxf(mx2, l2); mx3 = fmaxf(mx3, l3);
            degw += g_ewc[i];
        }
#pragma unroll
        for (int o = 16; o > 0; o >>= 1) {
            mx0 = fmaxf(mx0, __shfl_xor_sync(0xFFFFFFFFu, mx0, o));
            mx1 = fmaxf(mx1, __shfl_xor_sync(0xFFFFFFFFu, mx1, o));
            mx2 = fmaxf(mx2, __shfl_xor_sync(0xFFFFFFFFu, mx2, o));
            mx3 = fmaxf(mx3, __shfl_xor_sync(0xFFFFFFFFu, mx3, o));
            degw += __shfl_xor_sync(0xFFFFFFFFu, degw, o);
        }
        float s0 = 0.f, s1 = 0.f, s2 = 0.f, s3 = 0.f;
        for (int i = beg + lane; i < end; i += 32) {
            float4 l = *(const float4*)&g_alpha[(size_t)i * 4];
            float e0 = __expf(l.x - mx0), e1 = __expf(l.y - mx1);
            float e2 = __expf(l.z - mx2), e3 = __expf(l.w - mx3);
            *(float4*)&g_alpha[(size_t)i * 4] = make_float4(e0, e1, e2, e3);
            s0 += e0; s1 += e1; s2 += e2; s3 += e3;
        }
#pragma unroll
        for (int o = 16; o > 0; o >>= 1) {
            s0 += __shfl_xor_sync(0xFFFFFFFFu, s0, o);
            s1 += __shfl_xor_sync(0xFFFFFFFFu, s1, o);
            s2 += __shfl_xor_sync(0xFFFFFFFFu, s2, o);
            s3 += __shfl_xor_sync(0xFFFFFFFFu, s3, o);
        }
        float r0 = 1.f / (s0 + 1e-16f), r1 = 1.f / (s1 + 1e-16f);
        float r2 = 1.f / (s2 + 1e-16f), r3 = 1.f / (s3 + 1e-16f);
        for (int i = beg + lane; i < end; i += 32) {
            float4 l = *(const float4*)&g_alpha[(size_t)i * 4];
            *(float4*)&g_alpha[(size_t)i * 4] = make_float4(l.x * r0, l.y * r1, l.z * r2, l.w * r3);
        }
    }
    if (lane == 0) g_dinv[d] = degw > 0.f ? rsqrtf(degw) : 0.0f;
}

// ---------------- GAT aggregation ----------------
__global__ void __launch_bounds__(128)
k_aggregate(const float* __restrict__ b_gat) {
    int d = blockIdx.x;
    int tid = threadIdx.x;
    int head = tid >> 5;
    int c = tid * 4;
    float4 acc = *(const float4*)&b_gat[c];
    int beg = g_off[d], end = g_off[d + 1];
    int i = beg;
    for (; i + 1 < end; i += 2) {
        int s0 = g_esrc[i], s1 = g_esrc[i + 1];
        float a0 = g_alpha[(size_t)i * 4 + head];
        float a1 = g_alpha[(size_t)(i + 1) * 4 + head];
        float4 v0 = *(const float4*)&g_h[(size_t)s0 * HC + c];
        float4 v1 = *(const float4*)&g_h[(size_t)s1 * HC + c];
        acc.x = fmaf(v0.x, a0, acc.x); acc.y = fmaf(v0.y, a0, acc.y);
        acc.z = fmaf(v0.z, a0, acc.z); acc.w = fmaf(v0.w, a0, acc.w);
        acc.x = fmaf(v1.x, a1, acc.x); acc.y = fmaf(v1.y, a1, acc.y);
        acc.z = fmaf(v1.z, a1, acc.z); acc.w = fmaf(v1.w, a1, acc.w);
    }
    if (i < end) {
        int s0 = g_esrc[i];
        float a0 = g_alpha[(size_t)i * 4 + head];
        float4 v0 = *(const float4*)&g_h[(size_t)s0 * HC + c];
        acc.x = fmaf(v0.x, a0, acc.x); acc.y = fmaf(v0.y, a0, acc.y);
        acc.z = fmaf(v0.z, a0, acc.z); acc.w = fmaf(v0.w, a0, acc.w);
    }
    *(float4*)&g_out1[(size_t)d * HC + c] = acc;
}

// ---------------- BN stats ----------------
__global__ void k_bnstats() {
    int col = threadIdx.x;
    float s = 0.f, s2 = 0.f;
    for (int r = blockIdx.x; r < N_NODES; r += gridDim.x) {
        float v = g_out1[(size_t)r * HC + col];
        s += v; s2 += v * v;
    }
    atomicAdd(&g_colsum[col], s);
    atomicAdd(&g_colsum2[col], s2);
}

__global__ void k_bnfinal(const float* __restrict__ gamma, const float* __restrict__ beta) {
    int c = blockIdx.x * blockDim.x + threadIdx.x;
    if (c >= HC) return;
    float mean = g_colsum[c] * (1.0f / N_NODES);
    float var  = g_colsum2[c] * (1.0f / N_NODES) - mean * mean;
    float sc = gamma[c] * rsqrtf(var + 1e-5f);
    g_scale[c] = sc;
    g_shift[c] = beta[c] - mean * sc;
}

// ---------------- GEMM2 ----------------
__global__ void k_gemm2(const float* __restrict__ W) {
    __shared__ float As[16][64];
    __shared__ float Bs[16][64];
    int tid  = threadIdx.x;
    int row0 = blockIdx.x * 64;
    int arow = tid >> 2, acol = (tid & 3) * 4;
    int brow = tid >> 4, bcol = (tid & 15) * 4;
    int ty = tid >> 4, tx = tid & 15;

    float acc[4][4];
#pragma unroll
    for (int i = 0; i < 4; i++)
#pragma unroll
        for (int j = 0; j < 4; j++) acc[i][j] = 0.0f;

    for (int k0 = 0; k0 < HC; k0 += 16) {
        float4 av = make_float4(0.f, 0.f, 0.f, 0.f);
        int ar = row0 + arow;
        if (ar < N_NODES)
            av = *(const float4*)&g_out1[(size_t)ar * HC + k0 + acol];
        int kc = k0 + acol;
        av.x = fmaxf(fmaf(av.x, g_scale[kc + 0], g_shift[kc + 0]), 0.0f);
        av.y = fmaxf(fmaf(av.y, g_scale[kc + 1], g_shift[kc + 1]), 0.0f);
        av.z = fmaxf(fmaf(av.z, g_scale[kc + 2], g_shift[kc + 2]), 0.0f);
        av.w = fmaxf(fmaf(av.w, g_scale[kc + 3], g_shift[kc + 3]), 0.0f);
        As[acol + 0][arow] = av.x;
        As[acol + 1][arow] = av.y;
        As[acol + 2][arow] = av.z;
        As[acol + 3][arow] = av.w;
        float4 bv = *(const float4*)&W[(size_t)(k0 + brow) * HID + bcol];
        *(float4*)&Bs[brow][bcol] = bv;
        __syncthreads();
#pragma unroll
        for (int kk = 0; kk < 16; kk++) {
            float a4[4], b4[4];
#pragma unroll
            for (int i = 0; i < 4; i++) a4[i] = As[kk][ty * 4 + i];
#pragma unroll
            for (int j = 0; j < 4; j++) b4[j] = Bs[kk][tx * 4 + j];
#pragma unroll
            for (int i = 0; i < 4; i++)
#pragma unroll
                for (int j = 0; j < 4; j++) acc[i][j] = fmaf(a4[i], b4[j], acc[i][j]);
        }
        __syncthreads();
    }
#pragma unroll
    for (int i = 0; i < 4; i++) {
        int r = row0 + ty * 4 + i;
        if (r >= N_NODES) continue;
        float4 v = make_float4(acc[i][0], acc[i][1], acc[i][2], acc[i][3]);
        *(float4*)&g_h2[(size_t)r * HID + tx * 4] = v;
    }
}

// ---------------- GCN gather ----------------
__global__ void k_gcn(const float* __restrict__ b_gcn, float* __restrict__ out) {
    int d    = (blockIdx.x * blockDim.x + threadIdx.x) >> 5;
    int lane = threadIdx.x & 31;
    if (d >= N_NODES) return;
    float dinv_d = g_dinv[d];
    float2 acc = *(const float2*)&b_gcn[lane * 2];
    int beg = g_off[d], end = g_off[d + 1];
    int i = beg;
    for (; i + 1 < end; i += 2) {
        int s0 = g_esrc[i], s1 = g_esrc[i + 1];
        float n0 = g_dinv[s0] * g_ewc[i] * dinv_d;
        float n1 = g_dinv[s1] * g_ewc[i + 1] * dinv_d;
        float2 v0 = *(const float2*)&g_h2[(size_t)s0 * HID + lane * 2];
        float2 v1 = *(const float2*)&g_h2[(size_t)s1 * HID + lane * 2];
        acc.x = fmaf(v0.x, n0, acc.x); acc.y = fmaf(v0.y, n0, acc.y);
        acc.x = fmaf(v1.x, n1, acc.x); acc.y = fmaf(v1.y, n1, acc.y);
    }
    if (i < end) {
        int s0 = g_esrc[i];
        float n0 = g_dinv[s0] * g_ewc[i] * dinv_d;
        float2 v0 = *(const float2*)&g_h2[(size_t)s0 * HID + lane * 2];
        acc.x = fmaf(v0.x, n0, acc.x); acc.y = fmaf(v0.y, n0, acc.y);
    }
    *(float2*)&out[(size_t)d * HID + lane * 2] = acc;
}

// ---------------- launch ----------------
extern "C" void kernel_launch(void* const* d_in, const int* in_sizes, int n_in,
                              void* d_out, int out_size) {
    const float* x       = (const float*)d_in[0];
    const int*   ei      = (const int*)  d_in[1];
    const float* ew      = (const float*)d_in[2];
    const float* W_gat   = (const float*)d_in[3];
    const float* att_src = (const float*)d_in[4];
    const float* att_dst = (const float*)d_in[5];
    const float* b_gat   = (const float*)d_in[6];
    const float* gamma   = (const float*)d_in[7];
    const float* beta    = (const float*)d_in[8];
    const float* W_gcn   = (const float*)d_in[9];
    const float* b_gcn   = (const float*)d_in[10];
    float* out = (float*)d_out;

    int E  = in_sizes[1] / 2;
    int ET = E + N_NODES;

    static bool attr_set = false;
    if (!attr_set) {
        cudaFuncSetAttribute(k_gemm1, cudaFuncAttributeMaxDynamicSharedMemorySize, GEMM1_SMEM);
        attr_set = true;
    }

    k_init<<<(N_NODES + 255) / 256, 256>>>();
    k_conv_a<<<((N_NODES * (F_IN / 4)) + 255) / 256, 256>>>(x);
    k_conv_bt<<<(F_IN * HC + 255) / 256, 256>>>(W_gat);

    dim3 g1(HC / BN, (N_NODES + BM - 1) / BM);   // (4, 235)
    k_gemm1<<<g1, 256, GEMM1_SMEM>>>();

    k_count<<<(ET + 255) / 256, 256>>>(ei, E);
    k_scan1<<<SCAN_BLOCKS, 256>>>();
    k_scan2<<<1, 128>>>();
    k_scan3<<<SCAN_BLOCKS, 256>>>();
    k_fill<<<(ET + 255) / 256, 256>>>(ei, ew, E);

    k_att<<<(N_NODES * HEADS * 32 + 255) / 256, 256>>>(att_src, att_dst);
    k_softmax<<<(N_NODES * 32 + 255) / 256, 256>>>();
    k_aggregate<<<N_NODES, 128>>>(b_gat);

    k_bnstats<<<240, 512>>>();
    k_bnfinal<<<2, 256>>>(gamma, beta);

    k_gemm2<<<(N_NODES + 63) / 64, 256>>>(W_gcn);
    k_gcn<<<(N_NODES * 32 + 255) / 256, 256>>>(b_gcn, out);
}

// round 9
// speedup vs baseline: 6.0360x; 1.1438x over previous
#include <cuda_runtime.h>
#include <cuda_fp16.h>
#include <cstdint>
#include <math.h>

#define N_NODES 30000
#define E_MAX   480000
#define ET_MAX  (E_MAX + N_NODES)
#define F_IN    1280
#define HEADS   4
#define CH      128
#define HC      512
#define HID     64

// ---------------- scratch ----------------
__device__ __half g_hh[(size_t)N_NODES * HC];    // GAT features (fp16)
__device__ float g_out1[(size_t)N_NODES * HC];
__device__ __half g_xr[(size_t)N_NODES * HC];    // relu(bn(out1)) fp16
__device__ float g_asrc[N_NODES * HEADS];
__device__ float g_adst[N_NODES * HEADS];
__device__ float g_alpha[(size_t)ET_MAX * HEADS];
__device__ float g_h2[(size_t)N_NODES * HID];
__device__ float g_dinv[N_NODES];
__device__ float g_colsum[HC];
__device__ float g_colsum2[HC];
__device__ float g_scale[HC];
__device__ float g_shift[HC];
// CSR
__device__ int   g_cnt[N_NODES];
__device__ int   g_off[N_NODES + 1];
__device__ int   g_esrc[ET_MAX];
__device__ float g_ewc[ET_MAX];
// fp16 operands
__device__ __half g_af[(size_t)N_NODES * F_IN];
__device__ __half g_bf[(size_t)HC * F_IN];       // W_gat^T: [n][k]
__device__ __half g_wgf[(size_t)HID * HC];       // W_gcn^T: [n][k]
// scan partials
#define SCAN_BLOCKS 120
#define SCAN_CHUNK  ((N_NODES + SCAN_BLOCKS - 1) / SCAN_BLOCKS)
__device__ int g_bsum[SCAN_BLOCKS];

// ---------------- init ----------------
__global__ void k_init() {
    int i = blockIdx.x * blockDim.x + threadIdx.x;
    if (i < N_NODES) g_cnt[i] = 0;
    if (i < HC) { g_colsum[i] = 0.0f; g_colsum2[i] = 0.0f; }
}

// ---------------- convert kernels ----------------
__global__ void k_conv_a(const float* __restrict__ X) {
    size_t i = (size_t)blockIdx.x * blockDim.x + threadIdx.x;
    if (i * 4 >= (size_t)N_NODES * F_IN) return;
    float4 v = ((const float4*)X)[i];
    __half2* o = (__half2*)g_af;
    o[i * 2 + 0] = __floats2half2_rn(v.x, v.y);
    o[i * 2 + 1] = __floats2half2_rn(v.z, v.w);
}

__global__ void k_conv_bt(const float* __restrict__ W) {
    int idx = blockIdx.x * blockDim.x + threadIdx.x;
    if (idx >= F_IN * HC) return;
    int k = idx >> 9, n = idx & (HC - 1);
    g_bf[(size_t)n * F_IN + k] = __float2half(W[idx]);
}

__global__ void k_conv_wg(const float* __restrict__ W) {
    int idx = blockIdx.x * blockDim.x + threadIdx.x;
    if (idx >= HC * HID) return;
    int k = idx >> 6, n = idx & (HID - 1);
    g_wgf[(size_t)n * HC + k] = __float2half(W[idx]);
}

// BN + ReLU + fp16 convert (after bnfinal)
__global__ void k_conv_xr() {
    size_t i = (size_t)blockIdx.x * blockDim.x + threadIdx.x;
    if (i * 4 >= (size_t)N_NODES * HC) return;
    float4 v = ((const float4*)g_out1)[i];
    int kc = (int)((i * 4) & (HC - 1));
    v.x = fmaxf(fmaf(v.x, g_scale[kc + 0], g_shift[kc + 0]), 0.0f);
    v.y = fmaxf(fmaf(v.y, g_scale[kc + 1], g_shift[kc + 1]), 0.0f);
    v.z = fmaxf(fmaf(v.z, g_scale[kc + 2], g_shift[kc + 2]), 0.0f);
    v.w = fmaxf(fmaf(v.w, g_scale[kc + 3], g_shift[kc + 3]), 0.0f);
    __half2* o = (__half2*)g_xr;
    o[i * 2 + 0] = __floats2half2_rn(v.x, v.y);
    o[i * 2 + 1] = __floats2half2_rn(v.z, v.w);
}

// ========== shared mma helpers ==========
#define SA 72

__device__ __forceinline__ void mma16816(float* c, const unsigned* a, unsigned b0, unsigned b1) {
    asm volatile(
        "mma.sync.aligned.m16n8k16.row.col.f32.f16.f16.f32 "
        "{%0,%1,%2,%3}, {%4,%5,%6,%7}, {%8,%9}, {%0,%1,%2,%3};\n"
        : "+f"(c[0]), "+f"(c[1]), "+f"(c[2]), "+f"(c[3])
        : "r"(a[0]), "r"(a[1]), "r"(a[2]), "r"(a[3]), "r"(b0), "r"(b1));
}

__device__ __forceinline__ void ldsm4(unsigned* r, const __half* p) {
    unsigned a = (unsigned)__cvta_generic_to_shared(p);
    asm volatile("ldmatrix.sync.aligned.m8n8.x4.shared.b16 {%0,%1,%2,%3}, [%4];\n"
                 : "=r"(r[0]), "=r"(r[1]), "=r"(r[2]), "=r"(r[3]) : "r"(a));
}

__device__ __forceinline__ void cpa16(void* dst, const void* src, int sz) {
    unsigned d = (unsigned)__cvta_generic_to_shared(dst);
    asm volatile("cp.async.ca.shared.global [%0], [%1], 16, %2;\n"
                 :: "r"(d), "l"(src), "r"(sz));
}

// ========== GEMM1: fp16 mma, 128x128 tiles, BK=64, 2 CTAs/SM ==========
#define BM 128
#define BN 128
#define BK 64
#define A_ST   (BM * SA)
#define B_ST   (BN * SA)
#define STAGE_ELEMS (A_ST + B_ST)
#define GEMM1_SMEM (2 * STAGE_ELEMS * 2)

__global__ void __launch_bounds__(256, 2)
k_gemm1() {
    extern __shared__ __half sm[];

    int tid  = threadIdx.x;
    int warp = tid >> 5, lane = tid & 31;
    int row0 = blockIdx.y * BM, col0 = blockIdx.x * BN;
    int wm = (warp >> 1) * 32, wn = (warp & 1) * 64;

    float acc[2][8][4];
#pragma unroll
    for (int t = 0; t < 2; t++)
#pragma unroll
        for (int n = 0; n < 8; n++)
#pragma unroll
            for (int j = 0; j < 4; j++) acc[t][n][j] = 0.0f;

    int lrow = tid >> 1, lch0 = (tid & 1) * 4;
    int gra = row0 + lrow;
    int asz = (gra < N_NODES) ? 16 : 0;
    size_t asrc = (size_t)min(gra, N_NODES - 1) * F_IN + lch0 * 8;
    size_t bsrc = (size_t)(col0 + lrow) * F_IN + lch0 * 8;
    int sOff = lrow * SA + lch0 * 8;

    const int NIT = F_IN / BK;   // 20

    __half* st[2];
    st[0] = sm;
    st[1] = sm + STAGE_ELEMS;

    int aRow = lane & 15;
    int aK   = (lane >> 4) << 3;
    int bRow = ((lane >> 4) << 3) + (lane & 7);
    int bK   = ((lane >> 3) & 1) << 3;

    {
        __half* s = st[0];
#pragma unroll
        for (int c = 0; c < 4; c++) {
            cpa16(s + sOff + c * 8,        g_af + asrc + c * 8, asz);
            cpa16(s + A_ST + sOff + c * 8, g_bf + bsrc + c * 8, 16);
        }
        asm volatile("cp.async.commit_group;\n");
    }

    for (int it = 0; it < NIT; it++) {
        if (it + 1 < NIT) {
            int k0 = (it + 1) * BK;
            __half* s = st[(it + 1) & 1];
#pragma unroll
            for (int c = 0; c < 4; c++) {
                cpa16(s + sOff + c * 8,        g_af + asrc + k0 + c * 8, asz);
                cpa16(s + A_ST + sOff + c * 8, g_bf + bsrc + k0 + c * 8, 16);
            }
        }
        asm volatile("cp.async.commit_group;\n");
        asm volatile("cp.async.wait_group 1;\n");
        __syncthreads();

        const __half* pA = st[it & 1];
        const __half* pB = pA + A_ST;

#pragma unroll
        for (int kk = 0; kk < BK; kk += 16) {
            unsigned af[2][4];
            ldsm4(af[0], pA + (wm +  0 + aRow) * SA + kk + aK);
            ldsm4(af[1], pA + (wm + 16 + aRow) * SA + kk + aK);
#pragma unroll
            for (int p = 0; p < 4; p++) {
                unsigned bf[4];
                ldsm4(bf, pB + (wn + p * 16 + bRow) * SA + kk + bK);
                int n0 = 2 * p, n1 = 2 * p + 1;
                mma16816(acc[0][n0], af[0], bf[0], bf[1]);
                mma16816(acc[1][n0], af[1], bf[0], bf[1]);
                mma16816(acc[0][n1], af[0], bf[2], bf[3]);
                mma16816(acc[1][n1], af[1], bf[2], bf[3]);
            }
        }
        __syncthreads();
    }

    // epilogue -> fp16 g_hh
    int g = lane >> 2, tig = lane & 3;
#pragma unroll
    for (int t = 0; t < 2; t++) {
        int r0 = row0 + wm + t * 16 + g;
#pragma unroll
        for (int n = 0; n < 8; n++) {
            int cc = col0 + wn + n * 8 + tig * 2;
            if (r0 < N_NODES)
                *(__half2*)&g_hh[(size_t)r0 * HC + cc] = __floats2half2_rn(acc[t][n][0], acc[t][n][1]);
            if (r0 + 8 < N_NODES)
                *(__half2*)&g_hh[(size_t)(r0 + 8) * HC + cc] = __floats2half2_rn(acc[t][n][2], acc[t][n][3]);
        }
    }
}

// ========== GEMM2: fp16 mma, 128x64 tiles, BK=64, 2 CTAs/SM ==========
#define B2_ST  (64 * SA)
#define STAGE2 (A_ST + B2_ST)
#define GEMM2_SMEM (2 * STAGE2 * 2)

__global__ void __launch_bounds__(256, 2)
k_gemm2() {
    extern __shared__ __half sm[];

    int tid  = threadIdx.x;
    int warp = tid >> 5, lane = tid & 31;
    int row0 = blockIdx.x * BM;
    int wm = (warp >> 1) * 32, wn = (warp & 1) * 32;

    float acc[2][4][4];
#pragma unroll
    for (int t = 0; t < 2; t++)
#pragma unroll
        for (int n = 0; n < 4; n++)
#pragma unroll
            for (int j = 0; j < 4; j++) acc[t][n][j] = 0.0f;

    // A: 128 rows x 8 chunks; 2 threads/row, 4 chunks each
    int lrow = tid >> 1, lch0 = (tid & 1) * 4;
    int gra = row0 + lrow;
    int asz = (gra < N_NODES) ? 16 : 0;
    size_t asrc = (size_t)min(gra, N_NODES - 1) * HC + lch0 * 8;
    int sOffA = lrow * SA + lch0 * 8;
    // B: 64 rows x 8 chunks = 512 chunks; 2 chunks per thread
    int brow = tid >> 2, bch0 = (tid & 3) * 2;
    size_t bsrc = (size_t)brow * HC + bch0 * 8;
    int sOffB = brow * SA + bch0 * 8;

    const int NIT = HC / BK;   // 8

    __half* st[2];
    st[0] = sm;
    st[1] = sm + STAGE2;

    int aRow = lane & 15;
    int aK   = (lane >> 4) << 3;
    int bRow = ((lane >> 4) << 3) + (lane & 7);
    int bK   = ((lane >> 3) & 1) << 3;

    {
        __half* s = st[0];
#pragma unroll
        for (int c = 0; c < 4; c++)
            cpa16(s + sOffA + c * 8, g_xr + asrc + c * 8, asz);
#pragma unroll
        for (int c = 0; c < 2; c++)
            cpa16(s + A_ST + sOffB + c * 8, g_wgf + bsrc + c * 8, 16);
        asm volatile("cp.async.commit_group;\n");
    }

    for (int it = 0; it < NIT; it++) {
        if (it + 1 < NIT) {
            int k0 = (it + 1) * BK;
            __half* s = st[(it + 1) & 1];
#pragma unroll
            for (int c = 0; c < 4; c++)
                cpa16(s + sOffA + c * 8, g_xr + asrc + k0 + c * 8, asz);
#pragma unroll
            for (int c = 0; c < 2; c++)
                cpa16(s + A_ST + sOffB + c * 8, g_wgf + bsrc + k0 + c * 8, 16);
        }
        asm volatile("cp.async.commit_group;\n");
        asm volatile("cp.async.wait_group 1;\n");
        __syncthreads();

        const __half* pA = st[it & 1];
        const __half* pB = pA + A_ST;

#pragma unroll
        for (int kk = 0; kk < BK; kk += 16) {
            unsigned af[2][4];
            ldsm4(af[0], pA + (wm +  0 + aRow) * SA + kk + aK);
            ldsm4(af[1], pA + (wm + 16 + aRow) * SA + kk + aK);
#pragma unroll
            for (int p = 0; p < 2; p++) {
                unsigned bf[4];
                ldsm4(bf, pB + (wn + p * 16 + bRow) * SA + kk + bK);
                int n0 = 2 * p, n1 = 2 * p + 1;
                mma16816(acc[0][n0], af[0], bf[0], bf[1]);
                mma16816(acc[1][n0], af[1], bf[0], bf[1]);
                mma16816(acc[0][n1], af[0], bf[2], bf[3]);
                mma16816(acc[1][n1], af[1], bf[2], bf[3]);
            }
        }
        __syncthreads();
    }

    int g = lane >> 2, tig = lane & 3;
#pragma unroll
    for (int t = 0; t < 2; t++) {
        int r0 = row0 + wm + t * 16 + g;
#pragma unroll
        for (int n = 0; n < 4; n++) {
            int cc = wn + n * 8 + tig * 2;
            if (r0 < N_NODES)
                *(float2*)&g_h2[(size_t)r0 * HID + cc] = make_float2(acc[t][n][0], acc[t][n][1]);
            if (r0 + 8 < N_NODES)
                *(float2*)&g_h2[(size_t)(r0 + 8) * HID + cc] = make_float2(acc[t][n][2], acc[t][n][3]);
        }
    }
}

// ---------------- attention dots (fp16 h) ----------------
__global__ void k_att(const float* __restrict__ att_src, const float* __restrict__ att_dst) {
    int gw   = (blockIdx.x * blockDim.x + threadIdx.x) >> 5;
    int lane = threadIdx.x & 31;
    if (gw >= N_NODES * HEADS) return;
    int n = gw >> 2, hd = gw & 3;
    const __half2* hp = (const __half2*)&g_hh[(size_t)n * HC + hd * CH + lane * 4];
    float2 h01 = __half22float2(hp[0]);
    float2 h23 = __half22float2(hp[1]);
    float4 sv = *(const float4*)&att_src[hd * CH + lane * 4];
    float4 dv = *(const float4*)&att_dst[hd * CH + lane * 4];
    float vs = h01.x * sv.x + h01.y * sv.y + h23.x * sv.z + h23.y * sv.w;
    float vd = h01.x * dv.x + h01.y * dv.y + h23.x * dv.z + h23.y * dv.w;
#pragma unroll
    for (int o = 16; o > 0; o >>= 1) {
        vs += __shfl_down_sync(0xFFFFFFFFu, vs, o);
        vd += __shfl_down_sync(0xFFFFFFFFu, vd, o);
    }
    if (lane == 0) { g_asrc[gw] = vs; g_adst[gw] = vd; }
}

// ---------------- CSR build ----------------
__global__ void k_count(const int* __restrict__ ei, int E) {
    int e = blockIdx.x * blockDim.x + threadIdx.x;
    int ET = E + N_NODES;
    if (e >= ET) return;
    int d = (e < E) ? ei[E + e] : (e - E);
    atomicAdd(&g_cnt[d], 1);
}

__global__ void k_scan1() {
    __shared__ int red[8];
    int b = blockIdx.x, t = threadIdx.x;
    int lo = b * SCAN_CHUNK, hi = min(lo + SCAN_CHUNK, N_NODES);
    int s = 0;
    for (int i = lo + t; i < hi; i += 256) s += g_cnt[i];
#pragma unroll
    for (int o = 16; o > 0; o >>= 1) s += __shfl_xor_sync(0xFFFFFFFFu, s, o);
    if ((t & 31) == 0) red[t >> 5] = s;
    __syncthreads();
    if (t == 0) {
        int tot = 0;
#pragma unroll
        for (int i = 0; i < 8; i++) tot += red[i];
        g_bsum[b] = tot;
    }
}

__global__ void k_scan2() {
    __shared__ int sh[128];
    int t = threadIdx.x;
    int v = (t < SCAN_BLOCKS) ? g_bsum[t] : 0;
    sh[t] = v;
    __syncthreads();
#pragma unroll
    for (int o = 1; o < 128; o <<= 1) {
        int x = (t >= o) ? sh[t - o] : 0;
        __syncthreads();
        sh[t] += x;
        __syncthreads();
    }
    if (t < SCAN_BLOCKS) g_bsum[t] = sh[t] - v;
    if (t == 127) g_off[N_NODES] = sh[127];
}

__global__ void k_scan3() {
    __shared__ int sh[256];
    int b = blockIdx.x, t = threadIdx.x;
    int lo = b * SCAN_CHUNK;
    int i = lo + t;
    int v = (t < SCAN_CHUNK && i < N_NODES) ? g_cnt[i] : 0;
    sh[t] = v;
    __syncthreads();
#pragma unroll
    for (int o = 1; o < 256; o <<= 1) {
        int x = (t >= o) ? sh[t - o] : 0;
        __syncthreads();
        sh[t] += x;
        __syncthreads();
    }
    if (t < SCAN_CHUNK && i < N_NODES) {
        g_off[i] = g_bsum[b] + sh[t] - v;
        g_cnt[i] = 0;
    }
}

__global__ void k_fill(const int* __restrict__ ei, const float* __restrict__ ew, int E) {
    int e = blockIdx.x * blockDim.x + threadIdx.x;
    int ET = E + N_NODES;
    if (e >= ET) return;
    int s, d; float w;
    if (e < E) { s = ei[e]; d = ei[E + e]; w = ew[e]; }
    else       { s = d = e - E; w = 1.0f; }
    int slot = g_off[d] + atomicAdd(&g_cnt[d], 1);
    g_esrc[slot] = s;
    g_ewc[slot]  = w;
}

// ---------------- fused segment softmax + weighted degree ----------------
__global__ void k_softmax() {
    int d    = (blockIdx.x * blockDim.x + threadIdx.x) >> 5;
    int lane = threadIdx.x & 31;
    if (d >= N_NODES) return;
    int beg = g_off[d], end = g_off[d + 1];
    int cnt = end - beg;
    float4 ad = *(const float4*)&g_adst[d * 4];

    float mx0 = -1e30f, mx1 = -1e30f, mx2 = -1e30f, mx3 = -1e30f;
    float degw = 0.0f;

    if (cnt <= 32) {
        int i = beg + lane;
        bool act = lane < cnt;
        float l0 = -1e30f, l1 = -1e30f, l2 = -1e30f, l3 = -1e30f;
        if (act) {
            int s = g_esrc[i];
            float4 as = *(const float4*)&g_asrc[s * 4];
            l0 = as.x + ad.x; l1 = as.y + ad.y; l2 = as.z + ad.z; l3 = as.w + ad.w;
            l0 = l0 > 0.f ? l0 : 0.2f * l0;
            l1 = l1 > 0.f ? l1 : 0.2f * l1;
            l2 = l2 > 0.f ? l2 : 0.2f * l2;
            l3 = l3 > 0.f ? l3 : 0.2f * l3;
            degw = g_ewc[i];
        }
        mx0 = l0; mx1 = l1; mx2 = l2; mx3 = l3;
#pragma unroll
        for (int o = 16; o > 0; o >>= 1) {
            mx0 = fmaxf(mx0, __shfl_xor_sync(0xFFFFFFFFu, mx0, o));
            mx1 = fmaxf(mx1, __shfl_xor_sync(0xFFFFFFFFu, mx1, o));
            mx2 = fmaxf(mx2, __shfl_xor_sync(0xFFFFFFFFu, mx2, o));
            mx3 = fmaxf(mx3, __shfl_xor_sync(0xFFFFFFFFu, mx3, o));
            degw += __shfl_xor_sync(0xFFFFFFFFu, degw, o);
        }
        float e0 = act ? __expf(l0 - mx0) : 0.f;
        float e1 = act ? __expf(l1 - mx1) : 0.f;
        float e2 = act ? __expf(l2 - mx2) : 0.f;
        float e3 = act ? __expf(l3 - mx3) : 0.f;
        float s0 = e0, s1 = e1, s2 = e2, s3 = e3;
#pragma unroll
        for (int o = 16; o > 0; o >>= 1) {
            s0 += __shfl_xor_sync(0xFFFFFFFFu, s0, o);
            s1 += __shfl_xor_sync(0xFFFFFFFFu, s1, o);
            s2 += __shfl_xor_sync(0xFFFFFFFFu, s2, o);
            s3 += __shfl_xor_sync(0xFFFFFFFFu, s3, o);
        }
        if (act) {
            float4 al = make_float4(e0 / (s0 + 1e-16f), e1 / (s1 + 1e-16f),
                                    e2 / (s2 + 1e-16f), e3 / (s3 + 1e-16f));
            *(float4*)&g_alpha[(size_t)i * 4] = al;
        }
    } else {
        for (int i = beg + lane; i < end; i += 32) {
            int s = g_esrc[i];
            float4 as = *(const float4*)&g_asrc[s * 4];
            float l0 = as.x + ad.x, l1 = as.y + ad.y, l2 = as.z + ad.z, l3 = as.w + ad.w;
            l0 = l0 > 0.f ? l0 : 0.2f * l0;
            l1 = l1 > 0.f ? l1 : 0.2f * l1;
            l2 = l2 > 0.f ? l2 : 0.2f * l2;
            l3 = l3 > 0.f ? l3 : 0.2f * l3;
            *(float4*)&g_alpha[(size_t)i * 4] = make_float4(l0, l1, l2, l3);
            mx0 = fmaxf(mx0, l0); mx1 = fmaxf(mx1, l1);
            mx2 = fmaxf(mx2, l2); mx3 = fmaxf(mx3, l3);
            degw += g_ewc[i];
        }
#pragma unroll
        for (int o = 16; o > 0; o >>= 1) {
            mx0 = fmaxf(mx0, __shfl_xor_sync(0xFFFFFFFFu, mx0, o));
            mx1 = fmaxf(mx1, __shfl_xor_sync(0xFFFFFFFFu, mx1, o));
            mx2 = fmaxf(mx2, __shfl_xor_sync(0xFFFFFFFFu, mx2, o));
            mx3 = fmaxf(mx3, __shfl_xor_sync(0xFFFFFFFFu, mx3, o));
            degw += __shfl_xor_sync(0xFFFFFFFFu, degw, o);
        }
        float s0 = 0.f, s1 = 0.f, s2 = 0.f, s3 = 0.f;
        for (int i = beg + lane; i < end; i += 32) {
            float4 l = *(const float4*)&g_alpha[(size_t)i * 4];
            float e0 = __expf(l.x - mx0), e1 = __expf(l.y - mx1);
            float e2 = __expf(l.z - mx2), e3 = __expf(l.w - mx3);
            *(float4*)&g_alpha[(size_t)i * 4] = make_float4(e0, e1, e2, e3);
            s0 += e0; s1 += e1; s2 += e2; s3 += e3;
        }
#pragma unroll
        for (int o = 16; o > 0; o >>= 1) {
            s0 += __shfl_xor_sync(0xFFFFFFFFu, s0, o);
            s1 += __shfl_xor_sync(0xFFFFFFFFu, s1, o);
            s2 += __shfl_xor_sync(0xFFFFFFFFu, s2, o);
            s3 += __shfl_xor_sync(0xFFFFFFFFu, s3, o);
        }
        float r0 = 1.f / (s0 + 1e-16f), r1 = 1.f / (s1 + 1e-16f);
        float r2 = 1.f / (s2 + 1e-16f), r3 = 1.f / (s3 + 1e-16f);
        for (int i = beg + lane; i < end; i += 32) {
            float4 l = *(const float4*)&g_alpha[(size_t)i * 4];
            *(float4*)&g_alpha[(size_t)i * 4] = make_float4(l.x * r0, l.y * r1, l.z * r2, l.w * r3);
        }
    }
    if (lane == 0) g_dinv[d] = degw > 0.f ? rsqrtf(degw) : 0.0f;
}

// ---------------- GAT aggregation (fp16 h, fp32 acc) ----------------
__global__ void __launch_bounds__(128)
k_aggregate(const float* __restrict__ b_gat) {
    int d = blockIdx.x;
    int tid = threadIdx.x;
    int head = tid >> 5;
    int c = tid * 4;
    float4 acc = *(const float4*)&b_gat[c];
    int beg = g_off[d], end = g_off[d + 1];
    int i = beg;
    for (; i + 1 < end; i += 2) {
        int s0 = g_esrc[i], s1 = g_esrc[i + 1];
        float a0 = g_alpha[(size_t)i * 4 + head];
        float a1 = g_alpha[(size_t)(i + 1) * 4 + head];
        const __half2* p0 = (const __half2*)&g_hh[(size_t)s0 * HC + c];
        const __half2* p1 = (const __half2*)&g_hh[(size_t)s1 * HC + c];
        float2 v0a = __half22float2(p0[0]), v0b = __half22float2(p0[1]);
        float2 v1a = __half22float2(p1[0]), v1b = __half22float2(p1[1]);
        acc.x = fmaf(v0a.x, a0, acc.x); acc.y = fmaf(v0a.y, a0, acc.y);
        acc.z = fmaf(v0b.x, a0, acc.z); acc.w = fmaf(v0b.y, a0, acc.w);
        acc.x = fmaf(v1a.x, a1, acc.x); acc.y = fmaf(v1a.y, a1, acc.y);
        acc.z = fmaf(v1b.x, a1, acc.z); acc.w = fmaf(v1b.y, a1, acc.w);
    }
    if (i < end) {
        int s0 = g_esrc[i];
        float a0 = g_alpha[(size_t)i * 4 + head];
        const __half2* p0 = (const __half2*)&g_hh[(size_t)s0 * HC + c];
        float2 v0a = __half22float2(p0[0]), v0b = __half22float2(p0[1]);
        acc.x = fmaf(v0a.x, a0, acc.x); acc.y = fmaf(v0a.y, a0, acc.y);
        acc.z = fmaf(v0b.x, a0, acc.z); acc.w = fmaf(v0b.y, a0, acc.w);
    }
    *(float4*)&g_out1[(size_t)d * HC + c] = acc;
}

// ---------------- BN stats ----------------
__global__ void k_bnstats() {
    int col = threadIdx.x;
    float s = 0.f, s2 = 0.f;
    for (int r = blockIdx.x; r < N_NODES; r += gridDim.x) {
        float v = g_out1[(size_t)r * HC + col];
        s += v; s2 += v * v;
    }
    atomicAdd(&g_colsum[col], s);
    atomicAdd(&g_colsum2[col], s2);
}

__global__ void k_bnfinal(const float* __restrict__ gamma, const float* __restrict__ beta) {
    int c = blockIdx.x * blockDim.x + threadIdx.x;
    if (c >= HC) return;
    float mean = g_colsum[c] * (1.0f / N_NODES);
    float var  = g_colsum2[c] * (1.0f / N_NODES) - mean * mean;
    float sc = gamma[c] * rsqrtf(var + 1e-5f);
    g_scale[c] = sc;
    g_shift[c] = beta[c] - mean * sc;
}

// ---------------- GCN gather ----------------
__global__ void k_gcn(const float* __restrict__ b_gcn, float* __restrict__ out) {
    int d    = (blockIdx.x * blockDim.x + threadIdx.x) >> 5;
    int lane = threadIdx.x & 31;
    if (d >= N_NODES) return;
    float dinv_d = g_dinv[d];
    float2 acc = *(const float2*)&b_gcn[lane * 2];
    int beg = g_off[d], end = g_off[d + 1];
    int i = beg;
    for (; i + 1 < end; i += 2) {
        int s0 = g_esrc[i], s1 = g_esrc[i + 1];
        float n0 = g_dinv[s0] * g_ewc[i] * dinv_d;
        float n1 = g_dinv[s1] * g_ewc[i + 1] * dinv_d;
        float2 v0 = *(const float2*)&g_h2[(size_t)s0 * HID + lane * 2];
        float2 v1 = *(const float2*)&g_h2[(size_t)s1 * HID + lane * 2];
        acc.x = fmaf(v0.x, n0, acc.x); acc.y = fmaf(v0.y, n0, acc.y);
        acc.x = fmaf(v1.x, n1, acc.x); acc.y = fmaf(v1.y, n1, acc.y);
    }
    if (i < end) {
        int s0 = g_esrc[i];
        float n0 = g_dinv[s0] * g_ewc[i] * dinv_d;
        float2 v0 = *(const float2*)&g_h2[(size_t)s0 * HID + lane * 2];
        acc.x = fmaf(v0.x, n0, acc.x); acc.y = fmaf(v0.y, n0, acc.y);
    }
    *(float2*)&out[(size_t)d * HID + lane * 2] = acc;
}

// ---------------- launch ----------------
extern "C" void kernel_launch(void* const* d_in, const int* in_sizes, int n_in,
                              void* d_out, int out_size) {
    const float* x       = (const float*)d_in[0];
    const int*   ei      = (const int*)  d_in[1];
    const float* ew      = (const float*)d_in[2];
    const float* W_gat   = (const float*)d_in[3];
    const float* att_src = (const float*)d_in[4];
    const float* att_dst = (const float*)d_in[5];
    const float* b_gat   = (const float*)d_in[6];
    const float* gamma   = (const float*)d_in[7];
    const float* beta    = (const float*)d_in[8];
    const float* W_gcn   = (const float*)d_in[9];
    const float* b_gcn   = (const float*)d_in[10];
    float* out = (float*)d_out;

    int E  = in_sizes[1] / 2;
    int ET = E + N_NODES;

    static bool attr_set = false;
    if (!attr_set) {
        cudaFuncSetAttribute(k_gemm1, cudaFuncAttributeMaxDynamicSharedMemorySize, GEMM1_SMEM);
        cudaFuncSetAttribute(k_gemm2, cudaFuncAttributeMaxDynamicSharedMemorySize, GEMM2_SMEM);
        attr_set = true;
    }

    k_init<<<(N_NODES + 255) / 256, 256>>>();
    k_conv_a<<<((N_NODES * (F_IN / 4)) + 255) / 256, 256>>>(x);
    k_conv_bt<<<(F_IN * HC + 255) / 256, 256>>>(W_gat);
    k_conv_wg<<<(HC * HID + 255) / 256, 256>>>(W_gcn);

    dim3 g1(HC / BN, (N_NODES + BM - 1) / BM);   // (4, 235)
    k_gemm1<<<g1, 256, GEMM1_SMEM>>>();

    k_count<<<(ET + 255) / 256, 256>>>(ei, E);
    k_scan1<<<SCAN_BLOCKS, 256>>>();
    k_scan2<<<1, 128>>>();
    k_scan3<<<SCAN_BLOCKS, 256>>>();
    k_fill<<<(ET + 255) / 256, 256>>>(ei, ew, E);

    k_att<<<(N_NODES * HEADS * 32 + 255) / 256, 256>>>(att_src, att_dst);
    k_softmax<<<(N_NODES * 32 + 255) / 256, 256>>>();
    k_aggregate<<<N_NODES, 128>>>(b_gat);

    k_bnstats<<<240, 512>>>();
    k_bnfinal<<<2, 256>>>(gamma, beta);
    k_conv_xr<<<((N_NODES * (HC / 4)) + 255) / 256, 256>>>();

    k_gemm2<<<(N_NODES + BM - 1) / BM, 256, GEMM2_SMEM>>>();
    k_gcn<<<(N_NODES * 32 + 255) / 256, 256>>>(b_gcn, out);
}

// round 10
// speedup vs baseline: 6.3310x; 1.0489x over previous
#include <cuda_runtime.h>
#include <cuda_fp16.h>
#include <cstdint>
#include <math.h>

#define N_NODES 30000
#define E_MAX   480000
#define ET_MAX  (E_MAX + N_NODES)
#define F_IN    1280
#define HEADS   4
#define CH      128
#define HC      512
#define HID     64

// ---------------- scratch ----------------
__device__ __half g_hh[(size_t)N_NODES * HC];    // GAT features (fp16)
__device__ float g_out1[(size_t)N_NODES * HC];
__device__ __half g_xr[(size_t)N_NODES * HC];    // relu(bn(out1)) fp16
__device__ float g_asrc[N_NODES * HEADS];
__device__ float g_adst[N_NODES * HEADS];
__device__ float g_alpha[(size_t)ET_MAX * HEADS];
__device__ float g_h2[(size_t)N_NODES * HID];
__device__ float g_dinv[N_NODES];
__device__ float g_colsum[HC];
__device__ float g_colsum2[HC];
__device__ float g_scale[HC];
__device__ float g_shift[HC];
// CSR
__device__ int   g_cnt[N_NODES];
__device__ int   g_off[N_NODES + 1];
__device__ int   g_esrc[ET_MAX];
__device__ float g_ewc[ET_MAX];
// fp16 operands
__device__ __half g_af[(size_t)N_NODES * F_IN];
__device__ __half g_bf[(size_t)HC * F_IN];       // W_gat^T: [n][k]
__device__ __half g_wgf[(size_t)HID * HC];       // W_gcn^T: [n][k]
// scan partials
#define SCAN_BLOCKS 120
#define SCAN_CHUNK  ((N_NODES + SCAN_BLOCKS - 1) / SCAN_BLOCKS)
__device__ int g_bsum[SCAN_BLOCKS];

// ---------------- init ----------------
__global__ void k_init() {
    int i = blockIdx.x * blockDim.x + threadIdx.x;
    if (i < N_NODES) g_cnt[i] = 0;
    if (i < HC) { g_colsum[i] = 0.0f; g_colsum2[i] = 0.0f; }
}

// ---------------- convert kernels ----------------
__global__ void k_conv_a(const float* __restrict__ X) {
    size_t i = (size_t)blockIdx.x * blockDim.x + threadIdx.x;
    if (i * 4 >= (size_t)N_NODES * F_IN) return;
    float4 v = ((const float4*)X)[i];
    __half2* o = (__half2*)g_af;
    o[i * 2 + 0] = __floats2half2_rn(v.x, v.y);
    o[i * 2 + 1] = __floats2half2_rn(v.z, v.w);
}

__global__ void k_conv_bt(const float* __restrict__ W) {
    int idx = blockIdx.x * blockDim.x + threadIdx.x;
    if (idx >= F_IN * HC) return;
    int k = idx >> 9, n = idx & (HC - 1);
    g_bf[(size_t)n * F_IN + k] = __float2half(W[idx]);
}

__global__ void k_conv_wg(const float* __restrict__ W) {
    int idx = blockIdx.x * blockDim.x + threadIdx.x;
    if (idx >= HC * HID) return;
    int k = idx >> 6, n = idx & (HID - 1);
    g_wgf[(size_t)n * HC + k] = __float2half(W[idx]);
}

// BN + ReLU + fp16 convert (after bnfinal)
__global__ void k_conv_xr() {
    size_t i = (size_t)blockIdx.x * blockDim.x + threadIdx.x;
    if (i * 4 >= (size_t)N_NODES * HC) return;
    float4 v = ((const float4*)g_out1)[i];
    int kc = (int)((i * 4) & (HC - 1));
    v.x = fmaxf(fmaf(v.x, g_scale[kc + 0], g_shift[kc + 0]), 0.0f);
    v.y = fmaxf(fmaf(v.y, g_scale[kc + 1], g_shift[kc + 1]), 0.0f);
    v.z = fmaxf(fmaf(v.z, g_scale[kc + 2], g_shift[kc + 2]), 0.0f);
    v.w = fmaxf(fmaf(v.w, g_scale[kc + 3], g_shift[kc + 3]), 0.0f);
    __half2* o = (__half2*)g_xr;
    o[i * 2 + 0] = __floats2half2_rn(v.x, v.y);
    o[i * 2 + 1] = __floats2half2_rn(v.z, v.w);
}

// ========== shared mma helpers ==========
#define SA 72

__device__ __forceinline__ void mma16816(float* c, const unsigned* a, unsigned b0, unsigned b1) {
    asm volatile(
        "mma.sync.aligned.m16n8k16.row.col.f32.f16.f16.f32 "
        "{%0,%1,%2,%3}, {%4,%5,%6,%7}, {%8,%9}, {%0,%1,%2,%3};\n"
        : "+f"(c[0]), "+f"(c[1]), "+f"(c[2]), "+f"(c[3])
        : "r"(a[0]), "r"(a[1]), "r"(a[2]), "r"(a[3]), "r"(b0), "r"(b1));
}

__device__ __forceinline__ void ldsm4(unsigned* r, const __half* p) {
    unsigned a = (unsigned)__cvta_generic_to_shared(p);
    asm volatile("ldmatrix.sync.aligned.m8n8.x4.shared.b16 {%0,%1,%2,%3}, [%4];\n"
                 : "=r"(r[0]), "=r"(r[1]), "=r"(r[2]), "=r"(r[3]) : "r"(a));
}

__device__ __forceinline__ void cpa16(void* dst, const void* src, int sz) {
    unsigned d = (unsigned)__cvta_generic_to_shared(dst);
    asm volatile("cp.async.ca.shared.global [%0], [%1], 16, %2;\n"
                 :: "r"(d), "l"(src), "r"(sz));
}

// ========== GEMM1: fp16 mma, 128x128 tiles, BK=64, 2 CTAs/SM ==========
#define BM 128
#define BN 128
#define BK 64
#define A_ST   (BM * SA)
#define B_ST   (BN * SA)
#define STAGE_ELEMS (A_ST + B_ST)
#define GEMM1_SMEM (2 * STAGE_ELEMS * 2)

__global__ void __launch_bounds__(256, 2)
k_gemm1() {
    extern __shared__ __half sm[];

    int tid  = threadIdx.x;
    int warp = tid >> 5, lane = tid & 31;
    int row0 = blockIdx.y * BM, col0 = blockIdx.x * BN;
    int wm = (warp >> 1) * 32, wn = (warp & 1) * 64;

    float acc[2][8][4];
#pragma unroll
    for (int t = 0; t < 2; t++)
#pragma unroll
        for (int n = 0; n < 8; n++)
#pragma unroll
            for (int j = 0; j < 4; j++) acc[t][n][j] = 0.0f;

    int lrow = tid >> 1, lch0 = (tid & 1) * 4;
    int gra = row0 + lrow;
    int asz = (gra < N_NODES) ? 16 : 0;
    size_t asrc = (size_t)min(gra, N_NODES - 1) * F_IN + lch0 * 8;
    size_t bsrc = (size_t)(col0 + lrow) * F_IN + lch0 * 8;
    int sOff = lrow * SA + lch0 * 8;

    const int NIT = F_IN / BK;   // 20

    __half* st[2];
    st[0] = sm;
    st[1] = sm + STAGE_ELEMS;

    int aRow = lane & 15;
    int aK   = (lane >> 4) << 3;
    int bRow = ((lane >> 4) << 3) + (lane & 7);
    int bK   = ((lane >> 3) & 1) << 3;

    {
        __half* s = st[0];
#pragma unroll
        for (int c = 0; c < 4; c++) {
            cpa16(s + sOff + c * 8,        g_af + asrc + c * 8, asz);
            cpa16(s + A_ST + sOff + c * 8, g_bf + bsrc + c * 8, 16);
        }
        asm volatile("cp.async.commit_group;\n");
    }

    for (int it = 0; it < NIT; it++) {
        if (it + 1 < NIT) {
            int k0 = (it + 1) * BK;
            __half* s = st[(it + 1) & 1];
#pragma unroll
            for (int c = 0; c < 4; c++) {
                cpa16(s + sOff + c * 8,        g_af + asrc + k0 + c * 8, asz);
                cpa16(s + A_ST + sOff + c * 8, g_bf + bsrc + k0 + c * 8, 16);
            }
        }
        asm volatile("cp.async.commit_group;\n");
        asm volatile("cp.async.wait_group 1;\n");
        __syncthreads();

        const __half* pA = st[it & 1];
        const __half* pB = pA + A_ST;

#pragma unroll
        for (int kk = 0; kk < BK; kk += 16) {
            unsigned af[2][4];
            ldsm4(af[0], pA + (wm +  0 + aRow) * SA + kk + aK);
            ldsm4(af[1], pA + (wm + 16 + aRow) * SA + kk + aK);
#pragma unroll
            for (int p = 0; p < 4; p++) {
                unsigned bf[4];
                ldsm4(bf, pB + (wn + p * 16 + bRow) * SA + kk + bK);
                int n0 = 2 * p, n1 = 2 * p + 1;
                mma16816(acc[0][n0], af[0], bf[0], bf[1]);
                mma16816(acc[1][n0], af[1], bf[0], bf[1]);
                mma16816(acc[0][n1], af[0], bf[2], bf[3]);
                mma16816(acc[1][n1], af[1], bf[2], bf[3]);
            }
        }
        __syncthreads();
    }

    // epilogue -> fp16 g_hh
    int g = lane >> 2, tig = lane & 3;
#pragma unroll
    for (int t = 0; t < 2; t++) {
        int r0 = row0 + wm + t * 16 + g;
#pragma unroll
        for (int n = 0; n < 8; n++) {
            int cc = col0 + wn + n * 8 + tig * 2;
            if (r0 < N_NODES)
                *(__half2*)&g_hh[(size_t)r0 * HC + cc] = __floats2half2_rn(acc[t][n][0], acc[t][n][1]);
            if (r0 + 8 < N_NODES)
                *(__half2*)&g_hh[(size_t)(r0 + 8) * HC + cc] = __floats2half2_rn(acc[t][n][2], acc[t][n][3]);
        }
    }
}

// ========== GEMM2: fp16 mma, 128x64 tiles, BK=64, 2 CTAs/SM ==========
#define B2_ST  (64 * SA)
#define STAGE2 (A_ST + B2_ST)
#define GEMM2_SMEM (2 * STAGE2 * 2)

__global__ void __launch_bounds__(256, 2)
k_gemm2() {
    extern __shared__ __half sm[];

    int tid  = threadIdx.x;
    int warp = tid >> 5, lane = tid & 31;
    int row0 = blockIdx.x * BM;
    int wm = (warp >> 1) * 32, wn = (warp & 1) * 32;

    float acc[2][4][4];
#pragma unroll
    for (int t = 0; t < 2; t++)
#pragma unroll
        for (int n = 0; n < 4; n++)
#pragma unroll
            for (int j = 0; j < 4; j++) acc[t][n][j] = 0.0f;

    int lrow = tid >> 1, lch0 = (tid & 1) * 4;
    int gra = row0 + lrow;
    int asz = (gra < N_NODES) ? 16 : 0;
    size_t asrc = (size_t)min(gra, N_NODES - 1) * HC + lch0 * 8;
    int sOffA = lrow * SA + lch0 * 8;
    int brow = tid >> 2, bch0 = (tid & 3) * 2;
    size_t bsrc = (size_t)brow * HC + bch0 * 8;
    int sOffB = brow * SA + bch0 * 8;

    const int NIT = HC / BK;   // 8

    __half* st[2];
    st[0] = sm;
    st[1] = sm + STAGE2;

    int aRow = lane & 15;
    int aK   = (lane >> 4) << 3;
    int bRow = ((lane >> 4) << 3) + (lane & 7);
    int bK   = ((lane >> 3) & 1) << 3;

    {
        __half* s = st[0];
#pragma unroll
        for (int c = 0; c < 4; c++)
            cpa16(s + sOffA + c * 8, g_xr + asrc + c * 8, asz);
#pragma unroll
        for (int c = 0; c < 2; c++)
            cpa16(s + A_ST + sOffB + c * 8, g_wgf + bsrc + c * 8, 16);
        asm volatile("cp.async.commit_group;\n");
    }

    for (int it = 0; it < NIT; it++) {
        if (it + 1 < NIT) {
            int k0 = (it + 1) * BK;
            __half* s = st[(it + 1) & 1];
#pragma unroll
            for (int c = 0; c < 4; c++)
                cpa16(s + sOffA + c * 8, g_xr + asrc + k0 + c * 8, asz);
#pragma unroll
            for (int c = 0; c < 2; c++)
                cpa16(s + A_ST + sOffB + c * 8, g_wgf + bsrc + k0 + c * 8, 16);
        }
        asm volatile("cp.async.commit_group;\n");
        asm volatile("cp.async.wait_group 1;\n");
        __syncthreads();

        const __half* pA = st[it & 1];
        const __half* pB = pA + A_ST;

#pragma unroll
        for (int kk = 0; kk < BK; kk += 16) {
            unsigned af[2][4];
            ldsm4(af[0], pA + (wm +  0 + aRow) * SA + kk + aK);
            ldsm4(af[1], pA + (wm + 16 + aRow) * SA + kk + aK);
#pragma unroll
            for (int p = 0; p < 2; p++) {
                unsigned bf[4];
                ldsm4(bf, pB + (wn + p * 16 + bRow) * SA + kk + bK);
                int n0 = 2 * p, n1 = 2 * p + 1;
                mma16816(acc[0][n0], af[0], bf[0], bf[1]);
                mma16816(acc[1][n0], af[1], bf[0], bf[1]);
                mma16816(acc[0][n1], af[0], bf[2], bf[3]);
                mma16816(acc[1][n1], af[1], bf[2], bf[3]);
            }
        }
        __syncthreads();
    }

    int g = lane >> 2, tig = lane & 3;
#pragma unroll
    for (int t = 0; t < 2; t++) {
        int r0 = row0 + wm + t * 16 + g;
#pragma unroll
        for (int n = 0; n < 4; n++) {
            int cc = wn + n * 8 + tig * 2;
            if (r0 < N_NODES)
                *(float2*)&g_h2[(size_t)r0 * HID + cc] = make_float2(acc[t][n][0], acc[t][n][1]);
            if (r0 + 8 < N_NODES)
                *(float2*)&g_h2[(size_t)(r0 + 8) * HID + cc] = make_float2(acc[t][n][2], acc[t][n][3]);
        }
    }
}

// ---------------- attention dots (fp16 h) ----------------
__global__ void k_att(const float* __restrict__ att_src, const float* __restrict__ att_dst) {
    int gw   = (blockIdx.x * blockDim.x + threadIdx.x) >> 5;
    int lane = threadIdx.x & 31;
    if (gw >= N_NODES * HEADS) return;
    int n = gw >> 2, hd = gw & 3;
    const __half2* hp = (const __half2*)&g_hh[(size_t)n * HC + hd * CH + lane * 4];
    float2 h01 = __half22float2(hp[0]);
    float2 h23 = __half22float2(hp[1]);
    float4 sv = *(const float4*)&att_src[hd * CH + lane * 4];
    float4 dv = *(const float4*)&att_dst[hd * CH + lane * 4];
    float vs = h01.x * sv.x + h01.y * sv.y + h23.x * sv.z + h23.y * sv.w;
    float vd = h01.x * dv.x + h01.y * dv.y + h23.x * dv.z + h23.y * dv.w;
#pragma unroll
    for (int o = 16; o > 0; o >>= 1) {
        vs += __shfl_down_sync(0xFFFFFFFFu, vs, o);
        vd += __shfl_down_sync(0xFFFFFFFFu, vd, o);
    }
    if (lane == 0) { g_asrc[gw] = vs; g_adst[gw] = vd; }
}

// ---------------- CSR build ----------------
__global__ void k_count(const int* __restrict__ ei, int E) {
    int e = blockIdx.x * blockDim.x + threadIdx.x;
    int ET = E + N_NODES;
    if (e >= ET) return;
    int d = (e < E) ? ei[E + e] : (e - E);
    atomicAdd(&g_cnt[d], 1);
}

__global__ void k_scan1() {
    __shared__ int red[8];
    int b = blockIdx.x, t = threadIdx.x;
    int lo = b * SCAN_CHUNK, hi = min(lo + SCAN_CHUNK, N_NODES);
    int s = 0;
    for (int i = lo + t; i < hi; i += 256) s += g_cnt[i];
#pragma unroll
    for (int o = 16; o > 0; o >>= 1) s += __shfl_xor_sync(0xFFFFFFFFu, s, o);
    if ((t & 31) == 0) red[t >> 5] = s;
    __syncthreads();
    if (t == 0) {
        int tot = 0;
#pragma unroll
        for (int i = 0; i < 8; i++) tot += red[i];
        g_bsum[b] = tot;
    }
}

__global__ void k_scan2() {
    __shared__ int sh[128];
    int t = threadIdx.x;
    int v = (t < SCAN_BLOCKS) ? g_bsum[t] : 0;
    sh[t] = v;
    __syncthreads();
#pragma unroll
    for (int o = 1; o < 128; o <<= 1) {
        int x = (t >= o) ? sh[t - o] : 0;
        __syncthreads();
        sh[t] += x;
        __syncthreads();
    }
    if (t < SCAN_BLOCKS) g_bsum[t] = sh[t] - v;
    if (t == 127) g_off[N_NODES] = sh[127];
}

__global__ void k_scan3() {
    __shared__ int sh[256];
    int b = blockIdx.x, t = threadIdx.x;
    int lo = b * SCAN_CHUNK;
    int i = lo + t;
    int v = (t < SCAN_CHUNK && i < N_NODES) ? g_cnt[i] : 0;
    sh[t] = v;
    __syncthreads();
#pragma unroll
    for (int o = 1; o < 256; o <<= 1) {
        int x = (t >= o) ? sh[t - o] : 0;
        __syncthreads();
        sh[t] += x;
        __syncthreads();
    }
    if (t < SCAN_CHUNK && i < N_NODES) {
        g_off[i] = g_bsum[b] + sh[t] - v;
        g_cnt[i] = 0;
    }
}

__global__ void k_fill(const int* __restrict__ ei, const float* __restrict__ ew, int E) {
    int e = blockIdx.x * blockDim.x + threadIdx.x;
    int ET = E + N_NODES;
    if (e >= ET) return;
    int s, d; float w;
    if (e < E) { s = ei[e]; d = ei[E + e]; w = ew[e]; }
    else       { s = d = e - E; w = 1.0f; }
    int slot = g_off[d] + atomicAdd(&g_cnt[d], 1);
    g_esrc[slot] = s;
    g_ewc[slot]  = w;
}

// ---------------- fused segment softmax + weighted degree ----------------
__global__ void k_softmax() {
    int d    = (blockIdx.x * blockDim.x + threadIdx.x) >> 5;
    int lane = threadIdx.x & 31;
    if (d >= N_NODES) return;
    int beg = g_off[d], end = g_off[d + 1];
    int cnt = end - beg;
    float4 ad = *(const float4*)&g_adst[d * 4];

    float mx0 = -1e30f, mx1 = -1e30f, mx2 = -1e30f, mx3 = -1e30f;
    float degw = 0.0f;

    if (cnt <= 32) {
        int i = beg + lane;
        bool act = lane < cnt;
        float l0 = -1e30f, l1 = -1e30f, l2 = -1e30f, l3 = -1e30f;
        if (act) {
            int s = g_esrc[i];
            float4 as = *(const float4*)&g_asrc[s * 4];
            l0 = as.x + ad.x; l1 = as.y + ad.y; l2 = as.z + ad.z; l3 = as.w + ad.w;
            l0 = l0 > 0.f ? l0 : 0.2f * l0;
            l1 = l1 > 0.f ? l1 : 0.2f * l1;
            l2 = l2 > 0.f ? l2 : 0.2f * l2;
            l3 = l3 > 0.f ? l3 : 0.2f * l3;
            degw = g_ewc[i];
        }
        mx0 = l0; mx1 = l1; mx2 = l2; mx3 = l3;
#pragma unroll
        for (int o = 16; o > 0; o >>= 1) {
            mx0 = fmaxf(mx0, __shfl_xor_sync(0xFFFFFFFFu, mx0, o));
            mx1 = fmaxf(mx1, __shfl_xor_sync(0xFFFFFFFFu, mx1, o));
            mx2 = fmaxf(mx2, __shfl_xor_sync(0xFFFFFFFFu, mx2, o));
            mx3 = fmaxf(mx3, __shfl_xor_sync(0xFFFFFFFFu, mx3, o));
            degw += __shfl_xor_sync(0xFFFFFFFFu, degw, o);
        }
        float e0 = act ? __expf(l0 - mx0) : 0.f;
        float e1 = act ? __expf(l1 - mx1) : 0.f;
        float e2 = act ? __expf(l2 - mx2) : 0.f;
        float e3 = act ? __expf(l3 - mx3) : 0.f;
        float s0 = e0, s1 = e1, s2 = e2, s3 = e3;
#pragma unroll
        for (int o = 16; o > 0; o >>= 1) {
            s0 += __shfl_xor_sync(0xFFFFFFFFu, s0, o);
            s1 += __shfl_xor_sync(0xFFFFFFFFu, s1, o);
            s2 += __shfl_xor_sync(0xFFFFFFFFu, s2, o);
            s3 += __shfl_xor_sync(0xFFFFFFFFu, s3, o);
        }
        if (act) {
            float4 al = make_float4(e0 / (s0 + 1e-16f), e1 / (s1 + 1e-16f),
                                    e2 / (s2 + 1e-16f), e3 / (s3 + 1e-16f));
            *(float4*)&g_alpha[(size_t)i * 4] = al;
        }
    } else {
        for (int i = beg + lane; i < end; i += 32) {
            int s = g_esrc[i];
            float4 as = *(const float4*)&g_asrc[s * 4];
            float l0 = as.x + ad.x, l1 = as.y + ad.y, l2 = as.z + ad.z, l3 = as.w + ad.w;
            l0 = l0 > 0.f ? l0 : 0.2f * l0;
            l1 = l1 > 0.f ? l1 : 0.2f * l1;
            l2 = l2 > 0.f ? l2 : 0.2f * l2;
            l3 = l3 > 0.f ? l3 : 0.2f * l3;
            *(float4*)&g_alpha[(size_t)i * 4] = make_float4(l0, l1, l2, l3);
            mx0 = fmaxf(mx0, l0); mx1 = fmaxf(mx1, l1);
            mx2 = fmaxf(mx2, l2); mx3 = fmaxf(mx3, l3);
            degw += g_ewc[i];
        }
#pragma unroll
        for (int o = 16; o > 0; o >>= 1) {
            mx0 = fmaxf(mx0, __shfl_xor_sync(0xFFFFFFFFu, mx0, o));
            mx1 = fmaxf(mx1, __shfl_xor_sync(0xFFFFFFFFu, mx1, o));
            mx2 = fmaxf(mx2, __shfl_xor_sync(0xFFFFFFFFu, mx2, o));
            mx3 = fmaxf(mx3, __shfl_xor_sync(0xFFFFFFFFu, mx3, o));
            degw += __shfl_xor_sync(0xFFFFFFFFu, degw, o);
        }
        float s0 = 0.f, s1 = 0.f, s2 = 0.f, s3 = 0.f;
        for (int i = beg + lane; i < end; i += 32) {
            float4 l = *(const float4*)&g_alpha[(size_t)i * 4];
            float e0 = __expf(l.x - mx0), e1 = __expf(l.y - mx1);
            float e2 = __expf(l.z - mx2), e3 = __expf(l.w - mx3);
            *(float4*)&g_alpha[(size_t)i * 4] = make_float4(e0, e1, e2, e3);
            s0 += e0; s1 += e1; s2 += e2; s3 += e3;
        }
#pragma unroll
        for (int o = 16; o > 0; o >>= 1) {
            s0 += __shfl_xor_sync(0xFFFFFFFFu, s0, o);
            s1 += __shfl_xor_sync(0xFFFFFFFFu, s1, o);
            s2 += __shfl_xor_sync(0xFFFFFFFFu, s2, o);
            s3 += __shfl_xor_sync(0xFFFFFFFFu, s3, o);
        }
        float r0 = 1.f / (s0 + 1e-16f), r1 = 1.f / (s1 + 1e-16f);
        float r2 = 1.f / (s2 + 1e-16f), r3 = 1.f / (s3 + 1e-16f);
        for (int i = beg + lane; i < end; i += 32) {
            float4 l = *(const float4*)&g_alpha[(size_t)i * 4];
            *(float4*)&g_alpha[(size_t)i * 4] = make_float4(l.x * r0, l.y * r1, l.z * r2, l.w * r3);
        }
    }
    if (lane == 0) g_dinv[d] = degw > 0.f ? rsqrtf(degw) : 0.0f;
}

// ---------------- GAT aggregation (fp16 h, fp32 acc) ----------------
__global__ void __launch_bounds__(128)
k_aggregate(const float* __restrict__ b_gat) {
    int d = blockIdx.x;
    int tid = threadIdx.x;
    int head = tid >> 5;
    int c = tid * 4;
    float4 acc = *(const float4*)&b_gat[c];
    int beg = g_off[d], end = g_off[d + 1];
    int i = beg;
    for (; i + 1 < end; i += 2) {
        int s0 = g_esrc[i], s1 = g_esrc[i + 1];
        float a0 = g_alpha[(size_t)i * 4 + head];
        float a1 = g_alpha[(size_t)(i + 1) * 4 + head];
        const __half2* p0 = (const __half2*)&g_hh[(size_t)s0 * HC + c];
        const __half2* p1 = (const __half2*)&g_hh[(size_t)s1 * HC + c];
        float2 v0a = __half22float2(p0[0]), v0b = __half22float2(p0[1]);
        float2 v1a = __half22float2(p1[0]), v1b = __half22float2(p1[1]);
        acc.x = fmaf(v0a.x, a0, acc.x); acc.y = fmaf(v0a.y, a0, acc.y);
        acc.z = fmaf(v0b.x, a0, acc.z); acc.w = fmaf(v0b.y, a0, acc.w);
        acc.x = fmaf(v1a.x, a1, acc.x); acc.y = fmaf(v1a.y, a1, acc.y);
        acc.z = fmaf(v1b.x, a1, acc.z); acc.w = fmaf(v1b.y, a1, acc.w);
    }
    if (i < end) {
        int s0 = g_esrc[i];
        float a0 = g_alpha[(size_t)i * 4 + head];
        const __half2* p0 = (const __half2*)&g_hh[(size_t)s0 * HC + c];
        float2 v0a = __half22float2(p0[0]), v0b = __half22float2(p0[1]);
        acc.x = fmaf(v0a.x, a0, acc.x); acc.y = fmaf(v0a.y, a0, acc.y);
        acc.z = fmaf(v0b.x, a0, acc.z); acc.w = fmaf(v0b.y, a0, acc.w);
    }
    *(float4*)&g_out1[(size_t)d * HC + c] = acc;
}

// ---------------- BN stats ----------------
__global__ void k_bnstats() {
    int col = threadIdx.x;
    float s = 0.f, s2 = 0.f;
    for (int r = blockIdx.x; r < N_NODES; r += gridDim.x) {
        float v = g_out1[(size_t)r * HC + col];
        s += v; s2 += v * v;
    }
    atomicAdd(&g_colsum[col], s);
    atomicAdd(&g_colsum2[col], s2);
}

__global__ void k_bnfinal(const float* __restrict__ gamma, const float* __restrict__ beta) {
    int c = blockIdx.x * blockDim.x + threadIdx.x;
    if (c >= HC) return;
    float mean = g_colsum[c] * (1.0f / N_NODES);
    float var  = g_colsum2[c] * (1.0f / N_NODES) - mean * mean;
    float sc = gamma[c] * rsqrtf(var + 1e-5f);
    g_scale[c] = sc;
    g_shift[c] = beta[c] - mean * sc;
}

// ---------------- GCN gather ----------------
__global__ void k_gcn(const float* __restrict__ b_gcn, float* __restrict__ out) {
    int d    = (blockIdx.x * blockDim.x + threadIdx.x) >> 5;
    int lane = threadIdx.x & 31;
    if (d >= N_NODES) return;
    float dinv_d = g_dinv[d];
    float2 acc = *(const float2*)&b_gcn[lane * 2];
    int beg = g_off[d], end = g_off[d + 1];
    int i = beg;
    for (; i + 1 < end; i += 2) {
        int s0 = g_esrc[i], s1 = g_esrc[i + 1];
        float n0 = g_dinv[s0] * g_ewc[i] * dinv_d;
        float n1 = g_dinv[s1] * g_ewc[i + 1] * dinv_d;
        float2 v0 = *(const float2*)&g_h2[(size_t)s0 * HID + lane * 2];
        float2 v1 = *(const float2*)&g_h2[(size_t)s1 * HID + lane * 2];
        acc.x = fmaf(v0.x, n0, acc.x); acc.y = fmaf(v0.y, n0, acc.y);
        acc.x = fmaf(v1.x, n1, acc.x); acc.y = fmaf(v1.y, n1, acc.y);
    }
    if (i < end) {
        int s0 = g_esrc[i];
        float n0 = g_dinv[s0] * g_ewc[i] * dinv_d;
        float2 v0 = *(const float2*)&g_h2[(size_t)s0 * HID + lane * 2];
        acc.x = fmaf(v0.x, n0, acc.x); acc.y = fmaf(v0.y, n0, acc.y);
    }
    *(float2*)&out[(size_t)d * HID + lane * 2] = acc;
}

// ---------------- launch ----------------
extern "C" void kernel_launch(void* const* d_in, const int* in_sizes, int n_in,
                              void* d_out, int out_size) {
    const float* x       = (const float*)d_in[0];
    const int*   ei      = (const int*)  d_in[1];
    const float* ew      = (const float*)d_in[2];
    const float* W_gat   = (const float*)d_in[3];
    const float* att_src = (const float*)d_in[4];
    const float* att_dst = (const float*)d_in[5];
    const float* b_gat   = (const float*)d_in[6];
    const float* gamma   = (const float*)d_in[7];
    const float* beta    = (const float*)d_in[8];
    const float* W_gcn   = (const float*)d_in[9];
    const float* b_gcn   = (const float*)d_in[10];
    float* out = (float*)d_out;

    int E  = in_sizes[1] / 2;
    int ET = E + N_NODES;

    static cudaStream_t s_side = nullptr;
    static cudaEvent_t ev_fork = nullptr, ev_join = nullptr;
    if (!s_side) {
        cudaFuncSetAttribute(k_gemm1, cudaFuncAttributeMaxDynamicSharedMemorySize, GEMM1_SMEM);
        cudaFuncSetAttribute(k_gemm2, cudaFuncAttributeMaxDynamicSharedMemorySize, GEMM2_SMEM);
        cudaStreamCreateWithFlags(&s_side, cudaStreamNonBlocking);
        cudaEventCreateWithFlags(&ev_fork, cudaEventDisableTiming);
        cudaEventCreateWithFlags(&ev_join, cudaEventDisableTiming);
    }

    k_init<<<(N_NODES + 255) / 256, 256>>>();

    // ---- fork: CSR build + W_gcn convert run on side stream, hidden under GEMM1 ----
    cudaEventRecord(ev_fork, 0);
    cudaStreamWaitEvent(s_side, ev_fork, 0);
    k_count<<<(ET + 255) / 256, 256, 0, s_side>>>(ei, E);
    k_scan1<<<SCAN_BLOCKS, 256, 0, s_side>>>();
    k_scan2<<<1, 128, 0, s_side>>>();
    k_scan3<<<SCAN_BLOCKS, 256, 0, s_side>>>();
    k_fill<<<(ET + 255) / 256, 256, 0, s_side>>>(ei, ew, E);
    k_conv_wg<<<(HC * HID + 255) / 256, 256, 0, s_side>>>(W_gcn);
    cudaEventRecord(ev_join, s_side);

    // ---- main stream: converts + GEMM1 + attention dots ----
    k_conv_a<<<((N_NODES * (F_IN / 4)) + 255) / 256, 256>>>(x);
    k_conv_bt<<<(F_IN * HC + 255) / 256, 256>>>(W_gat);

    dim3 g1(HC / BN, (N_NODES + BM - 1) / BM);   // (4, 235)
    k_gemm1<<<g1, 256, GEMM1_SMEM>>>();

    k_att<<<(N_NODES * HEADS * 32 + 255) / 256, 256>>>(att_src, att_dst);

    // ---- join: softmax needs CSR ----
    cudaStreamWaitEvent(0, ev_join, 0);
    k_softmax<<<(N_NODES * 32 + 255) / 256, 256>>>();
    k_aggregate<<<N_NODES, 128>>>(b_gat);

    k_bnstats<<<240, 512>>>();
    k_bnfinal<<<2, 256>>>(gamma, beta);
    k_conv_xr<<<((N_NODES * (HC / 4)) + 255) / 256, 256>>>();

    k_gemm2<<<(N_NODES + BM - 1) / BM, 256, GEMM2_SMEM>>>();
    k_gcn<<<(N_NODES * 32 + 255) / 256, 256>>>(b_gcn, out);
}